// round 8
// baseline (speedup 1.0000x reference)
#include <cuda_runtime.h>
#include <cuda_fp16.h>
#include <math.h>

#define Bb 8
#define Nn 1024
#define Hh 12

#define QKVSZ ((size_t)Bb*Hh*Nn*64)

// Scratch (static device globals)
__device__ __half g_Qh[QKVSZ], g_Ql[QKVSZ];
__device__ __half g_Kh[QKVSZ];
__device__ __half g_Vh[QKVSZ];
__device__ __half g_S[(size_t)Bb*Hh*Nn*Nn];   // fp16 raw logits
__device__ __half g_P[(size_t)Bb*Hh*Nn*Nn];   // fp16 post-mixed attn
__device__ __half g_Ch[(size_t)Bb*Nn*768], g_Cl[(size_t)Bb*Nn*768];

// ---------------------------------------------------------------------------
__device__ __forceinline__ void split2(float a, float b, unsigned &h, unsigned &l) {
    __half ha = __float2half_rn(a), hb = __float2half_rn(b);
    __half2 H = __halves2half2(ha, hb);
    __half2 L = __halves2half2(__float2half_rn(a - __half2float(ha)),
                               __float2half_rn(b - __half2float(hb)));
    h = *(unsigned*)&H; l = *(unsigned*)&L;
}
__device__ __forceinline__ void split4(float4 v, uint2 &h, uint2 &l) {
    split2(v.x, v.y, h.x, l.x); split2(v.z, v.w, h.y, l.y);
}
__device__ __forceinline__ uint2 pack4h(float4 v) {
    __half2 a = __floats2half2_rn(v.x, v.y);
    __half2 b = __floats2half2_rn(v.z, v.w);
    uint2 r; r.x = *(unsigned*)&a; r.y = *(unsigned*)&b; return r;
}
__device__ __forceinline__ void store_hl(__half* Gh, __half* Gl, size_t idx,
                                         float v0, float v1) {
    __half h0 = __float2half_rn(v0), h1 = __float2half_rn(v1);
    __half l0 = __float2half_rn(v0 - __half2float(h0));
    __half l1 = __float2half_rn(v1 - __half2float(h1));
    *(__half2*)(Gh + idx) = __halves2half2(h0, h1);
    *(__half2*)(Gl + idx) = __halves2half2(l0, l1);
}

#define LDSM_X4(r0, r1, r2, r3, a) \
  asm volatile("ldmatrix.sync.aligned.m8n8.x4.shared.b16 {%0,%1,%2,%3},[%4];" \
               : "=r"(r0), "=r"(r1), "=r"(r2), "=r"(r3) : "r"(a))
#define LDSM_X4T(r0, r1, r2, r3, a) \
  asm volatile("ldmatrix.sync.aligned.m8n8.x4.trans.shared.b16 {%0,%1,%2,%3},[%4];" \
               : "=r"(r0), "=r"(r1), "=r"(r2), "=r"(r3) : "r"(a))
#define MMA16(c, a, b) \
  asm volatile("mma.sync.aligned.m16n8k16.row.col.f32.f16.f16.f32 " \
               "{%0,%1,%2,%3},{%4,%5,%6,%7},{%8,%9},{%0,%1,%2,%3};" \
               : "+f"(c[0]), "+f"(c[1]), "+f"(c[2]), "+f"(c[3]) \
               : "r"(a[0]), "r"(a[1]), "r"(a[2]), "r"(a[3]), "r"(b[0]), "r"(b[1]))

// ---------------------------------------------------------------------------
// K1: QKV projection. x @ fp16(W). Q: hi/lo split (scale 1/8 folded);
// K,V: plain fp16. 2 mma passes, double-buffered. grid (18, 64).
// ---------------------------------------------------------------------------
__global__ __launch_bounds__(256, 2) void k_qkv(const float* __restrict__ x,
                                                const float* __restrict__ Wq,
                                                const float* __restrict__ Wkv) {
    __shared__ __half As[2][2 * 128 * 24];
    __shared__ __half Bs[2][16 * 136];
    const int tid = threadIdx.x, lane = tid & 31, w = tid >> 5;
    const int bx = blockIdx.x, by = blockIdx.y;
    const int nglob = bx * 128;
    const float* Bp = (nglob < 768) ? (Wq + nglob) : (Wkv + (nglob - 768));
    const int ldb = (nglob < 768) ? 768 : 1536;
    const int wm = (w >> 2) * 64, wn = (w & 3) * 32;

    const int ar = tid >> 2, ak4 = (tid & 3) * 4;
    const int bk = tid >> 4, bn4 = (tid & 15) * 4;
    const float* Ap = x + ((size_t)by * 128 + ar) * 768 + ak4;

    const int lr = lane & 7, hs = (lane >> 3) & 1, kc = lane >> 4;
    const unsigned sa = (unsigned)__cvta_generic_to_shared(&As[0][0]);
    const unsigned sb = (unsigned)__cvta_generic_to_shared(&Bs[0][0]);
    const unsigned aaddr = sa + ((wm + hs * 8 + lr) * 24 + kc * 8) * 2;
    const unsigned baddr = sb + ((hs * 8 + lr) * 136 + wn + kc * 8) * 2;
    const unsigned ALO = 128 * 24 * 2;
    const unsigned ABUF = 2 * 128 * 24 * 2;
    const unsigned BBUF = 16 * 136 * 2;

    float acc[4][4][4] = {};

    float4 ra0 = *(const float4*)(Ap);
    float4 ra1 = *(const float4*)(Ap + (size_t)64 * 768);
    float4 rb0 = *(const float4*)(Bp + (size_t)bk * ldb + bn4);
    float4 rb1 = *(const float4*)(Bp + (size_t)bk * ldb + bn4 + 64);
    {
        uint2 h, l;
        split4(ra0, h, l);
        *(uint2*)&As[0][ar * 24 + ak4] = h;        *(uint2*)&As[0][3072 + ar * 24 + ak4] = l;
        split4(ra1, h, l);
        *(uint2*)&As[0][(ar + 64) * 24 + ak4] = h; *(uint2*)&As[0][3072 + (ar + 64) * 24 + ak4] = l;
        *(uint2*)&Bs[0][bk * 136 + bn4]      = pack4h(rb0);
        *(uint2*)&Bs[0][bk * 136 + bn4 + 64] = pack4h(rb1);
    }
    __syncthreads();

    for (int kt = 0; kt < 48; ++kt) {
        const int cur = kt & 1;
        if (kt < 47) {
            ra0 = *(const float4*)(Ap + (kt + 1) * 16);
            ra1 = *(const float4*)(Ap + (size_t)64 * 768 + (kt + 1) * 16);
            rb0 = *(const float4*)(Bp + (size_t)((kt + 1) * 16 + bk) * ldb + bn4);
            rb1 = *(const float4*)(Bp + (size_t)((kt + 1) * 16 + bk) * ldb + bn4 + 64);
        }
        unsigned af[4][4], bh[4][2];
        #pragma unroll
        for (int n2 = 0; n2 < 2; ++n2)
            LDSM_X4T(bh[2*n2][0], bh[2*n2][1], bh[2*n2+1][0], bh[2*n2+1][1],
                     baddr + cur * BBUF + n2 * 32);
        #pragma unroll
        for (int mt = 0; mt < 4; ++mt)
            LDSM_X4(af[mt][0], af[mt][1], af[mt][2], af[mt][3],
                    aaddr + cur * ABUF + mt * 768);
        #pragma unroll
        for (int mt = 0; mt < 4; ++mt)
            #pragma unroll
            for (int nt = 0; nt < 4; ++nt)
                MMA16(acc[mt][nt], af[mt], bh[nt]);
        #pragma unroll
        for (int mt = 0; mt < 4; ++mt)
            LDSM_X4(af[mt][0], af[mt][1], af[mt][2], af[mt][3],
                    aaddr + cur * ABUF + mt * 768 + ALO);
        #pragma unroll
        for (int mt = 0; mt < 4; ++mt)
            #pragma unroll
            for (int nt = 0; nt < 4; ++nt)
                MMA16(acc[mt][nt], af[mt], bh[nt]);
        if (kt < 47) {
            const int nb = cur ^ 1;
            uint2 h, l;
            split4(ra0, h, l);
            *(uint2*)&As[nb][ar * 24 + ak4] = h;        *(uint2*)&As[nb][3072 + ar * 24 + ak4] = l;
            split4(ra1, h, l);
            *(uint2*)&As[nb][(ar + 64) * 24 + ak4] = h; *(uint2*)&As[nb][3072 + (ar + 64) * 24 + ak4] = l;
            *(uint2*)&Bs[nb][bk * 136 + bn4]      = pack4h(rb0);
            *(uint2*)&Bs[nb][bk * 136 + bn4 + 64] = pack4h(rb1);
        }
        __syncthreads();
    }

    const int g = lane >> 2, th = lane & 3;
    #pragma unroll
    for (int nt = 0; nt < 4; ++nt) {
        const int col = nglob + wn + nt * 8 + 2 * th;
        const int mat = col / 768;
        const int within = col - mat * 768;
        const int head = within >> 6, d = within & 63;
        #pragma unroll
        for (int mt = 0; mt < 4; ++mt) {
            const int m0 = by * 128 + wm + mt * 16 + g;
            const int b = m0 >> 10, nr = m0 & 1023;
            const size_t base = (((size_t)b * 12 + head) * 1024 + nr) * 64 + d;
            if (mat == 0) {
                store_hl(g_Qh, g_Ql, base,          acc[mt][nt][0] * 0.125f, acc[mt][nt][1] * 0.125f);
                store_hl(g_Qh, g_Ql, base + 8 * 64, acc[mt][nt][2] * 0.125f, acc[mt][nt][3] * 0.125f);
            } else {
                __half* G = (mat == 1) ? g_Kh : g_Vh;
                *(__half2*)(G + base)          = __floats2half2_rn(acc[mt][nt][0], acc[mt][nt][1]);
                *(__half2*)(G + base + 8 * 64) = __floats2half2_rn(acc[mt][nt][2], acc[mt][nt][3]);
            }
        }
    }
}

// ---------------------------------------------------------------------------
// K2: logits = (Q/8) @ K^T per (b,h). Passes: Qh*Kh + Ql*Kh. -> fp16 g_S.
// grid (8,8,96)
// ---------------------------------------------------------------------------
__global__ __launch_bounds__(256, 2) void k_dots() {
    __shared__ __half Qs[2 * 128 * 40];
    __shared__ __half Ks[128 * 40];
    const int tid = threadIdx.x, lane = tid & 31, w = tid >> 5;
    const int jt = blockIdx.x, it = blockIdx.y, bh = blockIdx.z;
    const __half* Qhp = g_Qh + (size_t)bh * 65536 + (size_t)it * 128 * 64;
    const __half* Qlp = g_Ql + (size_t)bh * 65536 + (size_t)it * 128 * 64;
    const __half* Khp = g_Kh + (size_t)bh * 65536 + (size_t)jt * 128 * 64;
    __half* Sp = g_S + (size_t)bh * Nn * Nn;
    const int wm = (w >> 2) * 64, wn = (w & 3) * 32;

    const int lr = lane & 7, hs = (lane >> 3) & 1, kc = lane >> 4;
    const unsigned sq = (unsigned)__cvta_generic_to_shared(Qs);
    const unsigned sk = (unsigned)__cvta_generic_to_shared(Ks);
    const unsigned aaddr = sq + ((wm + hs * 8 + lr) * 40 + kc * 8) * 2;
    const unsigned kaddr = sk + ((wn + hs * 8 + lr) * 40 + kc * 8) * 2;
    const unsigned PLO = 128 * 40 * 2;

    float acc[4][4][4] = {};

    for (int kt = 0; kt < 2; ++kt) {
        #pragma unroll
        for (int j = 0; j < 2; ++j) {
            const int u = j * 256 + tid;
            const int row = u >> 2, c16 = u & 3;
            const int goff = row * 64 + kt * 32 + c16 * 8;
            const int soff = row * 40 + c16 * 8;
            *(uint4*)&Qs[soff]        = *(const uint4*)(Qhp + goff);
            *(uint4*)&Qs[5120 + soff] = *(const uint4*)(Qlp + goff);
            *(uint4*)&Ks[soff]        = *(const uint4*)(Khp + goff);
        }
        __syncthreads();
        #pragma unroll
        for (int kk = 0; kk < 32; kk += 16) {
            unsigned bkh[4][2], af[4][4];
            #pragma unroll
            for (int n2 = 0; n2 < 2; ++n2)
                LDSM_X4(bkh[2*n2][0], bkh[2*n2+1][0], bkh[2*n2][1], bkh[2*n2+1][1],
                        kaddr + n2 * 1280 + kk * 2);
            #pragma unroll
            for (int mt = 0; mt < 4; ++mt)
                LDSM_X4(af[mt][0], af[mt][1], af[mt][2], af[mt][3],
                        aaddr + mt * 1280 + kk * 2);
            #pragma unroll
            for (int mt = 0; mt < 4; ++mt)
                #pragma unroll
                for (int nt = 0; nt < 4; ++nt)
                    MMA16(acc[mt][nt], af[mt], bkh[nt]);
            #pragma unroll
            for (int mt = 0; mt < 4; ++mt)
                LDSM_X4(af[mt][0], af[mt][1], af[mt][2], af[mt][3],
                        aaddr + mt * 1280 + kk * 2 + PLO);
            #pragma unroll
            for (int mt = 0; mt < 4; ++mt)
                #pragma unroll
                for (int nt = 0; nt < 4; ++nt)
                    MMA16(acc[mt][nt], af[mt], bkh[nt]);
        }
        __syncthreads();
    }

    const int g = lane >> 2, th = lane & 3;
    #pragma unroll
    for (int mt = 0; mt < 4; ++mt) {
        const int m = it * 128 + wm + mt * 16 + g;
        #pragma unroll
        for (int nt = 0; nt < 4; ++nt) {
            const int c = jt * 128 + wn + nt * 8 + 2 * th;
            *(__half2*)(Sp + (size_t)m * 1024 + c) =
                __floats2half2_rn(acc[mt][nt][0], acc[mt][nt][1]);
            *(__half2*)(Sp + (size_t)(m + 8) * 1024 + c) =
                __floats2half2_rn(acc[mt][nt][2], acc[mt][nt][3]);
        }
    }
}

// ---------------------------------------------------------------------------
// K3: mix_pre -> softmax -> mix_post; fp16 g_S -> fp16 g_P.
// 512 threads, 2 j's per thread (lower regs, more warps).
// ---------------------------------------------------------------------------
__global__ __launch_bounds__(512) void k_mixsoft(const float* __restrict__ mix_pre,
                                                 const float* __restrict__ mix_post) {
    __shared__ __half raw[12 * 1024];
    __shared__ float pre[144], post[144];
    __shared__ float wred[12 * 16];
    __shared__ float gstat[24];
    const int t = threadIdx.x;
    const int b = blockIdx.x >> 10, i = blockIdx.x & 1023;
    if (t < 144) { pre[t] = mix_pre[t]; post[t] = mix_post[t]; }
    const size_t rowbase = (size_t)b * 12 * 1048576 + (size_t)i * 1024;

    #pragma unroll
    for (int u = 0; u < 3; ++u) {
        const int v = u * 512 + t;          // 0..1535
        const int h = v >> 7;
        const int j8 = (v & 127) * 8;
        *(uint4*)&raw[h * 1024 + j8] =
            *(const uint4*)(g_S + rowbase + (size_t)h * 1048576 + j8);
    }
    __syncthreads();

    float rv0[12], rv1[12];
    #pragma unroll
    for (int h = 0; h < 12; ++h) {
        rv0[h] = __half2float(raw[h * 1024 + t]);
        rv1[h] = __half2float(raw[h * 1024 + t + 512]);
    }
    float mx[12][2];
    #pragma unroll
    for (int g = 0; g < 12; ++g) {
        float a0 = 0.f, a1 = 0.f;
        #pragma unroll
        for (int h = 0; h < 12; ++h) {
            float p = pre[h * 12 + g];
            a0 += rv0[h] * p;
            a1 += rv1[h] * p;
        }
        mx[g][0] = a0; mx[g][1] = a1;
    }

    const int lane = t & 31, wid = t >> 5;
    #pragma unroll
    for (int g = 0; g < 12; ++g) {
        float m = fmaxf(mx[g][0], mx[g][1]);
        #pragma unroll
        for (int o = 16; o > 0; o >>= 1) m = fmaxf(m, __shfl_xor_sync(0xffffffffu, m, o));
        if (lane == 0) wred[g * 16 + wid] = m;
    }
    __syncthreads();
    if (t < 12) {
        float m = wred[t * 16];
        #pragma unroll
        for (int w2 = 1; w2 < 16; ++w2) m = fmaxf(m, wred[t * 16 + w2]);
        gstat[t] = m;
    }
    __syncthreads();
    #pragma unroll
    for (int g = 0; g < 12; ++g) {
        float mg = gstat[g];
        mx[g][0] = __expf(mx[g][0] - mg);
        mx[g][1] = __expf(mx[g][1] - mg);
        float s = mx[g][0] + mx[g][1];
        #pragma unroll
        for (int o = 16; o > 0; o >>= 1) s += __shfl_xor_sync(0xffffffffu, s, o);
        if (lane == 0) wred[g * 16 + wid] = s;
    }
    __syncthreads();
    if (t < 12) {
        float s = 0.f;
        #pragma unroll
        for (int w2 = 0; w2 < 16; ++w2) s += wred[t * 16 + w2];
        gstat[12 + t] = 1.0f / s;
    }
    __syncthreads();
    #pragma unroll
    for (int g = 0; g < 12; ++g) {
        float inv = gstat[12 + g];
        mx[g][0] *= inv; mx[g][1] *= inv;
    }
    #pragma unroll
    for (int h = 0; h < 12; ++h) {
        float o0 = 0.f, o1 = 0.f;
        #pragma unroll
        for (int g = 0; g < 12; ++g) {
            float p = post[g * 12 + h];
            o0 += mx[g][0] * p;
            o1 += mx[g][1] * p;
        }
        __half* dst = g_P + rowbase + (size_t)h * 1048576;
        dst[t]       = __float2half_rn(o0);
        dst[t + 512] = __float2half_rn(o1);
    }
}

// ---------------------------------------------------------------------------
// K4: O = attn(fp16) @ Vh(fp16) per (b,h) -> g_Ch/g_Cl. Single mma pass.
// Double-buffered. grid (8 it, 96 bh)
// ---------------------------------------------------------------------------
__global__ __launch_bounds__(256, 2) void k_av() {
    __shared__ __half As[2][128 * 40];
    __shared__ __half Vs[2][32 * 72];
    const int tid = threadIdx.x, lane = tid & 31, w = tid >> 5;
    const int it = blockIdx.x, bh = blockIdx.y;
    const int b = bh / 12, h = bh % 12;
    const __half* Pp  = g_P  + (size_t)bh * 1048576 + (size_t)it * 131072;
    const __half* Vhp = g_Vh + (size_t)bh * 65536;
    const int wm = (w >> 1) * 32, wn = (w & 1) * 32;

    const int arow = tid >> 2, ac16 = tid & 3;
    const int vrow = tid >> 3, vc16 = tid & 7;

    const int lr = lane & 7, hs = (lane >> 3) & 1, kc = lane >> 4;
    const unsigned sa = (unsigned)__cvta_generic_to_shared(&As[0][0]);
    const unsigned sb = (unsigned)__cvta_generic_to_shared(&Vs[0][0]);
    const unsigned aaddr = sa + ((wm + hs * 8 + lr) * 40 + kc * 8) * 2;
    const unsigned baddr = sb + ((hs * 8 + lr) * 72 + wn + kc * 8) * 2;
    const unsigned ABUF = 128 * 40 * 2;
    const unsigned VBUF = 32 * 72 * 2;

    float acc[2][4][4] = {};

    uint4 pa0 = *(const uint4*)(Pp + (size_t)arow * 1024 + ac16 * 8);
    uint4 pa1 = *(const uint4*)(Pp + (size_t)(arow + 64) * 1024 + ac16 * 8);
    uint4 pv0 = *(const uint4*)(Vhp + vrow * 64 + vc16 * 8);
    {
        *(uint4*)&As[0][arow * 40 + ac16 * 8]        = pa0;
        *(uint4*)&As[0][(arow + 64) * 40 + ac16 * 8] = pa1;
        *(uint4*)&Vs[0][vrow * 72 + vc16 * 8]        = pv0;
    }
    __syncthreads();

    for (int kt = 0; kt < 32; ++kt) {
        const int cur = kt & 1;
        if (kt < 31) {
            pa0 = *(const uint4*)(Pp + (size_t)arow * 1024 + (kt + 1) * 32 + ac16 * 8);
            pa1 = *(const uint4*)(Pp + (size_t)(arow + 64) * 1024 + (kt + 1) * 32 + ac16 * 8);
            pv0 = *(const uint4*)(Vhp + (size_t)((kt + 1) * 32 + vrow) * 64 + vc16 * 8);
        }
        #pragma unroll
        for (int kk = 0; kk < 32; kk += 16) {
            unsigned af[2][4], bvh[4][2];
            #pragma unroll
            for (int n2 = 0; n2 < 2; ++n2)
                LDSM_X4T(bvh[2*n2][0], bvh[2*n2][1], bvh[2*n2+1][0], bvh[2*n2+1][1],
                         baddr + cur * VBUF + kk * 144 + n2 * 32);
            #pragma unroll
            for (int mt = 0; mt < 2; ++mt)
                LDSM_X4(af[mt][0], af[mt][1], af[mt][2], af[mt][3],
                        aaddr + cur * ABUF + mt * 1280 + kk * 2);
            #pragma unroll
            for (int mt = 0; mt < 2; ++mt)
                #pragma unroll
                for (int nt = 0; nt < 4; ++nt)
                    MMA16(acc[mt][nt], af[mt], bvh[nt]);
        }
        if (kt < 31) {
            const int nb = cur ^ 1;
            *(uint4*)&As[nb][arow * 40 + ac16 * 8]        = pa0;
            *(uint4*)&As[nb][(arow + 64) * 40 + ac16 * 8] = pa1;
            *(uint4*)&Vs[nb][vrow * 72 + vc16 * 8]        = pv0;
        }
        __syncthreads();
    }

    const int g = lane >> 2, th = lane & 3;
    #pragma unroll
    for (int mt = 0; mt < 2; ++mt) {
        const int m = it * 128 + wm + mt * 16 + g;
        #pragma unroll
        for (int nt = 0; nt < 4; ++nt) {
            const int c = wn + nt * 8 + 2 * th;
            const size_t base = ((size_t)b * 1024 + m) * 768 + h * 64 + c;
            store_hl(g_Ch, g_Cl, base,             acc[mt][nt][0], acc[mt][nt][1]);
            store_hl(g_Ch, g_Cl, base + 8 * 768,   acc[mt][nt][2], acc[mt][nt][3]);
        }
    }
}

// ---------------------------------------------------------------------------
// K5: out = Ctx(hi/lo) @ fp16(Wo) + bo. 2 mma passes, double buffered.
// grid (6, 64)
// ---------------------------------------------------------------------------
__global__ __launch_bounds__(256, 2) void k_out(const float* __restrict__ Wo,
                                                const float* __restrict__ bo,
                                                float* __restrict__ out) {
    __shared__ __half As[2][2 * 128 * 24];
    __shared__ __half Bs[2][16 * 136];
    const int tid = threadIdx.x, lane = tid & 31, w = tid >> 5;
    const int bx = blockIdx.x, by = blockIdx.y;
    const float* Bp = Wo + bx * 128;
    const int wm = (w >> 2) * 64, wn = (w & 3) * 32;

    const int arow = tid >> 1, ac16 = tid & 1;
    const int bk = tid >> 4, bn4 = (tid & 15) * 4;
    const __half* Chp = g_Ch + (size_t)by * 128 * 768;
    const __half* Clp = g_Cl + (size_t)by * 128 * 768;

    const int lr = lane & 7, hs = (lane >> 3) & 1, kc = lane >> 4;
    const unsigned sa = (unsigned)__cvta_generic_to_shared(&As[0][0]);
    const unsigned sb = (unsigned)__cvta_generic_to_shared(&Bs[0][0]);
    const unsigned aaddr = sa + ((wm + hs * 8 + lr) * 24 + kc * 8) * 2;
    const unsigned baddr = sb + ((hs * 8 + lr) * 136 + wn + kc * 8) * 2;
    const unsigned ALO = 128 * 24 * 2;
    const unsigned ABUF = 2 * 128 * 24 * 2;
    const unsigned BBUF = 16 * 136 * 2;

    float acc[4][4][4] = {};

    uint4 rah = *(const uint4*)(Chp + (size_t)arow * 768 + ac16 * 8);
    uint4 ral = *(const uint4*)(Clp + (size_t)arow * 768 + ac16 * 8);
    float4 rb0 = *(const float4*)(Bp + (size_t)bk * 768 + bn4);
    float4 rb1 = *(const float4*)(Bp + (size_t)bk * 768 + bn4 + 64);
    {
        *(uint4*)&As[0][arow * 24 + ac16 * 8]        = rah;
        *(uint4*)&As[0][3072 + arow * 24 + ac16 * 8] = ral;
        *(uint2*)&Bs[0][bk * 136 + bn4]      = pack4h(rb0);
        *(uint2*)&Bs[0][bk * 136 + bn4 + 64] = pack4h(rb1);
    }
    __syncthreads();

    for (int kt = 0; kt < 48; ++kt) {
        const int cur = kt & 1;
        if (kt < 47) {
            rah = *(const uint4*)(Chp + (size_t)arow * 768 + (kt + 1) * 16 + ac16 * 8);
            ral = *(const uint4*)(Clp + (size_t)arow * 768 + (kt + 1) * 16 + ac16 * 8);
            rb0 = *(const float4*)(Bp + (size_t)((kt + 1) * 16 + bk) * 768 + bn4);
            rb1 = *(const float4*)(Bp + (size_t)((kt + 1) * 16 + bk) * 768 + bn4 + 64);
        }
        unsigned af[4][4], bh[4][2];
        #pragma unroll
        for (int n2 = 0; n2 < 2; ++n2)
            LDSM_X4T(bh[2*n2][0], bh[2*n2][1], bh[2*n2+1][0], bh[2*n2+1][1],
                     baddr + cur * BBUF + n2 * 32);
        #pragma unroll
        for (int mt = 0; mt < 4; ++mt)
            LDSM_X4(af[mt][0], af[mt][1], af[mt][2], af[mt][3],
                    aaddr + cur * ABUF + mt * 768);
        #pragma unroll
        for (int mt = 0; mt < 4; ++mt)
            #pragma unroll
            for (int nt = 0; nt < 4; ++nt)
                MMA16(acc[mt][nt], af[mt], bh[nt]);
        #pragma unroll
        for (int mt = 0; mt < 4; ++mt)
            LDSM_X4(af[mt][0], af[mt][1], af[mt][2], af[mt][3],
                    aaddr + cur * ABUF + mt * 768 + ALO);
        #pragma unroll
        for (int mt = 0; mt < 4; ++mt)
            #pragma unroll
            for (int nt = 0; nt < 4; ++nt)
                MMA16(acc[mt][nt], af[mt], bh[nt]);
        if (kt < 47) {
            const int nb = cur ^ 1;
            *(uint4*)&As[nb][arow * 24 + ac16 * 8]        = rah;
            *(uint4*)&As[nb][3072 + arow * 24 + ac16 * 8] = ral;
            *(uint2*)&Bs[nb][bk * 136 + bn4]      = pack4h(rb0);
            *(uint2*)&Bs[nb][bk * 136 + bn4 + 64] = pack4h(rb1);
        }
        __syncthreads();
    }

    const int g = lane >> 2, th = lane & 3;
    #pragma unroll
    for (int nt = 0; nt < 4; ++nt) {
        const int c = bx * 128 + wn + nt * 8 + 2 * th;
        const float b0v = bo[c], b1v = bo[c + 1];
        #pragma unroll
        for (int mt = 0; mt < 4; ++mt) {
            const int m = by * 128 + wm + mt * 16 + g;
            *(float2*)(out + (size_t)m * 768 + c) =
                make_float2(acc[mt][nt][0] + b0v, acc[mt][nt][1] + b1v);
            *(float2*)(out + (size_t)(m + 8) * 768 + c) =
                make_float2(acc[mt][nt][2] + b0v, acc[mt][nt][3] + b1v);
        }
    }
}

// ---------------------------------------------------------------------------
extern "C" void kernel_launch(void* const* d_in, const int* in_sizes, int n_in,
                              void* d_out, int out_size) {
    const float* x     = (const float*)d_in[0];
    const float* Wq    = (const float*)d_in[1];
    const float* Wkv   = (const float*)d_in[2];
    const float* mpre  = (const float*)d_in[3];
    const float* mpost = (const float*)d_in[4];
    const float* Wo    = (const float*)d_in[5];
    const float* bo    = (const float*)d_in[6];
    float* out = (float*)d_out;

    k_qkv    <<<dim3(18, 64),   256>>>(x, Wq, Wkv);
    k_dots   <<<dim3(8, 8, 96), 256>>>();
    k_mixsoft<<<8192,           512>>>(mpre, mpost);
    k_av     <<<dim3(8, 96),    256>>>();
    k_out    <<<dim3(6, 64),    256>>>(Wo, bo, out);
}

// round 9
// speedup vs baseline: 1.1670x; 1.1670x over previous
#include <cuda_runtime.h>
#include <cuda_fp16.h>
#include <math.h>

#define Bb 8
#define Nn 1024
#define Hh 12

#define QKVSZ ((size_t)Bb*Hh*Nn*64)

// Scratch (static device globals)
__device__ __half g_Qh[QKVSZ], g_Ql[QKVSZ];
__device__ __half g_Kh[QKVSZ];
__device__ __half g_Vh[QKVSZ];
__device__ __half g_S[(size_t)Bb*Hh*Nn*Nn];   // fp16 raw logits
__device__ __half g_P[(size_t)Bb*Hh*Nn*Nn];   // fp16 post-mixed attn
__device__ __half g_Ch[(size_t)Bb*Nn*768], g_Cl[(size_t)Bb*Nn*768];

// ---------------------------------------------------------------------------
__device__ __forceinline__ void split2(float a, float b, unsigned &h, unsigned &l) {
    __half ha = __float2half_rn(a), hb = __float2half_rn(b);
    __half2 H = __halves2half2(ha, hb);
    __half2 L = __halves2half2(__float2half_rn(a - __half2float(ha)),
                               __float2half_rn(b - __half2float(hb)));
    h = *(unsigned*)&H; l = *(unsigned*)&L;
}
__device__ __forceinline__ void split4(float4 v, uint2 &h, uint2 &l) {
    split2(v.x, v.y, h.x, l.x); split2(v.z, v.w, h.y, l.y);
}
__device__ __forceinline__ uint2 pack4h(float4 v) {
    __half2 a = __floats2half2_rn(v.x, v.y);
    __half2 b = __floats2half2_rn(v.z, v.w);
    uint2 r; r.x = *(unsigned*)&a; r.y = *(unsigned*)&b; return r;
}
__device__ __forceinline__ void store_hl(__half* Gh, __half* Gl, size_t idx,
                                         float v0, float v1) {
    __half h0 = __float2half_rn(v0), h1 = __float2half_rn(v1);
    __half l0 = __float2half_rn(v0 - __half2float(h0));
    __half l1 = __float2half_rn(v1 - __half2float(h1));
    *(__half2*)(Gh + idx) = __halves2half2(h0, h1);
    *(__half2*)(Gl + idx) = __halves2half2(l0, l1);
}

#define LDSM_X4(r0, r1, r2, r3, a) \
  asm volatile("ldmatrix.sync.aligned.m8n8.x4.shared.b16 {%0,%1,%2,%3},[%4];" \
               : "=r"(r0), "=r"(r1), "=r"(r2), "=r"(r3) : "r"(a))
#define LDSM_X4T(r0, r1, r2, r3, a) \
  asm volatile("ldmatrix.sync.aligned.m8n8.x4.trans.shared.b16 {%0,%1,%2,%3},[%4];" \
               : "=r"(r0), "=r"(r1), "=r"(r2), "=r"(r3) : "r"(a))
#define MMA16(c, a, b) \
  asm volatile("mma.sync.aligned.m16n8k16.row.col.f32.f16.f16.f32 " \
               "{%0,%1,%2,%3},{%4,%5,%6,%7},{%8,%9},{%0,%1,%2,%3};" \
               : "+f"(c[0]), "+f"(c[1]), "+f"(c[2]), "+f"(c[3]) \
               : "r"(a[0]), "r"(a[1]), "r"(a[2]), "r"(a[3]), "r"(b[0]), "r"(b[1]))

// ---------------------------------------------------------------------------
// K1: QKV projection. x @ fp16(W). Q: hi/lo split (scale 1/8 folded);
// K,V: plain fp16. 2 mma passes, double-buffered. grid (18, 64).
// ---------------------------------------------------------------------------
__global__ __launch_bounds__(256, 2) void k_qkv(const float* __restrict__ x,
                                                const float* __restrict__ Wq,
                                                const float* __restrict__ Wkv) {
    __shared__ __half As[2][2 * 128 * 24];
    __shared__ __half Bs[2][16 * 136];
    const int tid = threadIdx.x, lane = tid & 31, w = tid >> 5;
    const int bx = blockIdx.x, by = blockIdx.y;
    const int nglob = bx * 128;
    const float* Bp = (nglob < 768) ? (Wq + nglob) : (Wkv + (nglob - 768));
    const int ldb = (nglob < 768) ? 768 : 1536;
    const int wm = (w >> 2) * 64, wn = (w & 3) * 32;

    const int ar = tid >> 2, ak4 = (tid & 3) * 4;
    const int bk = tid >> 4, bn4 = (tid & 15) * 4;
    const float* Ap = x + ((size_t)by * 128 + ar) * 768 + ak4;

    const int lr = lane & 7, hs = (lane >> 3) & 1, kc = lane >> 4;
    const unsigned sa = (unsigned)__cvta_generic_to_shared(&As[0][0]);
    const unsigned sb = (unsigned)__cvta_generic_to_shared(&Bs[0][0]);
    const unsigned aaddr = sa + ((wm + hs * 8 + lr) * 24 + kc * 8) * 2;
    const unsigned baddr = sb + ((hs * 8 + lr) * 136 + wn + kc * 8) * 2;
    const unsigned ALO = 128 * 24 * 2;
    const unsigned ABUF = 2 * 128 * 24 * 2;
    const unsigned BBUF = 16 * 136 * 2;

    float acc[4][4][4] = {};

    float4 ra0 = *(const float4*)(Ap);
    float4 ra1 = *(const float4*)(Ap + (size_t)64 * 768);
    float4 rb0 = *(const float4*)(Bp + (size_t)bk * ldb + bn4);
    float4 rb1 = *(const float4*)(Bp + (size_t)bk * ldb + bn4 + 64);
    {
        uint2 h, l;
        split4(ra0, h, l);
        *(uint2*)&As[0][ar * 24 + ak4] = h;        *(uint2*)&As[0][3072 + ar * 24 + ak4] = l;
        split4(ra1, h, l);
        *(uint2*)&As[0][(ar + 64) * 24 + ak4] = h; *(uint2*)&As[0][3072 + (ar + 64) * 24 + ak4] = l;
        *(uint2*)&Bs[0][bk * 136 + bn4]      = pack4h(rb0);
        *(uint2*)&Bs[0][bk * 136 + bn4 + 64] = pack4h(rb1);
    }
    __syncthreads();

    for (int kt = 0; kt < 48; ++kt) {
        const int cur = kt & 1;
        if (kt < 47) {
            ra0 = *(const float4*)(Ap + (kt + 1) * 16);
            ra1 = *(const float4*)(Ap + (size_t)64 * 768 + (kt + 1) * 16);
            rb0 = *(const float4*)(Bp + (size_t)((kt + 1) * 16 + bk) * ldb + bn4);
            rb1 = *(const float4*)(Bp + (size_t)((kt + 1) * 16 + bk) * ldb + bn4 + 64);
        }
        unsigned af[4][4], bh[4][2];
        #pragma unroll
        for (int n2 = 0; n2 < 2; ++n2)
            LDSM_X4T(bh[2*n2][0], bh[2*n2][1], bh[2*n2+1][0], bh[2*n2+1][1],
                     baddr + cur * BBUF + n2 * 32);
        #pragma unroll
        for (int mt = 0; mt < 4; ++mt)
            LDSM_X4(af[mt][0], af[mt][1], af[mt][2], af[mt][3],
                    aaddr + cur * ABUF + mt * 768);
        #pragma unroll
        for (int mt = 0; mt < 4; ++mt)
            #pragma unroll
            for (int nt = 0; nt < 4; ++nt)
                MMA16(acc[mt][nt], af[mt], bh[nt]);
        #pragma unroll
        for (int mt = 0; mt < 4; ++mt)
            LDSM_X4(af[mt][0], af[mt][1], af[mt][2], af[mt][3],
                    aaddr + cur * ABUF + mt * 768 + ALO);
        #pragma unroll
        for (int mt = 0; mt < 4; ++mt)
            #pragma unroll
            for (int nt = 0; nt < 4; ++nt)
                MMA16(acc[mt][nt], af[mt], bh[nt]);
        if (kt < 47) {
            const int nb = cur ^ 1;
            uint2 h, l;
            split4(ra0, h, l);
            *(uint2*)&As[nb][ar * 24 + ak4] = h;        *(uint2*)&As[nb][3072 + ar * 24 + ak4] = l;
            split4(ra1, h, l);
            *(uint2*)&As[nb][(ar + 64) * 24 + ak4] = h; *(uint2*)&As[nb][3072 + (ar + 64) * 24 + ak4] = l;
            *(uint2*)&Bs[nb][bk * 136 + bn4]      = pack4h(rb0);
            *(uint2*)&Bs[nb][bk * 136 + bn4 + 64] = pack4h(rb1);
        }
        __syncthreads();
    }

    const int g = lane >> 2, th = lane & 3;
    #pragma unroll
    for (int nt = 0; nt < 4; ++nt) {
        const int col = nglob + wn + nt * 8 + 2 * th;
        const int mat = col / 768;
        const int within = col - mat * 768;
        const int head = within >> 6, d = within & 63;
        #pragma unroll
        for (int mt = 0; mt < 4; ++mt) {
            const int m0 = by * 128 + wm + mt * 16 + g;
            const int b = m0 >> 10, nr = m0 & 1023;
            const size_t base = (((size_t)b * 12 + head) * 1024 + nr) * 64 + d;
            if (mat == 0) {
                store_hl(g_Qh, g_Ql, base,          acc[mt][nt][0] * 0.125f, acc[mt][nt][1] * 0.125f);
                store_hl(g_Qh, g_Ql, base + 8 * 64, acc[mt][nt][2] * 0.125f, acc[mt][nt][3] * 0.125f);
            } else {
                __half* G = (mat == 1) ? g_Kh : g_Vh;
                *(__half2*)(G + base)          = __floats2half2_rn(acc[mt][nt][0], acc[mt][nt][1]);
                *(__half2*)(G + base + 8 * 64) = __floats2half2_rn(acc[mt][nt][2], acc[mt][nt][3]);
            }
        }
    }
}

// ---------------------------------------------------------------------------
// K2: logits = (Q/8) @ K^T per (b,h). Passes: Qh*Kh + Ql*Kh. -> fp16 g_S.
// grid (8,8,96)
// ---------------------------------------------------------------------------
__global__ __launch_bounds__(256, 2) void k_dots() {
    __shared__ __half Qs[2 * 128 * 40];
    __shared__ __half Ks[128 * 40];
    const int tid = threadIdx.x, lane = tid & 31, w = tid >> 5;
    const int jt = blockIdx.x, it = blockIdx.y, bh = blockIdx.z;
    const __half* Qhp = g_Qh + (size_t)bh * 65536 + (size_t)it * 128 * 64;
    const __half* Qlp = g_Ql + (size_t)bh * 65536 + (size_t)it * 128 * 64;
    const __half* Khp = g_Kh + (size_t)bh * 65536 + (size_t)jt * 128 * 64;
    __half* Sp = g_S + (size_t)bh * Nn * Nn;
    const int wm = (w >> 2) * 64, wn = (w & 3) * 32;

    const int lr = lane & 7, hs = (lane >> 3) & 1, kc = lane >> 4;
    const unsigned sq = (unsigned)__cvta_generic_to_shared(Qs);
    const unsigned sk = (unsigned)__cvta_generic_to_shared(Ks);
    const unsigned aaddr = sq + ((wm + hs * 8 + lr) * 40 + kc * 8) * 2;
    const unsigned kaddr = sk + ((wn + hs * 8 + lr) * 40 + kc * 8) * 2;
    const unsigned PLO = 128 * 40 * 2;

    float acc[4][4][4] = {};

    for (int kt = 0; kt < 2; ++kt) {
        #pragma unroll
        for (int j = 0; j < 2; ++j) {
            const int u = j * 256 + tid;
            const int row = u >> 2, c16 = u & 3;
            const int goff = row * 64 + kt * 32 + c16 * 8;
            const int soff = row * 40 + c16 * 8;
            *(uint4*)&Qs[soff]        = *(const uint4*)(Qhp + goff);
            *(uint4*)&Qs[5120 + soff] = *(const uint4*)(Qlp + goff);
            *(uint4*)&Ks[soff]        = *(const uint4*)(Khp + goff);
        }
        __syncthreads();
        #pragma unroll
        for (int kk = 0; kk < 32; kk += 16) {
            unsigned bkh[4][2], af[4][4];
            #pragma unroll
            for (int n2 = 0; n2 < 2; ++n2)
                LDSM_X4(bkh[2*n2][0], bkh[2*n2+1][0], bkh[2*n2][1], bkh[2*n2+1][1],
                        kaddr + n2 * 1280 + kk * 2);
            #pragma unroll
            for (int mt = 0; mt < 4; ++mt)
                LDSM_X4(af[mt][0], af[mt][1], af[mt][2], af[mt][3],
                        aaddr + mt * 1280 + kk * 2);
            #pragma unroll
            for (int mt = 0; mt < 4; ++mt)
                #pragma unroll
                for (int nt = 0; nt < 4; ++nt)
                    MMA16(acc[mt][nt], af[mt], bkh[nt]);
            #pragma unroll
            for (int mt = 0; mt < 4; ++mt)
                LDSM_X4(af[mt][0], af[mt][1], af[mt][2], af[mt][3],
                        aaddr + mt * 1280 + kk * 2 + PLO);
            #pragma unroll
            for (int mt = 0; mt < 4; ++mt)
                #pragma unroll
                for (int nt = 0; nt < 4; ++nt)
                    MMA16(acc[mt][nt], af[mt], bkh[nt]);
        }
        __syncthreads();
    }

    const int g = lane >> 2, th = lane & 3;
    #pragma unroll
    for (int mt = 0; mt < 4; ++mt) {
        const int m = it * 128 + wm + mt * 16 + g;
        #pragma unroll
        for (int nt = 0; nt < 4; ++nt) {
            const int c = jt * 128 + wn + nt * 8 + 2 * th;
            *(__half2*)(Sp + (size_t)m * 1024 + c) =
                __floats2half2_rn(acc[mt][nt][0], acc[mt][nt][1]);
            *(__half2*)(Sp + (size_t)(m + 8) * 1024 + c) =
                __floats2half2_rn(acc[mt][nt][2], acc[mt][nt][3]);
        }
    }
}

// ---------------------------------------------------------------------------
// K3: mix_pre -> softmax -> mix_post; fp16 g_S -> fp16 g_P.
// 256 threads; each thread owns j in {2t, 2t+1, 512+2t, 512+2t+1}:
// all smem traffic and g_P stores are __half2.
// ---------------------------------------------------------------------------
__global__ __launch_bounds__(256) void k_mixsoft(const float* __restrict__ mix_pre,
                                                 const float* __restrict__ mix_post) {
    __shared__ __half raw[12 * 1024];
    __shared__ float pre[144], post[144];
    __shared__ float wred[96];
    __shared__ float gstat[24];
    const int t = threadIdx.x;
    const int b = blockIdx.x >> 10, i = blockIdx.x & 1023;
    if (t < 144) { pre[t] = mix_pre[t]; post[t] = mix_post[t]; }
    const size_t rowbase = (size_t)b * 12 * 1048576 + (size_t)i * 1024;

    #pragma unroll
    for (int u = 0; u < 6; ++u) {
        const int v = u * 256 + t;
        const int h = v >> 7;
        const int j8 = (v & 127) * 8;
        *(uint4*)&raw[h * 1024 + j8] =
            *(const uint4*)(g_S + rowbase + (size_t)h * 1048576 + j8);
    }
    __syncthreads();

    float mx[12][4];
    #pragma unroll
    for (int c = 0; c < 2; ++c) {
        float rv[12][2];
        #pragma unroll
        for (int h = 0; h < 12; ++h) {
            __half2 p2 = *(const __half2*)&raw[h * 1024 + c * 512 + 2 * t];
            float2 f2 = __half22float2(p2);
            rv[h][0] = f2.x; rv[h][1] = f2.y;
        }
        #pragma unroll
        for (int g = 0; g < 12; ++g) {
            float a0 = 0.f, a1 = 0.f;
            #pragma unroll
            for (int h = 0; h < 12; ++h) {
                float p = pre[h * 12 + g];
                a0 += rv[h][0] * p;
                a1 += rv[h][1] * p;
            }
            mx[g][c * 2] = a0; mx[g][c * 2 + 1] = a1;
        }
    }

    const int lane = t & 31, wid = t >> 5;
    #pragma unroll
    for (int g = 0; g < 12; ++g) {
        float m = fmaxf(fmaxf(mx[g][0], mx[g][1]), fmaxf(mx[g][2], mx[g][3]));
        #pragma unroll
        for (int o = 16; o > 0; o >>= 1) m = fmaxf(m, __shfl_xor_sync(0xffffffffu, m, o));
        if (lane == 0) wred[g * 8 + wid] = m;
    }
    __syncthreads();
    if (t < 12) {
        float m = wred[t * 8];
        #pragma unroll
        for (int w2 = 1; w2 < 8; ++w2) m = fmaxf(m, wred[t * 8 + w2]);
        gstat[t] = m;
    }
    __syncthreads();
    #pragma unroll
    for (int g = 0; g < 12; ++g) {
        float mg = gstat[g];
        float s = 0.f;
        #pragma unroll
        for (int r = 0; r < 4; ++r) { mx[g][r] = __expf(mx[g][r] - mg); s += mx[g][r]; }
        #pragma unroll
        for (int o = 16; o > 0; o >>= 1) s += __shfl_xor_sync(0xffffffffu, s, o);
        if (lane == 0) wred[g * 8 + wid] = s;
    }
    __syncthreads();
    if (t < 12) {
        float s = 0.f;
        #pragma unroll
        for (int w2 = 0; w2 < 8; ++w2) s += wred[t * 8 + w2];
        gstat[12 + t] = 1.0f / s;
    }
    __syncthreads();
    #pragma unroll
    for (int g = 0; g < 12; ++g) {
        float inv = gstat[12 + g];
        #pragma unroll
        for (int r = 0; r < 4; ++r) mx[g][r] *= inv;
    }
    #pragma unroll
    for (int h = 0; h < 12; ++h) {
        float o0 = 0.f, o1 = 0.f, o2 = 0.f, o3 = 0.f;
        #pragma unroll
        for (int g = 0; g < 12; ++g) {
            float p = post[g * 12 + h];
            o0 += mx[g][0] * p; o1 += mx[g][1] * p;
            o2 += mx[g][2] * p; o3 += mx[g][3] * p;
        }
        __half* dst = g_P + rowbase + (size_t)h * 1048576;
        *(__half2*)(dst + 2 * t)       = __floats2half2_rn(o0, o1);
        *(__half2*)(dst + 512 + 2 * t) = __floats2half2_rn(o2, o3);
    }
}

// ---------------------------------------------------------------------------
// K4: O = attn(fp16) @ Vh(fp16) per (b,h) -> g_Ch/g_Cl. Single mma pass.
// Double-buffered. grid (8 it, 96 bh)
// ---------------------------------------------------------------------------
__global__ __launch_bounds__(256, 2) void k_av() {
    __shared__ __half As[2][128 * 40];
    __shared__ __half Vs[2][32 * 72];
    const int tid = threadIdx.x, lane = tid & 31, w = tid >> 5;
    const int it = blockIdx.x, bh = blockIdx.y;
    const int b = bh / 12, h = bh % 12;
    const __half* Pp  = g_P  + (size_t)bh * 1048576 + (size_t)it * 131072;
    const __half* Vhp = g_Vh + (size_t)bh * 65536;
    const int wm = (w >> 1) * 32, wn = (w & 1) * 32;

    const int arow = tid >> 2, ac16 = tid & 3;
    const int vrow = tid >> 3, vc16 = tid & 7;

    const int lr = lane & 7, hs = (lane >> 3) & 1, kc = lane >> 4;
    const unsigned sa = (unsigned)__cvta_generic_to_shared(&As[0][0]);
    const unsigned sb = (unsigned)__cvta_generic_to_shared(&Vs[0][0]);
    const unsigned aaddr = sa + ((wm + hs * 8 + lr) * 40 + kc * 8) * 2;
    const unsigned baddr = sb + ((hs * 8 + lr) * 72 + wn + kc * 8) * 2;
    const unsigned ABUF = 128 * 40 * 2;
    const unsigned VBUF = 32 * 72 * 2;

    float acc[2][4][4] = {};

    uint4 pa0 = *(const uint4*)(Pp + (size_t)arow * 1024 + ac16 * 8);
    uint4 pa1 = *(const uint4*)(Pp + (size_t)(arow + 64) * 1024 + ac16 * 8);
    uint4 pv0 = *(const uint4*)(Vhp + vrow * 64 + vc16 * 8);
    {
        *(uint4*)&As[0][arow * 40 + ac16 * 8]        = pa0;
        *(uint4*)&As[0][(arow + 64) * 40 + ac16 * 8] = pa1;
        *(uint4*)&Vs[0][vrow * 72 + vc16 * 8]        = pv0;
    }
    __syncthreads();

    for (int kt = 0; kt < 32; ++kt) {
        const int cur = kt & 1;
        if (kt < 31) {
            pa0 = *(const uint4*)(Pp + (size_t)arow * 1024 + (kt + 1) * 32 + ac16 * 8);
            pa1 = *(const uint4*)(Pp + (size_t)(arow + 64) * 1024 + (kt + 1) * 32 + ac16 * 8);
            pv0 = *(const uint4*)(Vhp + (size_t)((kt + 1) * 32 + vrow) * 64 + vc16 * 8);
        }
        #pragma unroll
        for (int kk = 0; kk < 32; kk += 16) {
            unsigned af[2][4], bvh[4][2];
            #pragma unroll
            for (int n2 = 0; n2 < 2; ++n2)
                LDSM_X4T(bvh[2*n2][0], bvh[2*n2][1], bvh[2*n2+1][0], bvh[2*n2+1][1],
                         baddr + cur * VBUF + kk * 144 + n2 * 32);
            #pragma unroll
            for (int mt = 0; mt < 2; ++mt)
                LDSM_X4(af[mt][0], af[mt][1], af[mt][2], af[mt][3],
                        aaddr + cur * ABUF + mt * 1280 + kk * 2);
            #pragma unroll
            for (int mt = 0; mt < 2; ++mt)
                #pragma unroll
                for (int nt = 0; nt < 4; ++nt)
                    MMA16(acc[mt][nt], af[mt], bvh[nt]);
        }
        if (kt < 31) {
            const int nb = cur ^ 1;
            *(uint4*)&As[nb][arow * 40 + ac16 * 8]        = pa0;
            *(uint4*)&As[nb][(arow + 64) * 40 + ac16 * 8] = pa1;
            *(uint4*)&Vs[nb][vrow * 72 + vc16 * 8]        = pv0;
        }
        __syncthreads();
    }

    const int g = lane >> 2, th = lane & 3;
    #pragma unroll
    for (int mt = 0; mt < 2; ++mt) {
        const int m = it * 128 + wm + mt * 16 + g;
        #pragma unroll
        for (int nt = 0; nt < 4; ++nt) {
            const int c = wn + nt * 8 + 2 * th;
            const size_t base = ((size_t)b * 1024 + m) * 768 + h * 64 + c;
            store_hl(g_Ch, g_Cl, base,             acc[mt][nt][0], acc[mt][nt][1]);
            store_hl(g_Ch, g_Cl, base + 8 * 768,   acc[mt][nt][2], acc[mt][nt][3]);
        }
    }
}

// ---------------------------------------------------------------------------
// K5: out = Ctx(hi/lo) @ fp16(Wo) + bo. 2 mma passes, double buffered.
// grid (6, 64)
// ---------------------------------------------------------------------------
__global__ __launch_bounds__(256, 2) void k_out(const float* __restrict__ Wo,
                                                const float* __restrict__ bo,
                                                float* __restrict__ out) {
    __shared__ __half As[2][2 * 128 * 24];
    __shared__ __half Bs[2][16 * 136];
    const int tid = threadIdx.x, lane = tid & 31, w = tid >> 5;
    const int bx = blockIdx.x, by = blockIdx.y;
    const float* Bp = Wo + bx * 128;
    const int wm = (w >> 2) * 64, wn = (w & 3) * 32;

    const int arow = tid >> 1, ac16 = tid & 1;
    const int bk = tid >> 4, bn4 = (tid & 15) * 4;
    const __half* Chp = g_Ch + (size_t)by * 128 * 768;
    const __half* Clp = g_Cl + (size_t)by * 128 * 768;

    const int lr = lane & 7, hs = (lane >> 3) & 1, kc = lane >> 4;
    const unsigned sa = (unsigned)__cvta_generic_to_shared(&As[0][0]);
    const unsigned sb = (unsigned)__cvta_generic_to_shared(&Bs[0][0]);
    const unsigned aaddr = sa + ((wm + hs * 8 + lr) * 24 + kc * 8) * 2;
    const unsigned baddr = sb + ((hs * 8 + lr) * 136 + wn + kc * 8) * 2;
    const unsigned ALO = 128 * 24 * 2;
    const unsigned ABUF = 2 * 128 * 24 * 2;
    const unsigned BBUF = 16 * 136 * 2;

    float acc[4][4][4] = {};

    uint4 rah = *(const uint4*)(Chp + (size_t)arow * 768 + ac16 * 8);
    uint4 ral = *(const uint4*)(Clp + (size_t)arow * 768 + ac16 * 8);
    float4 rb0 = *(const float4*)(Bp + (size_t)bk * 768 + bn4);
    float4 rb1 = *(const float4*)(Bp + (size_t)bk * 768 + bn4 + 64);
    {
        *(uint4*)&As[0][arow * 24 + ac16 * 8]        = rah;
        *(uint4*)&As[0][3072 + arow * 24 + ac16 * 8] = ral;
        *(uint2*)&Bs[0][bk * 136 + bn4]      = pack4h(rb0);
        *(uint2*)&Bs[0][bk * 136 + bn4 + 64] = pack4h(rb1);
    }
    __syncthreads();

    for (int kt = 0; kt < 48; ++kt) {
        const int cur = kt & 1;
        if (kt < 47) {
            rah = *(const uint4*)(Chp + (size_t)arow * 768 + (kt + 1) * 16 + ac16 * 8);
            ral = *(const uint4*)(Clp + (size_t)arow * 768 + (kt + 1) * 16 + ac16 * 8);
            rb0 = *(const float4*)(Bp + (size_t)((kt + 1) * 16 + bk) * 768 + bn4);
            rb1 = *(const float4*)(Bp + (size_t)((kt + 1) * 16 + bk) * 768 + bn4 + 64);
        }
        unsigned af[4][4], bh[4][2];
        #pragma unroll
        for (int n2 = 0; n2 < 2; ++n2)
            LDSM_X4T(bh[2*n2][0], bh[2*n2][1], bh[2*n2+1][0], bh[2*n2+1][1],
                     baddr + cur * BBUF + n2 * 32);
        #pragma unroll
        for (int mt = 0; mt < 4; ++mt)
            LDSM_X4(af[mt][0], af[mt][1], af[mt][2], af[mt][3],
                    aaddr + cur * ABUF + mt * 768);
        #pragma unroll
        for (int mt = 0; mt < 4; ++mt)
            #pragma unroll
            for (int nt = 0; nt < 4; ++nt)
                MMA16(acc[mt][nt], af[mt], bh[nt]);
        #pragma unroll
        for (int mt = 0; mt < 4; ++mt)
            LDSM_X4(af[mt][0], af[mt][1], af[mt][2], af[mt][3],
                    aaddr + cur * ABUF + mt * 768 + ALO);
        #pragma unroll
        for (int mt = 0; mt < 4; ++mt)
            #pragma unroll
            for (int nt = 0; nt < 4; ++nt)
                MMA16(acc[mt][nt], af[mt], bh[nt]);
        if (kt < 47) {
            const int nb = cur ^ 1;
            *(uint4*)&As[nb][arow * 24 + ac16 * 8]        = rah;
            *(uint4*)&As[nb][3072 + arow * 24 + ac16 * 8] = ral;
            *(uint2*)&Bs[nb][bk * 136 + bn4]      = pack4h(rb0);
            *(uint2*)&Bs[nb][bk * 136 + bn4 + 64] = pack4h(rb1);
        }
        __syncthreads();
    }

    const int g = lane >> 2, th = lane & 3;
    #pragma unroll
    for (int nt = 0; nt < 4; ++nt) {
        const int c = bx * 128 + wn + nt * 8 + 2 * th;
        const float b0v = bo[c], b1v = bo[c + 1];
        #pragma unroll
        for (int mt = 0; mt < 4; ++mt) {
            const int m = by * 128 + wm + mt * 16 + g;
            *(float2*)(out + (size_t)m * 768 + c) =
                make_float2(acc[mt][nt][0] + b0v, acc[mt][nt][1] + b1v);
            *(float2*)(out + (size_t)(m + 8) * 768 + c) =
                make_float2(acc[mt][nt][2] + b0v, acc[mt][nt][3] + b1v);
        }
    }
}

// ---------------------------------------------------------------------------
extern "C" void kernel_launch(void* const* d_in, const int* in_sizes, int n_in,
                              void* d_out, int out_size) {
    const float* x     = (const float*)d_in[0];
    const float* Wq    = (const float*)d_in[1];
    const float* Wkv   = (const float*)d_in[2];
    const float* mpre  = (const float*)d_in[3];
    const float* mpost = (const float*)d_in[4];
    const float* Wo    = (const float*)d_in[5];
    const float* bo    = (const float*)d_in[6];
    float* out = (float*)d_out;

    k_qkv    <<<dim3(18, 64),   256>>>(x, Wq, Wkv);
    k_dots   <<<dim3(8, 8, 96), 256>>>();
    k_mixsoft<<<8192,           256>>>(mpre, mpost);
    k_av     <<<dim3(8, 96),    256>>>();
    k_out    <<<dim3(6, 64),    256>>>(Wo, bo, out);
}

// round 10
// speedup vs baseline: 1.1855x; 1.0158x over previous
#include <cuda_runtime.h>
#include <cuda_fp16.h>
#include <math.h>

#define Bb 8
#define Nn 1024
#define Hh 12

#define QKVSZ ((size_t)Bb*Hh*Nn*64)

// Scratch (static device globals)
__device__ __half g_xh[(size_t)8192*768], g_xl[(size_t)8192*768];
__device__ __half g_Wh[(size_t)768*2304];      // fp16 [Wq|Wkv], row-major [768][2304]
__device__ __half g_Woh[(size_t)768*768];      // fp16 Wo
__device__ __half g_Qh[QKVSZ], g_Ql[QKVSZ];
__device__ __half g_Kh[QKVSZ];
__device__ __half g_Vh[QKVSZ];
__device__ __half g_S[(size_t)Bb*Hh*Nn*Nn];    // fp16 raw logits
__device__ __half g_P[(size_t)Bb*Hh*Nn*Nn];    // fp16 post-mixed attn
__device__ __half g_Ch[(size_t)Bb*Nn*768], g_Cl[(size_t)Bb*Nn*768];

// ---------------------------------------------------------------------------
__device__ __forceinline__ void split2(float a, float b, unsigned &h, unsigned &l) {
    __half ha = __float2half_rn(a), hb = __float2half_rn(b);
    __half2 H = __halves2half2(ha, hb);
    __half2 L = __halves2half2(__float2half_rn(a - __half2float(ha)),
                               __float2half_rn(b - __half2float(hb)));
    h = *(unsigned*)&H; l = *(unsigned*)&L;
}
__device__ __forceinline__ void split4(float4 v, uint2 &h, uint2 &l) {
    split2(v.x, v.y, h.x, l.x); split2(v.z, v.w, h.y, l.y);
}
__device__ __forceinline__ uint2 pack4h(float4 v) {
    __half2 a = __floats2half2_rn(v.x, v.y);
    __half2 b = __floats2half2_rn(v.z, v.w);
    uint2 r; r.x = *(unsigned*)&a; r.y = *(unsigned*)&b; return r;
}
__device__ __forceinline__ void store_hl(__half* Gh, __half* Gl, size_t idx,
                                         float v0, float v1) {
    __half h0 = __float2half_rn(v0), h1 = __float2half_rn(v1);
    __half l0 = __float2half_rn(v0 - __half2float(h0));
    __half l1 = __float2half_rn(v1 - __half2float(h1));
    *(__half2*)(Gh + idx) = __halves2half2(h0, h1);
    *(__half2*)(Gl + idx) = __halves2half2(l0, l1);
}

#define LDSM_X4(r0, r1, r2, r3, a) \
  asm volatile("ldmatrix.sync.aligned.m8n8.x4.shared.b16 {%0,%1,%2,%3},[%4];" \
               : "=r"(r0), "=r"(r1), "=r"(r2), "=r"(r3) : "r"(a))
#define LDSM_X4T(r0, r1, r2, r3, a) \
  asm volatile("ldmatrix.sync.aligned.m8n8.x4.trans.shared.b16 {%0,%1,%2,%3},[%4];" \
               : "=r"(r0), "=r"(r1), "=r"(r2), "=r"(r3) : "r"(a))
#define MMA16(c, a, b) \
  asm volatile("mma.sync.aligned.m16n8k16.row.col.f32.f16.f16.f32 " \
               "{%0,%1,%2,%3},{%4,%5,%6,%7},{%8,%9},{%0,%1,%2,%3};" \
               : "+f"(c[0]), "+f"(c[1]), "+f"(c[2]), "+f"(c[3]) \
               : "r"(a[0]), "r"(a[1]), "r"(a[2]), "r"(a[3]), "r"(b[0]), "r"(b[1]))
#define CP16(dst, src) \
  asm volatile("cp.async.ca.shared.global [%0], [%1], 16;" :: "r"(dst), "l"(src))
#define CPCOMMIT() asm volatile("cp.async.commit_group;")
#define CPWAIT0()  asm volatile("cp.async.wait_group 0;" ::: "memory")

// ---------------------------------------------------------------------------
// K0: prep — split x into fp16 hi/lo, quantize W's to fp16 (once).
// grid 8448 x 256, one float4 per thread.
// ---------------------------------------------------------------------------
__global__ __launch_bounds__(256) void k_prep(const float* __restrict__ x,
                                              const float* __restrict__ Wq,
                                              const float* __restrict__ Wkv,
                                              const float* __restrict__ Wo) {
    const size_t id = (size_t)blockIdx.x * 256 + threadIdx.x;
    if (id < 1572864) {                       // x: 8192*768/4
        float4 v = ((const float4*)x)[id];
        uint2 h, l; split4(v, h, l);
        *(uint2*)(g_xh + 4 * id) = h;
        *(uint2*)(g_xl + 4 * id) = l;
    } else if (id < 1720320) {                // Wq: 768*768/4
        const size_t f = id - 1572864;
        float4 v = ((const float4*)Wq)[f];
        const size_t e = 4 * f;
        const size_t k = e / 768, c = e % 768;
        *(uint2*)(g_Wh + k * 2304 + c) = pack4h(v);
    } else if (id < 2015232) {                // Wkv: 768*1536/4
        const size_t f = id - 1720320;
        float4 v = ((const float4*)Wkv)[f];
        const size_t e = 4 * f;
        const size_t k = e / 1536, c = e % 1536;
        *(uint2*)(g_Wh + k * 2304 + 768 + c) = pack4h(v);
    } else if (id < 2162688) {                // Wo: 768*768/4
        const size_t f = id - 2015232;
        float4 v = ((const float4*)Wo)[f];
        *(uint2*)(g_Woh + 4 * f) = pack4h(v);
    }
}

// ---------------------------------------------------------------------------
// K1: QKV projection. xh/xl @ g_Wh -> Q(hi/lo, scaled 1/8), K, V fp16.
// cp.async double-buffered. grid (18, 64).
// ---------------------------------------------------------------------------
__global__ __launch_bounds__(256, 2) void k_qkv() {
    __shared__ __align__(16) __half As[2][2 * 128 * 24];
    __shared__ __align__(16) __half Bs[2][16 * 136];
    const int tid = threadIdx.x, lane = tid & 31, w = tid >> 5;
    const int bx = blockIdx.x, by = blockIdx.y;
    const int nglob = bx * 128;
    const int wm = (w >> 2) * 64, wn = (w & 3) * 32;

    const int arow = tid >> 1, ac8 = (tid & 1) * 8;
    const int brow = tid >> 4, bc8 = (tid & 15) * 8;
    const __half* Ah = g_xh + ((size_t)by * 128 + arow) * 768 + ac8;
    const __half* Al = g_xl + ((size_t)by * 128 + arow) * 768 + ac8;
    const __half* Bp = g_Wh + (size_t)brow * 2304 + nglob + bc8;

    const int lr = lane & 7, hs = (lane >> 3) & 1, kc = lane >> 4;
    const unsigned sa = (unsigned)__cvta_generic_to_shared(&As[0][0]);
    const unsigned sb = (unsigned)__cvta_generic_to_shared(&Bs[0][0]);
    const unsigned aaddr = sa + ((wm + hs * 8 + lr) * 24 + kc * 8) * 2;
    const unsigned baddr = sb + ((hs * 8 + lr) * 136 + wn + kc * 8) * 2;
    const unsigned ALO = 128 * 24 * 2, ABUF = 2 * 128 * 24 * 2, BBUF = 16 * 136 * 2;
    const unsigned adst = sa + (arow * 24 + ac8) * 2;
    const unsigned bdst = sb + (brow * 136 + bc8) * 2;

    float acc[4][4][4] = {};

    CP16(adst, Ah);
    CP16(adst + ALO, Al);
    CP16(bdst, Bp);
    CPCOMMIT();

    for (int kt = 0; kt < 48; ++kt) {
        const int cur = kt & 1;
        CPWAIT0();
        __syncthreads();
        if (kt < 47) {
            const unsigned nb = (cur ^ 1);
            CP16(adst + nb * ABUF,       Ah + (kt + 1) * 16);
            CP16(adst + nb * ABUF + ALO, Al + (kt + 1) * 16);
            CP16(bdst + nb * BBUF,       Bp + (size_t)(kt + 1) * 16 * 2304);
            CPCOMMIT();
        }
        unsigned af[4][4], bh[4][2];
        #pragma unroll
        for (int n2 = 0; n2 < 2; ++n2)
            LDSM_X4T(bh[2*n2][0], bh[2*n2][1], bh[2*n2+1][0], bh[2*n2+1][1],
                     baddr + cur * BBUF + n2 * 32);
        #pragma unroll
        for (int mt = 0; mt < 4; ++mt)
            LDSM_X4(af[mt][0], af[mt][1], af[mt][2], af[mt][3],
                    aaddr + cur * ABUF + mt * 768);
        #pragma unroll
        for (int mt = 0; mt < 4; ++mt)
            #pragma unroll
            for (int nt = 0; nt < 4; ++nt)
                MMA16(acc[mt][nt], af[mt], bh[nt]);
        #pragma unroll
        for (int mt = 0; mt < 4; ++mt)
            LDSM_X4(af[mt][0], af[mt][1], af[mt][2], af[mt][3],
                    aaddr + cur * ABUF + mt * 768 + ALO);
        #pragma unroll
        for (int mt = 0; mt < 4; ++mt)
            #pragma unroll
            for (int nt = 0; nt < 4; ++nt)
                MMA16(acc[mt][nt], af[mt], bh[nt]);
    }

    const int g = lane >> 2, th = lane & 3;
    #pragma unroll
    for (int nt = 0; nt < 4; ++nt) {
        const int col = nglob + wn + nt * 8 + 2 * th;
        const int mat = col / 768;
        const int within = col - mat * 768;
        const int head = within >> 6, d = within & 63;
        #pragma unroll
        for (int mt = 0; mt < 4; ++mt) {
            const int m0 = by * 128 + wm + mt * 16 + g;
            const int b = m0 >> 10, nr = m0 & 1023;
            const size_t base = (((size_t)b * 12 + head) * 1024 + nr) * 64 + d;
            if (mat == 0) {
                store_hl(g_Qh, g_Ql, base,          acc[mt][nt][0] * 0.125f, acc[mt][nt][1] * 0.125f);
                store_hl(g_Qh, g_Ql, base + 8 * 64, acc[mt][nt][2] * 0.125f, acc[mt][nt][3] * 0.125f);
            } else {
                __half* G = (mat == 1) ? g_Kh : g_Vh;
                *(__half2*)(G + base)          = __floats2half2_rn(acc[mt][nt][0], acc[mt][nt][1]);
                *(__half2*)(G + base + 8 * 64) = __floats2half2_rn(acc[mt][nt][2], acc[mt][nt][3]);
            }
        }
    }
}

// ---------------------------------------------------------------------------
// K2: logits = (Q/8) @ K^T per (b,h). Single-stage cp.async (full 64-k tiles).
// Passes: Qh*Kh + Ql*Kh. grid (8,8,96)
// ---------------------------------------------------------------------------
__global__ __launch_bounds__(256, 2) void k_dots() {
    __shared__ __align__(16) __half Qs[2 * 128 * 72];
    __shared__ __align__(16) __half Ks[128 * 72];
    const int tid = threadIdx.x, lane = tid & 31, w = tid >> 5;
    const int jt = blockIdx.x, it = blockIdx.y, bh = blockIdx.z;
    const __half* Qhp = g_Qh + (size_t)bh * 65536 + (size_t)it * 128 * 64;
    const __half* Qlp = g_Ql + (size_t)bh * 65536 + (size_t)it * 128 * 64;
    const __half* Khp = g_Kh + (size_t)bh * 65536 + (size_t)jt * 128 * 64;
    __half* Sp = g_S + (size_t)bh * Nn * Nn;
    const int wm = (w >> 2) * 64, wn = (w & 3) * 32;

    const int lr = lane & 7, hs = (lane >> 3) & 1, kc = lane >> 4;
    const unsigned sq = (unsigned)__cvta_generic_to_shared(Qs);
    const unsigned sk = (unsigned)__cvta_generic_to_shared(Ks);
    const unsigned aaddr = sq + ((wm + hs * 8 + lr) * 72 + kc * 8) * 2;
    const unsigned kaddr = sk + ((wn + hs * 8 + lr) * 72 + kc * 8) * 2;
    const unsigned PLO = 128 * 72 * 2;

    // Stage everything: 128 rows x 64 halves per plane, pitch 72.
    #pragma unroll
    for (int j = 0; j < 4; ++j) {
        const int v = j * 256 + tid;           // 0..1023
        const int row = v >> 3, c8 = (v & 7) * 8;
        const unsigned d = (row * 72 + c8) * 2;
        CP16(sq + d,       Qhp + row * 64 + c8);
        CP16(sq + d + PLO, Qlp + row * 64 + c8);
        CP16(sk + d,       Khp + row * 64 + c8);
    }
    CPCOMMIT();
    CPWAIT0();
    __syncthreads();

    float acc[4][4][4] = {};

    #pragma unroll
    for (int kk = 0; kk < 64; kk += 16) {
        unsigned bkh[4][2], af[4][4];
        #pragma unroll
        for (int n2 = 0; n2 < 2; ++n2)
            LDSM_X4(bkh[2*n2][0], bkh[2*n2+1][0], bkh[2*n2][1], bkh[2*n2+1][1],
                    kaddr + n2 * 2304 + kk * 2);
        #pragma unroll
        for (int mt = 0; mt < 4; ++mt)
            LDSM_X4(af[mt][0], af[mt][1], af[mt][2], af[mt][3],
                    aaddr + mt * 2304 + kk * 2);
        #pragma unroll
        for (int mt = 0; mt < 4; ++mt)
            #pragma unroll
            for (int nt = 0; nt < 4; ++nt)
                MMA16(acc[mt][nt], af[mt], bkh[nt]);
        #pragma unroll
        for (int mt = 0; mt < 4; ++mt)
            LDSM_X4(af[mt][0], af[mt][1], af[mt][2], af[mt][3],
                    aaddr + mt * 2304 + kk * 2 + PLO);
        #pragma unroll
        for (int mt = 0; mt < 4; ++mt)
            #pragma unroll
            for (int nt = 0; nt < 4; ++nt)
                MMA16(acc[mt][nt], af[mt], bkh[nt]);
    }

    const int g = lane >> 2, th = lane & 3;
    #pragma unroll
    for (int mt = 0; mt < 4; ++mt) {
        const int m = it * 128 + wm + mt * 16 + g;
        #pragma unroll
        for (int nt = 0; nt < 4; ++nt) {
            const int c = jt * 128 + wn + nt * 8 + 2 * th;
            *(__half2*)(Sp + (size_t)m * 1024 + c) =
                __floats2half2_rn(acc[mt][nt][0], acc[mt][nt][1]);
            *(__half2*)(Sp + (size_t)(m + 8) * 1024 + c) =
                __floats2half2_rn(acc[mt][nt][2], acc[mt][nt][3]);
        }
    }
}

// ---------------------------------------------------------------------------
// K3: mix_pre -> softmax -> mix_post; fp16 g_S -> fp16 g_P. (round-9 proven)
// ---------------------------------------------------------------------------
__global__ __launch_bounds__(256) void k_mixsoft(const float* __restrict__ mix_pre,
                                                 const float* __restrict__ mix_post) {
    __shared__ __align__(16) __half raw[12 * 1024];
    __shared__ float pre[144], post[144];
    __shared__ float wred[96];
    __shared__ float gstat[24];
    const int t = threadIdx.x;
    const int b = blockIdx.x >> 10, i = blockIdx.x & 1023;
    if (t < 144) { pre[t] = mix_pre[t]; post[t] = mix_post[t]; }
    const size_t rowbase = (size_t)b * 12 * 1048576 + (size_t)i * 1024;

    #pragma unroll
    for (int u = 0; u < 6; ++u) {
        const int v = u * 256 + t;
        const int h = v >> 7;
        const int j8 = (v & 127) * 8;
        *(uint4*)&raw[h * 1024 + j8] =
            *(const uint4*)(g_S + rowbase + (size_t)h * 1048576 + j8);
    }
    __syncthreads();

    float mx[12][4];
    #pragma unroll
    for (int c = 0; c < 2; ++c) {
        float rv[12][2];
        #pragma unroll
        for (int h = 0; h < 12; ++h) {
            __half2 p2 = *(const __half2*)&raw[h * 1024 + c * 512 + 2 * t];
            float2 f2 = __half22float2(p2);
            rv[h][0] = f2.x; rv[h][1] = f2.y;
        }
        #pragma unroll
        for (int g = 0; g < 12; ++g) {
            float a0 = 0.f, a1 = 0.f;
            #pragma unroll
            for (int h = 0; h < 12; ++h) {
                float p = pre[h * 12 + g];
                a0 += rv[h][0] * p;
                a1 += rv[h][1] * p;
            }
            mx[g][c * 2] = a0; mx[g][c * 2 + 1] = a1;
        }
    }

    const int lane = t & 31, wid = t >> 5;
    #pragma unroll
    for (int g = 0; g < 12; ++g) {
        float m = fmaxf(fmaxf(mx[g][0], mx[g][1]), fmaxf(mx[g][2], mx[g][3]));
        #pragma unroll
        for (int o = 16; o > 0; o >>= 1) m = fmaxf(m, __shfl_xor_sync(0xffffffffu, m, o));
        if (lane == 0) wred[g * 8 + wid] = m;
    }
    __syncthreads();
    if (t < 12) {
        float m = wred[t * 8];
        #pragma unroll
        for (int w2 = 1; w2 < 8; ++w2) m = fmaxf(m, wred[t * 8 + w2]);
        gstat[t] = m;
    }
    __syncthreads();
    #pragma unroll
    for (int g = 0; g < 12; ++g) {
        float mg = gstat[g];
        float s = 0.f;
        #pragma unroll
        for (int r = 0; r < 4; ++r) { mx[g][r] = __expf(mx[g][r] - mg); s += mx[g][r]; }
        #pragma unroll
        for (int o = 16; o > 0; o >>= 1) s += __shfl_xor_sync(0xffffffffu, s, o);
        if (lane == 0) wred[g * 8 + wid] = s;
    }
    __syncthreads();
    if (t < 12) {
        float s = 0.f;
        #pragma unroll
        for (int w2 = 0; w2 < 8; ++w2) s += wred[t * 8 + w2];
        gstat[12 + t] = 1.0f / s;
    }
    __syncthreads();
    #pragma unroll
    for (int g = 0; g < 12; ++g) {
        float inv = gstat[12 + g];
        #pragma unroll
        for (int r = 0; r < 4; ++r) mx[g][r] *= inv;
    }
    #pragma unroll
    for (int h = 0; h < 12; ++h) {
        float o0 = 0.f, o1 = 0.f, o2 = 0.f, o3 = 0.f;
        #pragma unroll
        for (int g = 0; g < 12; ++g) {
            float p = post[g * 12 + h];
            o0 += mx[g][0] * p; o1 += mx[g][1] * p;
            o2 += mx[g][2] * p; o3 += mx[g][3] * p;
        }
        __half* dst = g_P + rowbase + (size_t)h * 1048576;
        *(__half2*)(dst + 2 * t)       = __floats2half2_rn(o0, o1);
        *(__half2*)(dst + 512 + 2 * t) = __floats2half2_rn(o2, o3);
    }
}

// ---------------------------------------------------------------------------
// K4: O = attn(fp16) @ Vh(fp16) per (b,h) -> g_Ch/g_Cl. Single mma pass,
// cp.async double-buffered. grid (8 it, 96 bh)
// ---------------------------------------------------------------------------
__global__ __launch_bounds__(256, 2) void k_av() {
    __shared__ __align__(16) __half As[2][128 * 40];
    __shared__ __align__(16) __half Vs[2][32 * 72];
    const int tid = threadIdx.x, lane = tid & 31, w = tid >> 5;
    const int it = blockIdx.x, bh = blockIdx.y;
    const int b = bh / 12, h = bh % 12;
    const __half* Pp  = g_P  + (size_t)bh * 1048576 + (size_t)it * 131072;
    const __half* Vhp = g_Vh + (size_t)bh * 65536;
    const int wm = (w >> 1) * 32, wn = (w & 1) * 32;

    const int arow = tid >> 2, ac8 = (tid & 3) * 8;
    const int vrow = tid >> 3, vc8 = (tid & 7) * 8;

    const int lr = lane & 7, hs = (lane >> 3) & 1, kc = lane >> 4;
    const unsigned sa = (unsigned)__cvta_generic_to_shared(&As[0][0]);
    const unsigned sb = (unsigned)__cvta_generic_to_shared(&Vs[0][0]);
    const unsigned aaddr = sa + ((wm + hs * 8 + lr) * 40 + kc * 8) * 2;
    const unsigned baddr = sb + ((hs * 8 + lr) * 72 + wn + kc * 8) * 2;
    const unsigned ABUF = 128 * 40 * 2;
    const unsigned VBUF = 32 * 72 * 2;
    const unsigned adst0 = sa + (arow * 40 + ac8) * 2;
    const unsigned adst1 = sa + ((arow + 64) * 40 + ac8) * 2;
    const unsigned vdst  = sb + (vrow * 72 + vc8) * 2;

    float acc[2][4][4] = {};

    CP16(adst0, Pp + (size_t)arow * 1024 + ac8);
    CP16(adst1, Pp + (size_t)(arow + 64) * 1024 + ac8);
    CP16(vdst,  Vhp + vrow * 64 + vc8);
    CPCOMMIT();

    for (int kt = 0; kt < 32; ++kt) {
        const int cur = kt & 1;
        CPWAIT0();
        __syncthreads();
        if (kt < 31) {
            const unsigned nb = cur ^ 1;
            CP16(adst0 + nb * ABUF, Pp + (size_t)arow * 1024 + (kt + 1) * 32 + ac8);
            CP16(adst1 + nb * ABUF, Pp + (size_t)(arow + 64) * 1024 + (kt + 1) * 32 + ac8);
            CP16(vdst + nb * VBUF,  Vhp + (size_t)((kt + 1) * 32 + vrow) * 64 + vc8);
            CPCOMMIT();
        }
        #pragma unroll
        for (int kk = 0; kk < 32; kk += 16) {
            unsigned af[2][4], bvh[4][2];
            #pragma unroll
            for (int n2 = 0; n2 < 2; ++n2)
                LDSM_X4T(bvh[2*n2][0], bvh[2*n2][1], bvh[2*n2+1][0], bvh[2*n2+1][1],
                         baddr + cur * VBUF + kk * 144 + n2 * 32);
            #pragma unroll
            for (int mt = 0; mt < 2; ++mt)
                LDSM_X4(af[mt][0], af[mt][1], af[mt][2], af[mt][3],
                        aaddr + cur * ABUF + mt * 1280 + kk * 2);
            #pragma unroll
            for (int mt = 0; mt < 2; ++mt)
                #pragma unroll
                for (int nt = 0; nt < 4; ++nt)
                    MMA16(acc[mt][nt], af[mt], bvh[nt]);
        }
    }

    const int g = lane >> 2, th = lane & 3;
    #pragma unroll
    for (int mt = 0; mt < 2; ++mt) {
        const int m = it * 128 + wm + mt * 16 + g;
        #pragma unroll
        for (int nt = 0; nt < 4; ++nt) {
            const int c = wn + nt * 8 + 2 * th;
            const size_t base = ((size_t)b * 1024 + m) * 768 + h * 64 + c;
            store_hl(g_Ch, g_Cl, base,             acc[mt][nt][0], acc[mt][nt][1]);
            store_hl(g_Ch, g_Cl, base + 8 * 768,   acc[mt][nt][2], acc[mt][nt][3]);
        }
    }
}

// ---------------------------------------------------------------------------
// K5: out = Ctx(hi/lo) @ g_Woh + bo. 2 mma passes, cp.async double-buffered.
// grid (6, 64)
// ---------------------------------------------------------------------------
__global__ __launch_bounds__(256, 2) void k_out(const float* __restrict__ bo,
                                                float* __restrict__ out) {
    __shared__ __align__(16) __half As[2][2 * 128 * 24];
    __shared__ __align__(16) __half Bs[2][16 * 136];
    const int tid = threadIdx.x, lane = tid & 31, w = tid >> 5;
    const int bx = blockIdx.x, by = blockIdx.y;
    const int wm = (w >> 2) * 64, wn = (w & 3) * 32;

    const int arow = tid >> 1, ac8 = (tid & 1) * 8;
    const int brow = tid >> 4, bc8 = (tid & 15) * 8;
    const __half* Chp = g_Ch + ((size_t)by * 128 + arow) * 768 + ac8;
    const __half* Clp = g_Cl + ((size_t)by * 128 + arow) * 768 + ac8;
    const __half* Bp  = g_Woh + (size_t)brow * 768 + bx * 128 + bc8;

    const int lr = lane & 7, hs = (lane >> 3) & 1, kc = lane >> 4;
    const unsigned sa = (unsigned)__cvta_generic_to_shared(&As[0][0]);
    const unsigned sb = (unsigned)__cvta_generic_to_shared(&Bs[0][0]);
    const unsigned aaddr = sa + ((wm + hs * 8 + lr) * 24 + kc * 8) * 2;
    const unsigned baddr = sb + ((hs * 8 + lr) * 136 + wn + kc * 8) * 2;
    const unsigned ALO = 128 * 24 * 2, ABUF = 2 * 128 * 24 * 2, BBUF = 16 * 136 * 2;
    const unsigned adst = sa + (arow * 24 + ac8) * 2;
    const unsigned bdst = sb + (brow * 136 + bc8) * 2;

    float acc[4][4][4] = {};

    CP16(adst,       Chp);
    CP16(adst + ALO, Clp);
    CP16(bdst,       Bp);
    CPCOMMIT();

    for (int kt = 0; kt < 48; ++kt) {
        const int cur = kt & 1;
        CPWAIT0();
        __syncthreads();
        if (kt < 47) {
            const unsigned nb = cur ^ 1;
            CP16(adst + nb * ABUF,       Chp + (kt + 1) * 16);
            CP16(adst + nb * ABUF + ALO, Clp + (kt + 1) * 16);
            CP16(bdst + nb * BBUF,       Bp + (size_t)(kt + 1) * 16 * 768);
            CPCOMMIT();
        }
        unsigned af[4][4], bh[4][2];
        #pragma unroll
        for (int n2 = 0; n2 < 2; ++n2)
            LDSM_X4T(bh[2*n2][0], bh[2*n2][1], bh[2*n2+1][0], bh[2*n2+1][1],
                     baddr + cur * BBUF + n2 * 32);
        #pragma unroll
        for (int mt = 0; mt < 4; ++mt)
            LDSM_X4(af[mt][0], af[mt][1], af[mt][2], af[mt][3],
                    aaddr + cur * ABUF + mt * 768);
        #pragma unroll
        for (int mt = 0; mt < 4; ++mt)
            #pragma unroll
            for (int nt = 0; nt < 4; ++nt)
                MMA16(acc[mt][nt], af[mt], bh[nt]);
        #pragma unroll
        for (int mt = 0; mt < 4; ++mt)
            LDSM_X4(af[mt][0], af[mt][1], af[mt][2], af[mt][3],
                    aaddr + cur * ABUF + mt * 768 + ALO);
        #pragma unroll
        for (int mt = 0; mt < 4; ++mt)
            #pragma unroll
            for (int nt = 0; nt < 4; ++nt)
                MMA16(acc[mt][nt], af[mt], bh[nt]);
    }

    const int g = lane >> 2, th = lane & 3;
    #pragma unroll
    for (int nt = 0; nt < 4; ++nt) {
        const int c = bx * 128 + wn + nt * 8 + 2 * th;
        const float b0v = bo[c], b1v = bo[c + 1];
        #pragma unroll
        for (int mt = 0; mt < 4; ++mt) {
            const int m = by * 128 + wm + mt * 16 + g;
            *(float2*)(out + (size_t)m * 768 + c) =
                make_float2(acc[mt][nt][0] + b0v, acc[mt][nt][1] + b1v);
            *(float2*)(out + (size_t)(m + 8) * 768 + c) =
                make_float2(acc[mt][nt][2] + b0v, acc[mt][nt][3] + b1v);
        }
    }
}

// ---------------------------------------------------------------------------
extern "C" void kernel_launch(void* const* d_in, const int* in_sizes, int n_in,
                              void* d_out, int out_size) {
    const float* x     = (const float*)d_in[0];
    const float* Wq    = (const float*)d_in[1];
    const float* Wkv   = (const float*)d_in[2];
    const float* mpre  = (const float*)d_in[3];
    const float* mpost = (const float*)d_in[4];
    const float* Wo    = (const float*)d_in[5];
    const float* bo    = (const float*)d_in[6];
    float* out = (float*)d_out;

    k_prep   <<<8448, 256>>>(x, Wq, Wkv, Wo);
    k_qkv    <<<dim3(18, 64),   256>>>();
    k_dots   <<<dim3(8, 8, 96), 256>>>();
    k_mixsoft<<<8192,           256>>>(mpre, mpost);
    k_av     <<<dim3(8, 96),    256>>>();
    k_out    <<<dim3(6, 64),    256>>>(bo, out);
}

// round 12
// speedup vs baseline: 1.3076x; 1.1030x over previous
#include <cuda_runtime.h>
#include <cuda_fp16.h>
#include <math.h>

#define Bb 8
#define Nn 1024
#define Hh 12

#define QKVSZ ((size_t)Bb*Hh*Nn*64)

// Scratch (static device globals)
__device__ __half g_xh[(size_t)8192*768], g_xl[(size_t)8192*768];
__device__ __half g_Wh[(size_t)768*2304];      // fp16 [Wq|Wkv], row-major [768][2304]
__device__ __half g_Woh[(size_t)768*768];      // fp16 Wo
__device__ __half g_Qh[QKVSZ], g_Ql[QKVSZ];
__device__ __half g_Kh[QKVSZ];
__device__ __half g_Vh[QKVSZ];
__device__ __half g_S[(size_t)Bb*Hh*Nn*Nn];    // fp16 raw logits
__device__ __half g_P[(size_t)Bb*Hh*Nn*Nn];    // fp16 post-mixed attn
__device__ __half g_Ch[(size_t)Bb*Nn*768], g_Cl[(size_t)Bb*Nn*768];

// ---------------------------------------------------------------------------
__device__ __forceinline__ void split2(float a, float b, unsigned &h, unsigned &l) {
    __half ha = __float2half_rn(a), hb = __float2half_rn(b);
    __half2 H = __halves2half2(ha, hb);
    __half2 L = __halves2half2(__float2half_rn(a - __half2float(ha)),
                               __float2half_rn(b - __half2float(hb)));
    h = *(unsigned*)&H; l = *(unsigned*)&L;
}
__device__ __forceinline__ void split4(float4 v, uint2 &h, uint2 &l) {
    split2(v.x, v.y, h.x, l.x); split2(v.z, v.w, h.y, l.y);
}
__device__ __forceinline__ uint2 pack4h(float4 v) {
    __half2 a = __floats2half2_rn(v.x, v.y);
    __half2 b = __floats2half2_rn(v.z, v.w);
    uint2 r; r.x = *(unsigned*)&a; r.y = *(unsigned*)&b; return r;
}
__device__ __forceinline__ unsigned h2bits(__half2 v) { return *(unsigned*)&v; }
__device__ __forceinline__ void store_hl(__half* Gh, __half* Gl, size_t idx,
                                         float v0, float v1) {
    __half h0 = __float2half_rn(v0), h1 = __float2half_rn(v1);
    __half l0 = __float2half_rn(v0 - __half2float(h0));
    __half l1 = __float2half_rn(v1 - __half2float(h1));
    *(__half2*)(Gh + idx) = __halves2half2(h0, h1);
    *(__half2*)(Gl + idx) = __halves2half2(l0, l1);
}

#define LDSM_X4(r0, r1, r2, r3, a) \
  asm volatile("ldmatrix.sync.aligned.m8n8.x4.shared.b16 {%0,%1,%2,%3},[%4];" \
               : "=r"(r0), "=r"(r1), "=r"(r2), "=r"(r3) : "r"(a))
#define LDSM_X4T(r0, r1, r2, r3, a) \
  asm volatile("ldmatrix.sync.aligned.m8n8.x4.trans.shared.b16 {%0,%1,%2,%3},[%4];" \
               : "=r"(r0), "=r"(r1), "=r"(r2), "=r"(r3) : "r"(a))
#define MMA16(c, a, b) \
  asm volatile("mma.sync.aligned.m16n8k16.row.col.f32.f16.f16.f32 " \
               "{%0,%1,%2,%3},{%4,%5,%6,%7},{%8,%9},{%0,%1,%2,%3};" \
               : "+f"(c[0]), "+f"(c[1]), "+f"(c[2]), "+f"(c[3]) \
               : "r"(a[0]), "r"(a[1]), "r"(a[2]), "r"(a[3]), "r"(b[0]), "r"(b[1]))
#define CP16(dst, src) \
  asm volatile("cp.async.ca.shared.global [%0], [%1], 16;" :: "r"(dst), "l"(src))
#define CPCOMMIT() asm volatile("cp.async.commit_group;")
#define CPWAIT0()  asm volatile("cp.async.wait_group 0;" ::: "memory")

// ---------------------------------------------------------------------------
// K0: prep — split x into fp16 hi/lo, quantize W's to fp16 (once).
// ---------------------------------------------------------------------------
__global__ __launch_bounds__(256) void k_prep(const float* __restrict__ x,
                                              const float* __restrict__ Wq,
                                              const float* __restrict__ Wkv,
                                              const float* __restrict__ Wo) {
    const size_t id = (size_t)blockIdx.x * 256 + threadIdx.x;
    if (id < 1572864) {                       // x: 8192*768/4
        float4 v = ((const float4*)x)[id];
        uint2 h, l; split4(v, h, l);
        *(uint2*)(g_xh + 4 * id) = h;
        *(uint2*)(g_xl + 4 * id) = l;
    } else if (id < 1720320) {                // Wq
        const size_t f = id - 1572864;
        float4 v = ((const float4*)Wq)[f];
        const size_t e = 4 * f;
        const size_t k = e / 768, c = e % 768;
        *(uint2*)(g_Wh + k * 2304 + c) = pack4h(v);
    } else if (id < 2015232) {                // Wkv
        const size_t f = id - 1720320;
        float4 v = ((const float4*)Wkv)[f];
        const size_t e = 4 * f;
        const size_t k = e / 1536, c = e % 1536;
        *(uint2*)(g_Wh + k * 2304 + 768 + c) = pack4h(v);
    } else if (id < 2162688) {                // Wo
        const size_t f = id - 2015232;
        float4 v = ((const float4*)Wo)[f];
        *(uint2*)(g_Woh + 4 * f) = pack4h(v);
    }
}

// ---------------------------------------------------------------------------
// K1: QKV projection. xh/xl @ g_Wh -> Q(hi/lo, scaled 1/8), K, V fp16.
// cp.async double-buffered. grid (18, 64). (round-10 proven)
// ---------------------------------------------------------------------------
__global__ __launch_bounds__(256, 2) void k_qkv() {
    __shared__ __align__(16) __half As[2][2 * 128 * 24];
    __shared__ __align__(16) __half Bs[2][16 * 136];
    const int tid = threadIdx.x, lane = tid & 31, w = tid >> 5;
    const int bx = blockIdx.x, by = blockIdx.y;
    const int nglob = bx * 128;
    const int wm = (w >> 2) * 64, wn = (w & 3) * 32;

    const int arow = tid >> 1, ac8 = (tid & 1) * 8;
    const int brow = tid >> 4, bc8 = (tid & 15) * 8;
    const __half* Ah = g_xh + ((size_t)by * 128 + arow) * 768 + ac8;
    const __half* Al = g_xl + ((size_t)by * 128 + arow) * 768 + ac8;
    const __half* Bp = g_Wh + (size_t)brow * 2304 + nglob + bc8;

    const int lr = lane & 7, hs = (lane >> 3) & 1, kc = lane >> 4;
    const unsigned sa = (unsigned)__cvta_generic_to_shared(&As[0][0]);
    const unsigned sb = (unsigned)__cvta_generic_to_shared(&Bs[0][0]);
    const unsigned aaddr = sa + ((wm + hs * 8 + lr) * 24 + kc * 8) * 2;
    const unsigned baddr = sb + ((hs * 8 + lr) * 136 + wn + kc * 8) * 2;
    const unsigned ALO = 128 * 24 * 2, ABUF = 2 * 128 * 24 * 2, BBUF = 16 * 136 * 2;
    const unsigned adst = sa + (arow * 24 + ac8) * 2;
    const unsigned bdst = sb + (brow * 136 + bc8) * 2;

    float acc[4][4][4] = {};

    CP16(adst, Ah);
    CP16(adst + ALO, Al);
    CP16(bdst, Bp);
    CPCOMMIT();

    for (int kt = 0; kt < 48; ++kt) {
        const int cur = kt & 1;
        CPWAIT0();
        __syncthreads();
        if (kt < 47) {
            const unsigned nb = (cur ^ 1);
            CP16(adst + nb * ABUF,       Ah + (kt + 1) * 16);
            CP16(adst + nb * ABUF + ALO, Al + (kt + 1) * 16);
            CP16(bdst + nb * BBUF,       Bp + (size_t)(kt + 1) * 16 * 2304);
            CPCOMMIT();
        }
        unsigned af[4][4], bh[4][2];
        #pragma unroll
        for (int n2 = 0; n2 < 2; ++n2)
            LDSM_X4T(bh[2*n2][0], bh[2*n2][1], bh[2*n2+1][0], bh[2*n2+1][1],
                     baddr + cur * BBUF + n2 * 32);
        #pragma unroll
        for (int mt = 0; mt < 4; ++mt)
            LDSM_X4(af[mt][0], af[mt][1], af[mt][2], af[mt][3],
                    aaddr + cur * ABUF + mt * 768);
        #pragma unroll
        for (int mt = 0; mt < 4; ++mt)
            #pragma unroll
            for (int nt = 0; nt < 4; ++nt)
                MMA16(acc[mt][nt], af[mt], bh[nt]);
        #pragma unroll
        for (int mt = 0; mt < 4; ++mt)
            LDSM_X4(af[mt][0], af[mt][1], af[mt][2], af[mt][3],
                    aaddr + cur * ABUF + mt * 768 + ALO);
        #pragma unroll
        for (int mt = 0; mt < 4; ++mt)
            #pragma unroll
            for (int nt = 0; nt < 4; ++nt)
                MMA16(acc[mt][nt], af[mt], bh[nt]);
    }

    const int g = lane >> 2, th = lane & 3;
    #pragma unroll
    for (int nt = 0; nt < 4; ++nt) {
        const int col = nglob + wn + nt * 8 + 2 * th;
        const int mat = col / 768;
        const int within = col - mat * 768;
        const int head = within >> 6, d = within & 63;
        #pragma unroll
        for (int mt = 0; mt < 4; ++mt) {
            const int m0 = by * 128 + wm + mt * 16 + g;
            const int b = m0 >> 10, nr = m0 & 1023;
            const size_t base = (((size_t)b * 12 + head) * 1024 + nr) * 64 + d;
            if (mat == 0) {
                store_hl(g_Qh, g_Ql, base,          acc[mt][nt][0] * 0.125f, acc[mt][nt][1] * 0.125f);
                store_hl(g_Qh, g_Ql, base + 8 * 64, acc[mt][nt][2] * 0.125f, acc[mt][nt][3] * 0.125f);
            } else {
                __half* G = (mat == 1) ? g_Kh : g_Vh;
                *(__half2*)(G + base)          = __floats2half2_rn(acc[mt][nt][0], acc[mt][nt][1]);
                *(__half2*)(G + base + 8 * 64) = __floats2half2_rn(acc[mt][nt][2], acc[mt][nt][3]);
            }
        }
    }
}

// ---------------------------------------------------------------------------
// K2: logits = (Q/8) @ K^T per (b,h). Single-stage cp.async. (round-10 proven)
// ---------------------------------------------------------------------------
__global__ __launch_bounds__(256, 2) void k_dots() {
    __shared__ __align__(16) __half Qs[2 * 128 * 72];
    __shared__ __align__(16) __half Ks[128 * 72];
    const int tid = threadIdx.x, lane = tid & 31, w = tid >> 5;
    const int jt = blockIdx.x, it = blockIdx.y, bh = blockIdx.z;
    const __half* Qhp = g_Qh + (size_t)bh * 65536 + (size_t)it * 128 * 64;
    const __half* Qlp = g_Ql + (size_t)bh * 65536 + (size_t)it * 128 * 64;
    const __half* Khp = g_Kh + (size_t)bh * 65536 + (size_t)jt * 128 * 64;
    __half* Sp = g_S + (size_t)bh * Nn * Nn;
    const int wm = (w >> 2) * 64, wn = (w & 3) * 32;

    const int lr = lane & 7, hs = (lane >> 3) & 1, kc = lane >> 4;
    const unsigned sq = (unsigned)__cvta_generic_to_shared(Qs);
    const unsigned sk = (unsigned)__cvta_generic_to_shared(Ks);
    const unsigned aaddr = sq + ((wm + hs * 8 + lr) * 72 + kc * 8) * 2;
    const unsigned kaddr = sk + ((wn + hs * 8 + lr) * 72 + kc * 8) * 2;
    const unsigned PLO = 128 * 72 * 2;

    #pragma unroll
    for (int j = 0; j < 4; ++j) {
        const int v = j * 256 + tid;
        const int row = v >> 3, c8 = (v & 7) * 8;
        const unsigned d = (row * 72 + c8) * 2;
        CP16(sq + d,       Qhp + row * 64 + c8);
        CP16(sq + d + PLO, Qlp + row * 64 + c8);
        CP16(sk + d,       Khp + row * 64 + c8);
    }
    CPCOMMIT();
    CPWAIT0();
    __syncthreads();

    float acc[4][4][4] = {};

    #pragma unroll
    for (int kk = 0; kk < 64; kk += 16) {
        unsigned bkh[4][2], af[4][4];
        #pragma unroll
        for (int n2 = 0; n2 < 2; ++n2)
            LDSM_X4(bkh[2*n2][0], bkh[2*n2+1][0], bkh[2*n2][1], bkh[2*n2+1][1],
                    kaddr + n2 * 2304 + kk * 2);
        #pragma unroll
        for (int mt = 0; mt < 4; ++mt)
            LDSM_X4(af[mt][0], af[mt][1], af[mt][2], af[mt][3],
                    aaddr + mt * 2304 + kk * 2);
        #pragma unroll
        for (int mt = 0; mt < 4; ++mt)
            #pragma unroll
            for (int nt = 0; nt < 4; ++nt)
                MMA16(acc[mt][nt], af[mt], bkh[nt]);
        #pragma unroll
        for (int mt = 0; mt < 4; ++mt)
            LDSM_X4(af[mt][0], af[mt][1], af[mt][2], af[mt][3],
                    aaddr + mt * 2304 + kk * 2 + PLO);
        #pragma unroll
        for (int mt = 0; mt < 4; ++mt)
            #pragma unroll
            for (int nt = 0; nt < 4; ++nt)
                MMA16(acc[mt][nt], af[mt], bkh[nt]);
    }

    const int g = lane >> 2, th = lane & 3;
    #pragma unroll
    for (int mt = 0; mt < 4; ++mt) {
        const int m = it * 128 + wm + mt * 16 + g;
        #pragma unroll
        for (int nt = 0; nt < 4; ++nt) {
            const int c = jt * 128 + wn + nt * 8 + 2 * th;
            *(__half2*)(Sp + (size_t)m * 1024 + c) =
                __floats2half2_rn(acc[mt][nt][0], acc[mt][nt][1]);
            *(__half2*)(Sp + (size_t)(m + 8) * 1024 + c) =
                __floats2half2_rn(acc[mt][nt][2], acc[mt][nt][3]);
        }
    }
}

// ---------------------------------------------------------------------------
// K3: talking-heads softmax on tensor cores (round-11 design, staging FIXED).
// ---------------------------------------------------------------------------
__global__ __launch_bounds__(256, 2) void k_mixsoft(const float* __restrict__ mix_pre,
                                                    const float* __restrict__ mix_post) {
    __shared__ __align__(16) __half big[1024 * 18];   // raw[16][1032] then attnS[1024][18]
    __shared__ __align__(16) __half preS[16 * 24], postS[16 * 24];
    __shared__ float wred[8 * 16];
    __shared__ float gmax[16], ginv[16];
    const int t = threadIdx.x, lane = t & 31, w = t >> 5;
    const int b = blockIdx.x >> 10, i = blockIdx.x & 1023;
    const size_t rowbase = (size_t)b * 12 * 1048576 + (size_t)i * 1024;

    // mix matrices -> fp16 smem, transposed, zero-padded. FIX: strided loop
    // (blockDim=256 < 384 entries; round-11 left rows >=10 uninitialized).
    for (int v = t; v < 384; v += 256) {
        const int row = v / 24, col = v % 24;
        const bool ok = (row < 12) && (col < 12);
        preS[v]  = ok ? __float2half_rn(mix_pre[col * 12 + row])  : __float2half_rn(0.f);
        postS[v] = ok ? __float2half_rn(mix_post[col * 12 + row]) : __float2half_rn(0.f);
    }
    // raw rows 0..11 (pitch 1032)
    #pragma unroll
    for (int u = 0; u < 6; ++u) {
        const int v = u * 256 + t;
        const int h = v >> 7, j8 = (v & 127) * 8;
        *(uint4*)&big[h * 1032 + j8] =
            *(const uint4*)(g_S + rowbase + (size_t)h * 1048576 + j8);
    }
    // zero pad rows 12..15 (516 uint4 from half-index 12384)
    #pragma unroll
    for (int u = 0; u < 3; ++u) {
        const int v = u * 256 + t;
        if (v < 516) *(uint4*)&big[12384 + v * 8] = make_uint4(0, 0, 0, 0);
    }
    __syncthreads();

    const int lr = lane & 7, hb = (lane >> 3) & 1, kc = lane >> 4;
    const int th = lane & 3, g8 = lane >> 2;
    unsigned preB[4], postB[4];
    LDSM_X4(preB[0], preB[1], preB[2], preB[3],
            (unsigned)__cvta_generic_to_shared(preS) + ((hb * 8 + lr) * 24 + kc * 8) * 2);
    LDSM_X4(postB[0], postB[1], postB[2], postB[3],
            (unsigned)__cvta_generic_to_shared(postS) + ((hb * 8 + lr) * 24 + kc * 8) * 2);

    const unsigned sbig = (unsigned)__cvta_generic_to_shared(big);
    const int hrow = ((lane >> 4) << 3) | (lane & 7);
    const int joff = ((lane >> 3) & 1) * 8;
    const int jbase = w * 128;

    // Pre-mix: 8 m-tiles x 2 n-tiles
    float acc[8][2][4];
    #pragma unroll
    for (int mt = 0; mt < 8; ++mt) {
        unsigned a[4];
        LDSM_X4T(a[0], a[1], a[2], a[3],
                 sbig + (hrow * 1032 + jbase + mt * 16 + joff) * 2);
        #pragma unroll
        for (int nt = 0; nt < 2; ++nt) {
            acc[mt][nt][0] = acc[mt][nt][1] = acc[mt][nt][2] = acc[mt][nt][3] = 0.f;
            unsigned bf[2] = {preB[nt], preB[nt + 2]};
            MMA16(acc[mt][nt], a, bf);
        }
    }

    // Row max per g-col
    float lm[4] = {-1e30f, -1e30f, -1e30f, -1e30f};
    #pragma unroll
    for (int mt = 0; mt < 8; ++mt)
        #pragma unroll
        for (int nt = 0; nt < 2; ++nt) {
            lm[nt * 2 + 0] = fmaxf(lm[nt * 2 + 0], fmaxf(acc[mt][nt][0], acc[mt][nt][2]));
            lm[nt * 2 + 1] = fmaxf(lm[nt * 2 + 1], fmaxf(acc[mt][nt][1], acc[mt][nt][3]));
        }
    #pragma unroll
    for (int o = 4; o < 32; o <<= 1)
        #pragma unroll
        for (int c = 0; c < 4; ++c)
            lm[c] = fmaxf(lm[c], __shfl_xor_sync(0xffffffffu, lm[c], o));
    if (lane < 4) {
        wred[w * 16 + 2 * th]         = lm[0];
        wred[w * 16 + 2 * th + 1]     = lm[1];
        wred[w * 16 + 8 + 2 * th]     = lm[2];
        wred[w * 16 + 8 + 2 * th + 1] = lm[3];
    }
    __syncthreads();
    if (t < 16) {
        float m = wred[t];
        #pragma unroll
        for (int ww = 1; ww < 8; ++ww) m = fmaxf(m, wred[ww * 16 + t]);
        gmax[t] = m;
    }
    __syncthreads();

    // exp + sum
    const float gm0 = gmax[2 * th], gm1 = gmax[2 * th + 1];
    const float gm2 = gmax[8 + 2 * th], gm3 = gmax[9 + 2 * th];
    float ls[4] = {0.f, 0.f, 0.f, 0.f};
    #pragma unroll
    for (int mt = 0; mt < 8; ++mt) {
        acc[mt][0][0] = __expf(acc[mt][0][0] - gm0);
        acc[mt][0][1] = __expf(acc[mt][0][1] - gm1);
        acc[mt][0][2] = __expf(acc[mt][0][2] - gm0);
        acc[mt][0][3] = __expf(acc[mt][0][3] - gm1);
        acc[mt][1][0] = __expf(acc[mt][1][0] - gm2);
        acc[mt][1][1] = __expf(acc[mt][1][1] - gm3);
        acc[mt][1][2] = __expf(acc[mt][1][2] - gm2);
        acc[mt][1][3] = __expf(acc[mt][1][3] - gm3);
        ls[0] += acc[mt][0][0] + acc[mt][0][2];
        ls[1] += acc[mt][0][1] + acc[mt][0][3];
        ls[2] += acc[mt][1][0] + acc[mt][1][2];
        ls[3] += acc[mt][1][1] + acc[mt][1][3];
    }
    #pragma unroll
    for (int o = 4; o < 32; o <<= 1)
        #pragma unroll
        for (int c = 0; c < 4; ++c)
            ls[c] += __shfl_xor_sync(0xffffffffu, ls[c], o);
    if (lane < 4) {
        wred[w * 16 + 2 * th]         = ls[0];
        wred[w * 16 + 2 * th + 1]     = ls[1];
        wred[w * 16 + 8 + 2 * th]     = ls[2];
        wred[w * 16 + 8 + 2 * th + 1] = ls[3];
    }
    __syncthreads();
    if (t < 16) {
        float s = 0.f;
        #pragma unroll
        for (int ww = 0; ww < 8; ++ww) s += wred[ww * 16 + t];
        ginv[t] = 1.0f / s;
    }
    __syncthreads();
    const float gi0 = ginv[2 * th], gi1 = ginv[2 * th + 1];
    const float gi2 = ginv[8 + 2 * th], gi3 = ginv[9 + 2 * th];

    // Post-mix per m-tile; store to attnS[j][18] (reuses big; raw is dead)
    #pragma unroll
    for (int mt = 0; mt < 8; ++mt) {
        unsigned aP[4];
        aP[0] = h2bits(__floats2half2_rn(acc[mt][0][0] * gi0, acc[mt][0][1] * gi1));
        aP[1] = h2bits(__floats2half2_rn(acc[mt][0][2] * gi0, acc[mt][0][3] * gi1));
        aP[2] = h2bits(__floats2half2_rn(acc[mt][1][0] * gi2, acc[mt][1][1] * gi3));
        aP[3] = h2bits(__floats2half2_rn(acc[mt][1][2] * gi2, acc[mt][1][3] * gi3));
        float o0[4] = {0.f, 0.f, 0.f, 0.f}, o1[4] = {0.f, 0.f, 0.f, 0.f};
        unsigned bf0[2] = {postB[0], postB[2]};
        unsigned bf1[2] = {postB[1], postB[3]};
        MMA16(o0, aP, bf0);
        MMA16(o1, aP, bf1);
        const int r = jbase + mt * 16 + g8;
        *(__half2*)&big[r * 18 + 2 * th]           = __floats2half2_rn(o0[0], o0[1]);
        *(__half2*)&big[(r + 8) * 18 + 2 * th]     = __floats2half2_rn(o0[2], o0[3]);
        *(__half2*)&big[r * 18 + 8 + 2 * th]       = __floats2half2_rn(o1[0], o1[1]);
        *(__half2*)&big[(r + 8) * 18 + 8 + 2 * th] = __floats2half2_rn(o1[2], o1[3]);
    }
    __syncthreads();

    // Coalesced write to g_P[h][j]
    #pragma unroll
    for (int h = 0; h < 12; ++h) {
        __half* dst = g_P + rowbase + (size_t)h * 1048576;
        #pragma unroll
        for (int rep = 0; rep < 2; ++rep) {
            const int p = rep * 256 + t;
            const __half lo = big[(2 * p) * 18 + h];
            const __half hi = big[(2 * p + 1) * 18 + h];
            *(__half2*)(dst + 2 * p) = __halves2half2(lo, hi);
        }
    }
}

// ---------------------------------------------------------------------------
// K4: O = attn(fp16) @ Vh(fp16) per (b,h) -> g_Ch/g_Cl. (round-10 proven)
// ---------------------------------------------------------------------------
__global__ __launch_bounds__(256, 2) void k_av() {
    __shared__ __align__(16) __half As[2][128 * 40];
    __shared__ __align__(16) __half Vs[2][32 * 72];
    const int tid = threadIdx.x, lane = tid & 31, w = tid >> 5;
    const int it = blockIdx.x, bh = blockIdx.y;
    const int b = bh / 12, h = bh % 12;
    const __half* Pp  = g_P  + (size_t)bh * 1048576 + (size_t)it * 131072;
    const __half* Vhp = g_Vh + (size_t)bh * 65536;
    const int wm = (w >> 1) * 32, wn = (w & 1) * 32;

    const int arow = tid >> 2, ac8 = (tid & 3) * 8;
    const int vrow = tid >> 3, vc8 = (tid & 7) * 8;

    const int lr = lane & 7, hs = (lane >> 3) & 1, kc = lane >> 4;
    const unsigned sa = (unsigned)__cvta_generic_to_shared(&As[0][0]);
    const unsigned sb = (unsigned)__cvta_generic_to_shared(&Vs[0][0]);
    const unsigned aaddr = sa + ((wm + hs * 8 + lr) * 40 + kc * 8) * 2;
    const unsigned baddr = sb + ((hs * 8 + lr) * 72 + wn + kc * 8) * 2;
    const unsigned ABUF = 128 * 40 * 2;
    const unsigned VBUF = 32 * 72 * 2;
    const unsigned adst0 = sa + (arow * 40 + ac8) * 2;
    const unsigned adst1 = sa + ((arow + 64) * 40 + ac8) * 2;
    const unsigned vdst  = sb + (vrow * 72 + vc8) * 2;

    float acc[2][4][4] = {};

    CP16(adst0, Pp + (size_t)arow * 1024 + ac8);
    CP16(adst1, Pp + (size_t)(arow + 64) * 1024 + ac8);
    CP16(vdst,  Vhp + vrow * 64 + vc8);
    CPCOMMIT();

    for (int kt = 0; kt < 32; ++kt) {
        const int cur = kt & 1;
        CPWAIT0();
        __syncthreads();
        if (kt < 31) {
            const unsigned nb = cur ^ 1;
            CP16(adst0 + nb * ABUF, Pp + (size_t)arow * 1024 + (kt + 1) * 32 + ac8);
            CP16(adst1 + nb * ABUF, Pp + (size_t)(arow + 64) * 1024 + (kt + 1) * 32 + ac8);
            CP16(vdst + nb * VBUF,  Vhp + (size_t)((kt + 1) * 32 + vrow) * 64 + vc8);
            CPCOMMIT();
        }
        #pragma unroll
        for (int kk = 0; kk < 32; kk += 16) {
            unsigned af[2][4], bvh[4][2];
            #pragma unroll
            for (int n2 = 0; n2 < 2; ++n2)
                LDSM_X4T(bvh[2*n2][0], bvh[2*n2][1], bvh[2*n2+1][0], bvh[2*n2+1][1],
                         baddr + cur * VBUF + kk * 144 + n2 * 32);
            #pragma unroll
            for (int mt = 0; mt < 2; ++mt)
                LDSM_X4(af[mt][0], af[mt][1], af[mt][2], af[mt][3],
                        aaddr + cur * ABUF + mt * 1280 + kk * 2);
            #pragma unroll
            for (int mt = 0; mt < 2; ++mt)
                #pragma unroll
                for (int nt = 0; nt < 4; ++nt)
                    MMA16(acc[mt][nt], af[mt], bvh[nt]);
        }
    }

    const int g = lane >> 2, th = lane & 3;
    #pragma unroll
    for (int mt = 0; mt < 2; ++mt) {
        const int m = it * 128 + wm + mt * 16 + g;
        #pragma unroll
        for (int nt = 0; nt < 4; ++nt) {
            const int c = wn + nt * 8 + 2 * th;
            const size_t base = ((size_t)b * 1024 + m) * 768 + h * 64 + c;
            store_hl(g_Ch, g_Cl, base,             acc[mt][nt][0], acc[mt][nt][1]);
            store_hl(g_Ch, g_Cl, base + 8 * 768,   acc[mt][nt][2], acc[mt][nt][3]);
        }
    }
}

// ---------------------------------------------------------------------------
// K5: out = Ctx(hi/lo) @ g_Woh + bo. (round-10 proven)
// ---------------------------------------------------------------------------
__global__ __launch_bounds__(256, 2) void k_out(const float* __restrict__ bo,
                                                float* __restrict__ out) {
    __shared__ __align__(16) __half As[2][2 * 128 * 24];
    __shared__ __align__(16) __half Bs[2][16 * 136];
    const int tid = threadIdx.x, lane = tid & 31, w = tid >> 5;
    const int bx = blockIdx.x, by = blockIdx.y;
    const int wm = (w >> 2) * 64, wn = (w & 3) * 32;

    const int arow = tid >> 1, ac8 = (tid & 1) * 8;
    const int brow = tid >> 4, bc8 = (tid & 15) * 8;
    const __half* Chp = g_Ch + ((size_t)by * 128 + arow) * 768 + ac8;
    const __half* Clp = g_Cl + ((size_t)by * 128 + arow) * 768 + ac8;
    const __half* Bp  = g_Woh + (size_t)brow * 768 + bx * 128 + bc8;

    const int lr = lane & 7, hs = (lane >> 3) & 1, kc = lane >> 4;
    const unsigned sa = (unsigned)__cvta_generic_to_shared(&As[0][0]);
    const unsigned sb = (unsigned)__cvta_generic_to_shared(&Bs[0][0]);
    const unsigned aaddr = sa + ((wm + hs * 8 + lr) * 24 + kc * 8) * 2;
    const unsigned baddr = sb + ((hs * 8 + lr) * 136 + wn + kc * 8) * 2;
    const unsigned ALO = 128 * 24 * 2, ABUF = 2 * 128 * 24 * 2, BBUF = 16 * 136 * 2;
    const unsigned adst = sa + (arow * 24 + ac8) * 2;
    const unsigned bdst = sb + (brow * 136 + bc8) * 2;

    float acc[4][4][4] = {};

    CP16(adst,       Chp);
    CP16(adst + ALO, Clp);
    CP16(bdst,       Bp);
    CPCOMMIT();

    for (int kt = 0; kt < 48; ++kt) {
        const int cur = kt & 1;
        CPWAIT0();
        __syncthreads();
        if (kt < 47) {
            const unsigned nb = cur ^ 1;
            CP16(adst + nb * ABUF,       Chp + (kt + 1) * 16);
            CP16(adst + nb * ABUF + ALO, Clp + (kt + 1) * 16);
            CP16(bdst + nb * BBUF,       Bp + (size_t)(kt + 1) * 16 * 768);
            CPCOMMIT();
        }
        unsigned af[4][4], bh[4][2];
        #pragma unroll
        for (int n2 = 0; n2 < 2; ++n2)
            LDSM_X4T(bh[2*n2][0], bh[2*n2][1], bh[2*n2+1][0], bh[2*n2+1][1],
                     baddr + cur * BBUF + n2 * 32);
        #pragma unroll
        for (int mt = 0; mt < 4; ++mt)
            LDSM_X4(af[mt][0], af[mt][1], af[mt][2], af[mt][3],
                    aaddr + cur * ABUF + mt * 768);
        #pragma unroll
        for (int mt = 0; mt < 4; ++mt)
            #pragma unroll
            for (int nt = 0; nt < 4; ++nt)
                MMA16(acc[mt][nt], af[mt], bh[nt]);
        #pragma unroll
        for (int mt = 0; mt < 4; ++mt)
            LDSM_X4(af[mt][0], af[mt][1], af[mt][2], af[mt][3],
                    aaddr + cur * ABUF + mt * 768 + ALO);
        #pragma unroll
        for (int mt = 0; mt < 4; ++mt)
            #pragma unroll
            for (int nt = 0; nt < 4; ++nt)
                MMA16(acc[mt][nt], af[mt], bh[nt]);
    }

    const int g = lane >> 2, th = lane & 3;
    #pragma unroll
    for (int nt = 0; nt < 4; ++nt) {
        const int c = bx * 128 + wn + nt * 8 + 2 * th;
        const float b0v = bo[c], b1v = bo[c + 1];
        #pragma unroll
        for (int mt = 0; mt < 4; ++mt) {
            const int m = by * 128 + wm + mt * 16 + g;
            *(float2*)(out + (size_t)m * 768 + c) =
                make_float2(acc[mt][nt][0] + b0v, acc[mt][nt][1] + b1v);
            *(float2*)(out + (size_t)(m + 8) * 768 + c) =
                make_float2(acc[mt][nt][2] + b0v, acc[mt][nt][3] + b1v);
        }
    }
}

// ---------------------------------------------------------------------------
extern "C" void kernel_launch(void* const* d_in, const int* in_sizes, int n_in,
                              void* d_out, int out_size) {
    const float* x     = (const float*)d_in[0];
    const float* Wq    = (const float*)d_in[1];
    const float* Wkv   = (const float*)d_in[2];
    const float* mpre  = (const float*)d_in[3];
    const float* mpost = (const float*)d_in[4];
    const float* Wo    = (const float*)d_in[5];
    const float* bo    = (const float*)d_in[6];
    float* out = (float*)d_out;

    k_prep   <<<8448, 256>>>(x, Wq, Wkv, Wo);
    k_qkv    <<<dim3(18, 64),   256>>>();
    k_dots   <<<dim3(8, 8, 96), 256>>>();
    k_mixsoft<<<8192,           256>>>(mpre, mpost);
    k_av     <<<dim3(8, 96),    256>>>();
    k_out    <<<dim3(6, 64),    256>>>(bo, out);
}

// round 14
// speedup vs baseline: 1.3577x; 1.0383x over previous
#include <cuda_runtime.h>
#include <cuda_fp16.h>
#include <math.h>

#define Bb 8
#define Nn 1024
#define Hh 12

#define QKVSZ ((size_t)Bb*Hh*Nn*64)

// Scratch (static device globals)
__device__ __half g_xh[(size_t)8192*768], g_xl[(size_t)8192*768];
__device__ __half g_Wh[(size_t)768*2304];      // fp16 [Wq|Wkv], row-major [768][2304]
__device__ __half g_Woh[(size_t)768*768];      // fp16 Wo
__device__ __half g_Qh[QKVSZ], g_Ql[QKVSZ];
__device__ __half g_Kh[QKVSZ];
__device__ __half g_Vh[QKVSZ];
__device__ __half g_S[(size_t)Bb*Hh*Nn*Nn];    // fp16 raw logits
__device__ __half g_P[(size_t)Bb*Hh*Nn*Nn];    // fp16 post-mixed attn
__device__ __half g_Ch[(size_t)Bb*Nn*768];     // fp16 context (single plane)

// ---------------------------------------------------------------------------
__device__ __forceinline__ void split2(float a, float b, unsigned &h, unsigned &l) {
    __half ha = __float2half_rn(a), hb = __float2half_rn(b);
    __half2 H = __halves2half2(ha, hb);
    __half2 L = __halves2half2(__float2half_rn(a - __half2float(ha)),
                               __float2half_rn(b - __half2float(hb)));
    h = *(unsigned*)&H; l = *(unsigned*)&L;
}
__device__ __forceinline__ void split4(float4 v, uint2 &h, uint2 &l) {
    split2(v.x, v.y, h.x, l.x); split2(v.z, v.w, h.y, l.y);
}
__device__ __forceinline__ uint2 pack4h(float4 v) {
    __half2 a = __floats2half2_rn(v.x, v.y);
    __half2 b = __floats2half2_rn(v.z, v.w);
    uint2 r; r.x = *(unsigned*)&a; r.y = *(unsigned*)&b; return r;
}
__device__ __forceinline__ unsigned h2bits(__half2 v) { return *(unsigned*)&v; }
__device__ __forceinline__ void store_hl(__half* Gh, __half* Gl, size_t idx,
                                         float v0, float v1) {
    __half h0 = __float2half_rn(v0), h1 = __float2half_rn(v1);
    __half l0 = __float2half_rn(v0 - __half2float(h0));
    __half l1 = __float2half_rn(v1 - __half2float(h1));
    *(__half2*)(Gh + idx) = __halves2half2(h0, h1);
    *(__half2*)(Gl + idx) = __halves2half2(l0, l1);
}

#define LDSM_X4(r0, r1, r2, r3, a) \
  asm volatile("ldmatrix.sync.aligned.m8n8.x4.shared.b16 {%0,%1,%2,%3},[%4];" \
               : "=r"(r0), "=r"(r1), "=r"(r2), "=r"(r3) : "r"(a))
#define LDSM_X4T(r0, r1, r2, r3, a) \
  asm volatile("ldmatrix.sync.aligned.m8n8.x4.trans.shared.b16 {%0,%1,%2,%3},[%4];" \
               : "=r"(r0), "=r"(r1), "=r"(r2), "=r"(r3) : "r"(a))
#define MMA16(c, a, b) \
  asm volatile("mma.sync.aligned.m16n8k16.row.col.f32.f16.f16.f32 " \
               "{%0,%1,%2,%3},{%4,%5,%6,%7},{%8,%9},{%0,%1,%2,%3};" \
               : "+f"(c[0]), "+f"(c[1]), "+f"(c[2]), "+f"(c[3]) \
               : "r"(a[0]), "r"(a[1]), "r"(a[2]), "r"(a[3]), "r"(b[0]), "r"(b[1]))
#define CP16(dst, src) \
  asm volatile("cp.async.ca.shared.global [%0], [%1], 16;" :: "r"(dst), "l"(src))
#define CPCOMMIT() asm volatile("cp.async.commit_group;")
#define CPWAIT0()  asm volatile("cp.async.wait_group 0;" ::: "memory")

// ---------------------------------------------------------------------------
// K0: prep — split x into fp16 hi/lo, quantize W's to fp16 (once).
// ---------------------------------------------------------------------------
__global__ __launch_bounds__(256) void k_prep(const float* __restrict__ x,
                                              const float* __restrict__ Wq,
                                              const float* __restrict__ Wkv,
                                              const float* __restrict__ Wo) {
    const size_t id = (size_t)blockIdx.x * 256 + threadIdx.x;
    if (id < 1572864) {                       // x: 8192*768/4
        float4 v = ((const float4*)x)[id];
        uint2 h, l; split4(v, h, l);
        *(uint2*)(g_xh + 4 * id) = h;
        *(uint2*)(g_xl + 4 * id) = l;
    } else if (id < 1720320) {                // Wq
        const size_t f = id - 1572864;
        float4 v = ((const float4*)Wq)[f];
        const size_t e = 4 * f;
        const size_t k = e / 768, c = e % 768;
        *(uint2*)(g_Wh + k * 2304 + c) = pack4h(v);
    } else if (id < 2015232) {                // Wkv
        const size_t f = id - 1720320;
        float4 v = ((const float4*)Wkv)[f];
        const size_t e = 4 * f;
        const size_t k = e / 1536, c = e % 1536;
        *(uint2*)(g_Wh + k * 2304 + 768 + c) = pack4h(v);
    } else if (id < 2162688) {                // Wo
        const size_t f = id - 2015232;
        float4 v = ((const float4*)Wo)[f];
        *(uint2*)(g_Woh + 4 * f) = pack4h(v);
    }
}

// ---------------------------------------------------------------------------
// K1: QKV projection. xh/xl @ g_Wh -> Q(hi/lo, scaled 1/8), K, V fp16.
// cp.async double-buffered. grid (18, 64). (round-12 proven)
// ---------------------------------------------------------------------------
__global__ __launch_bounds__(256, 2) void k_qkv() {
    __shared__ __align__(16) __half As[2][2 * 128 * 24];
    __shared__ __align__(16) __half Bs[2][16 * 136];
    const int tid = threadIdx.x, lane = tid & 31, w = tid >> 5;
    const int bx = blockIdx.x, by = blockIdx.y;
    const int nglob = bx * 128;
    const int wm = (w >> 2) * 64, wn = (w & 3) * 32;

    const int arow = tid >> 1, ac8 = (tid & 1) * 8;
    const int brow = tid >> 4, bc8 = (tid & 15) * 8;
    const __half* Ah = g_xh + ((size_t)by * 128 + arow) * 768 + ac8;
    const __half* Al = g_xl + ((size_t)by * 128 + arow) * 768 + ac8;
    const __half* Bp = g_Wh + (size_t)brow * 2304 + nglob + bc8;

    const int lr = lane & 7, hs = (lane >> 3) & 1, kc = lane >> 4;
    const unsigned sa = (unsigned)__cvta_generic_to_shared(&As[0][0]);
    const unsigned sb = (unsigned)__cvta_generic_to_shared(&Bs[0][0]);
    const unsigned aaddr = sa + ((wm + hs * 8 + lr) * 24 + kc * 8) * 2;
    const unsigned baddr = sb + ((hs * 8 + lr) * 136 + wn + kc * 8) * 2;
    const unsigned ALO = 128 * 24 * 2, ABUF = 2 * 128 * 24 * 2, BBUF = 16 * 136 * 2;
    const unsigned adst = sa + (arow * 24 + ac8) * 2;
    const unsigned bdst = sb + (brow * 136 + bc8) * 2;

    float acc[4][4][4] = {};

    CP16(adst, Ah);
    CP16(adst + ALO, Al);
    CP16(bdst, Bp);
    CPCOMMIT();

    for (int kt = 0; kt < 48; ++kt) {
        const int cur = kt & 1;
        CPWAIT0();
        __syncthreads();
        if (kt < 47) {
            const unsigned nb = (cur ^ 1);
            CP16(adst + nb * ABUF,       Ah + (kt + 1) * 16);
            CP16(adst + nb * ABUF + ALO, Al + (kt + 1) * 16);
            CP16(bdst + nb * BBUF,       Bp + (size_t)(kt + 1) * 16 * 2304);
            CPCOMMIT();
        }
        unsigned af[4][4], bh[4][2];
        #pragma unroll
        for (int n2 = 0; n2 < 2; ++n2)
            LDSM_X4T(bh[2*n2][0], bh[2*n2][1], bh[2*n2+1][0], bh[2*n2+1][1],
                     baddr + cur * BBUF + n2 * 32);
        #pragma unroll
        for (int mt = 0; mt < 4; ++mt)
            LDSM_X4(af[mt][0], af[mt][1], af[mt][2], af[mt][3],
                    aaddr + cur * ABUF + mt * 768);
        #pragma unroll
        for (int mt = 0; mt < 4; ++mt)
            #pragma unroll
            for (int nt = 0; nt < 4; ++nt)
                MMA16(acc[mt][nt], af[mt], bh[nt]);
        #pragma unroll
        for (int mt = 0; mt < 4; ++mt)
            LDSM_X4(af[mt][0], af[mt][1], af[mt][2], af[mt][3],
                    aaddr + cur * ABUF + mt * 768 + ALO);
        #pragma unroll
        for (int mt = 0; mt < 4; ++mt)
            #pragma unroll
            for (int nt = 0; nt < 4; ++nt)
                MMA16(acc[mt][nt], af[mt], bh[nt]);
    }

    const int g = lane >> 2, th = lane & 3;
    #pragma unroll
    for (int nt = 0; nt < 4; ++nt) {
        const int col = nglob + wn + nt * 8 + 2 * th;
        const int mat = col / 768;
        const int within = col - mat * 768;
        const int head = within >> 6, d = within & 63;
        #pragma unroll
        for (int mt = 0; mt < 4; ++mt) {
            const int m0 = by * 128 + wm + mt * 16 + g;
            const int b = m0 >> 10, nr = m0 & 1023;
            const size_t base = (((size_t)b * 12 + head) * 1024 + nr) * 64 + d;
            if (mat == 0) {
                store_hl(g_Qh, g_Ql, base,          acc[mt][nt][0] * 0.125f, acc[mt][nt][1] * 0.125f);
                store_hl(g_Qh, g_Ql, base + 8 * 64, acc[mt][nt][2] * 0.125f, acc[mt][nt][3] * 0.125f);
            } else {
                __half* G = (mat == 1) ? g_Kh : g_Vh;
                *(__half2*)(G + base)          = __floats2half2_rn(acc[mt][nt][0], acc[mt][nt][1]);
                *(__half2*)(G + base + 8 * 64) = __floats2half2_rn(acc[mt][nt][2], acc[mt][nt][3]);
            }
        }
    }
}

// ---------------------------------------------------------------------------
// K2: logits = (Q/8) @ K^T per (b,h). Single-stage cp.async. (round-12 proven)
// ---------------------------------------------------------------------------
__global__ __launch_bounds__(256, 2) void k_dots() {
    __shared__ __align__(16) __half Qs[2 * 128 * 72];
    __shared__ __align__(16) __half Ks[128 * 72];
    const int tid = threadIdx.x, lane = tid & 31, w = tid >> 5;
    const int jt = blockIdx.x, it = blockIdx.y, bh = blockIdx.z;
    const __half* Qhp = g_Qh + (size_t)bh * 65536 + (size_t)it * 128 * 64;
    const __half* Qlp = g_Ql + (size_t)bh * 65536 + (size_t)it * 128 * 64;
    const __half* Khp = g_Kh + (size_t)bh * 65536 + (size_t)jt * 128 * 64;
    __half* Sp = g_S + (size_t)bh * Nn * Nn;
    const int wm = (w >> 2) * 64, wn = (w & 3) * 32;

    const int lr = lane & 7, hs = (lane >> 3) & 1, kc = lane >> 4;
    const unsigned sq = (unsigned)__cvta_generic_to_shared(Qs);
    const unsigned sk = (unsigned)__cvta_generic_to_shared(Ks);
    const unsigned aaddr = sq + ((wm + hs * 8 + lr) * 72 + kc * 8) * 2;
    const unsigned kaddr = sk + ((wn + hs * 8 + lr) * 72 + kc * 8) * 2;
    const unsigned PLO = 128 * 72 * 2;

    #pragma unroll
    for (int j = 0; j < 4; ++j) {
        const int v = j * 256 + tid;
        const int row = v >> 3, c8 = (v & 7) * 8;
        const unsigned d = (row * 72 + c8) * 2;
        CP16(sq + d,       Qhp + row * 64 + c8);
        CP16(sq + d + PLO, Qlp + row * 64 + c8);
        CP16(sk + d,       Khp + row * 64 + c8);
    }
    CPCOMMIT();
    CPWAIT0();
    __syncthreads();

    float acc[4][4][4] = {};

    #pragma unroll
    for (int kk = 0; kk < 64; kk += 16) {
        unsigned bkh[4][2], af[4][4];
        #pragma unroll
        for (int n2 = 0; n2 < 2; ++n2)
            LDSM_X4(bkh[2*n2][0], bkh[2*n2+1][0], bkh[2*n2][1], bkh[2*n2+1][1],
                    kaddr + n2 * 2304 + kk * 2);
        #pragma unroll
        for (int mt = 0; mt < 4; ++mt)
            LDSM_X4(af[mt][0], af[mt][1], af[mt][2], af[mt][3],
                    aaddr + mt * 2304 + kk * 2);
        #pragma unroll
        for (int mt = 0; mt < 4; ++mt)
            #pragma unroll
            for (int nt = 0; nt < 4; ++nt)
                MMA16(acc[mt][nt], af[mt], bkh[nt]);
        #pragma unroll
        for (int mt = 0; mt < 4; ++mt)
            LDSM_X4(af[mt][0], af[mt][1], af[mt][2], af[mt][3],
                    aaddr + mt * 2304 + kk * 2 + PLO);
        #pragma unroll
        for (int mt = 0; mt < 4; ++mt)
            #pragma unroll
            for (int nt = 0; nt < 4; ++nt)
                MMA16(acc[mt][nt], af[mt], bkh[nt]);
    }

    const int g = lane >> 2, th = lane & 3;
    #pragma unroll
    for (int mt = 0; mt < 4; ++mt) {
        const int m = it * 128 + wm + mt * 16 + g;
        #pragma unroll
        for (int nt = 0; nt < 4; ++nt) {
            const int c = jt * 128 + wn + nt * 8 + 2 * th;
            *(__half2*)(Sp + (size_t)m * 1024 + c) =
                __floats2half2_rn(acc[mt][nt][0], acc[mt][nt][1]);
            *(__half2*)(Sp + (size_t)(m + 8) * 1024 + c) =
                __floats2half2_rn(acc[mt][nt][2], acc[mt][nt][3]);
        }
    }
}

// ---------------------------------------------------------------------------
// K3: talking-heads softmax on tensor cores. (round-12 proven)
// ---------------------------------------------------------------------------
__global__ __launch_bounds__(256, 2) void k_mixsoft(const float* __restrict__ mix_pre,
                                                    const float* __restrict__ mix_post) {
    __shared__ __align__(16) __half big[1024 * 18];
    __shared__ __align__(16) __half preS[16 * 24], postS[16 * 24];
    __shared__ float wred[8 * 16];
    __shared__ float gmax[16], ginv[16];
    const int t = threadIdx.x, lane = t & 31, w = t >> 5;
    const int b = blockIdx.x >> 10, i = blockIdx.x & 1023;
    const size_t rowbase = (size_t)b * 12 * 1048576 + (size_t)i * 1024;

    for (int v = t; v < 384; v += 256) {
        const int row = v / 24, col = v % 24;
        const bool ok = (row < 12) && (col < 12);
        preS[v]  = ok ? __float2half_rn(mix_pre[col * 12 + row])  : __float2half_rn(0.f);
        postS[v] = ok ? __float2half_rn(mix_post[col * 12 + row]) : __float2half_rn(0.f);
    }
    #pragma unroll
    for (int u = 0; u < 6; ++u) {
        const int v = u * 256 + t;
        const int h = v >> 7, j8 = (v & 127) * 8;
        *(uint4*)&big[h * 1032 + j8] =
            *(const uint4*)(g_S + rowbase + (size_t)h * 1048576 + j8);
    }
    #pragma unroll
    for (int u = 0; u < 3; ++u) {
        const int v = u * 256 + t;
        if (v < 516) *(uint4*)&big[12384 + v * 8] = make_uint4(0, 0, 0, 0);
    }
    __syncthreads();

    const int lr = lane & 7, hb = (lane >> 3) & 1, kc = lane >> 4;
    const int th = lane & 3, g8 = lane >> 2;
    unsigned preB[4], postB[4];
    LDSM_X4(preB[0], preB[1], preB[2], preB[3],
            (unsigned)__cvta_generic_to_shared(preS) + ((hb * 8 + lr) * 24 + kc * 8) * 2);
    LDSM_X4(postB[0], postB[1], postB[2], postB[3],
            (unsigned)__cvta_generic_to_shared(postS) + ((hb * 8 + lr) * 24 + kc * 8) * 2);

    const unsigned sbig = (unsigned)__cvta_generic_to_shared(big);
    const int hrow = ((lane >> 4) << 3) | (lane & 7);
    const int joff = ((lane >> 3) & 1) * 8;
    const int jbase = w * 128;

    float acc[8][2][4];
    #pragma unroll
    for (int mt = 0; mt < 8; ++mt) {
        unsigned a[4];
        LDSM_X4T(a[0], a[1], a[2], a[3],
                 sbig + (hrow * 1032 + jbase + mt * 16 + joff) * 2);
        #pragma unroll
        for (int nt = 0; nt < 2; ++nt) {
            acc[mt][nt][0] = acc[mt][nt][1] = acc[mt][nt][2] = acc[mt][nt][3] = 0.f;
            unsigned bf[2] = {preB[nt], preB[nt + 2]};
            MMA16(acc[mt][nt], a, bf);
        }
    }

    float lm[4] = {-1e30f, -1e30f, -1e30f, -1e30f};
    #pragma unroll
    for (int mt = 0; mt < 8; ++mt)
        #pragma unroll
        for (int nt = 0; nt < 2; ++nt) {
            lm[nt * 2 + 0] = fmaxf(lm[nt * 2 + 0], fmaxf(acc[mt][nt][0], acc[mt][nt][2]));
            lm[nt * 2 + 1] = fmaxf(lm[nt * 2 + 1], fmaxf(acc[mt][nt][1], acc[mt][nt][3]));
        }
    #pragma unroll
    for (int o = 4; o < 32; o <<= 1)
        #pragma unroll
        for (int c = 0; c < 4; ++c)
            lm[c] = fmaxf(lm[c], __shfl_xor_sync(0xffffffffu, lm[c], o));
    if (lane < 4) {
        wred[w * 16 + 2 * th]         = lm[0];
        wred[w * 16 + 2 * th + 1]     = lm[1];
        wred[w * 16 + 8 + 2 * th]     = lm[2];
        wred[w * 16 + 8 + 2 * th + 1] = lm[3];
    }
    __syncthreads();
    if (t < 16) {
        float m = wred[t];
        #pragma unroll
        for (int ww = 1; ww < 8; ++ww) m = fmaxf(m, wred[ww * 16 + t]);
        gmax[t] = m;
    }
    __syncthreads();

    const float gm0 = gmax[2 * th], gm1 = gmax[2 * th + 1];
    const float gm2 = gmax[8 + 2 * th], gm3 = gmax[9 + 2 * th];
    float ls[4] = {0.f, 0.f, 0.f, 0.f};
    #pragma unroll
    for (int mt = 0; mt < 8; ++mt) {
        acc[mt][0][0] = __expf(acc[mt][0][0] - gm0);
        acc[mt][0][1] = __expf(acc[mt][0][1] - gm1);
        acc[mt][0][2] = __expf(acc[mt][0][2] - gm0);
        acc[mt][0][3] = __expf(acc[mt][0][3] - gm1);
        acc[mt][1][0] = __expf(acc[mt][1][0] - gm2);
        acc[mt][1][1] = __expf(acc[mt][1][1] - gm3);
        acc[mt][1][2] = __expf(acc[mt][1][2] - gm2);
        acc[mt][1][3] = __expf(acc[mt][1][3] - gm3);
        ls[0] += acc[mt][0][0] + acc[mt][0][2];
        ls[1] += acc[mt][0][1] + acc[mt][0][3];
        ls[2] += acc[mt][1][0] + acc[mt][1][2];
        ls[3] += acc[mt][1][1] + acc[mt][1][3];
    }
    #pragma unroll
    for (int o = 4; o < 32; o <<= 1)
        #pragma unroll
        for (int c = 0; c < 4; ++c)
            ls[c] += __shfl_xor_sync(0xffffffffu, ls[c], o);
    if (lane < 4) {
        wred[w * 16 + 2 * th]         = ls[0];
        wred[w * 16 + 2 * th + 1]     = ls[1];
        wred[w * 16 + 8 + 2 * th]     = ls[2];
        wred[w * 16 + 8 + 2 * th + 1] = ls[3];
    }
    __syncthreads();
    if (t < 16) {
        float s = 0.f;
        #pragma unroll
        for (int ww = 0; ww < 8; ++ww) s += wred[ww * 16 + t];
        ginv[t] = 1.0f / s;
    }
    __syncthreads();
    const float gi0 = ginv[2 * th], gi1 = ginv[2 * th + 1];
    const float gi2 = ginv[8 + 2 * th], gi3 = ginv[9 + 2 * th];

    #pragma unroll
    for (int mt = 0; mt < 8; ++mt) {
        unsigned aP[4];
        aP[0] = h2bits(__floats2half2_rn(acc[mt][0][0] * gi0, acc[mt][0][1] * gi1));
        aP[1] = h2bits(__floats2half2_rn(acc[mt][0][2] * gi0, acc[mt][0][3] * gi1));
        aP[2] = h2bits(__floats2half2_rn(acc[mt][1][0] * gi2, acc[mt][1][1] * gi3));
        aP[3] = h2bits(__floats2half2_rn(acc[mt][1][2] * gi2, acc[mt][1][3] * gi3));
        float o0[4] = {0.f, 0.f, 0.f, 0.f}, o1[4] = {0.f, 0.f, 0.f, 0.f};
        unsigned bf0[2] = {postB[0], postB[2]};
        unsigned bf1[2] = {postB[1], postB[3]};
        MMA16(o0, aP, bf0);
        MMA16(o1, aP, bf1);
        const int r = jbase + mt * 16 + g8;
        *(__half2*)&big[r * 18 + 2 * th]           = __floats2half2_rn(o0[0], o0[1]);
        *(__half2*)&big[(r + 8) * 18 + 2 * th]     = __floats2half2_rn(o0[2], o0[3]);
        *(__half2*)&big[r * 18 + 8 + 2 * th]       = __floats2half2_rn(o1[0], o1[1]);
        *(__half2*)&big[(r + 8) * 18 + 8 + 2 * th] = __floats2half2_rn(o1[2], o1[3]);
    }
    __syncthreads();

    #pragma unroll
    for (int h = 0; h < 12; ++h) {
        __half* dst = g_P + rowbase + (size_t)h * 1048576;
        #pragma unroll
        for (int rep = 0; rep < 2; ++rep) {
            const int p = rep * 256 + t;
            const __half lo = big[(2 * p) * 18 + h];
            const __half hi = big[(2 * p + 1) * 18 + h];
            *(__half2*)(dst + 2 * p) = __halves2half2(lo, hi);
        }
    }
}

// ---------------------------------------------------------------------------
// K4: O = attn(fp16) @ Vh(fp16) per (b,h) -> g_Ch (single fp16 plane).
// grid (8 it, 96 bh)
// ---------------------------------------------------------------------------
__global__ __launch_bounds__(256, 2) void k_av() {
    __shared__ __align__(16) __half As[2][128 * 40];
    __shared__ __align__(16) __half Vs[2][32 * 72];
    const int tid = threadIdx.x, lane = tid & 31, w = tid >> 5;
    const int it = blockIdx.x, bh = blockIdx.y;
    const int b = bh / 12, h = bh % 12;
    const __half* Pp  = g_P  + (size_t)bh * 1048576 + (size_t)it * 131072;
    const __half* Vhp = g_Vh + (size_t)bh * 65536;
    const int wm = (w >> 1) * 32, wn = (w & 1) * 32;

    const int arow = tid >> 2, ac8 = (tid & 3) * 8;
    const int vrow = tid >> 3, vc8 = (tid & 7) * 8;

    const int lr = lane & 7, hs = (lane >> 3) & 1, kc = lane >> 4;
    const unsigned sa = (unsigned)__cvta_generic_to_shared(&As[0][0]);
    const unsigned sb = (unsigned)__cvta_generic_to_shared(&Vs[0][0]);
    const unsigned aaddr = sa + ((wm + hs * 8 + lr) * 40 + kc * 8) * 2;
    const unsigned baddr = sb + ((hs * 8 + lr) * 72 + wn + kc * 8) * 2;
    const unsigned ABUF = 128 * 40 * 2;
    const unsigned VBUF = 32 * 72 * 2;
    const unsigned adst0 = sa + (arow * 40 + ac8) * 2;
    const unsigned adst1 = sa + ((arow + 64) * 40 + ac8) * 2;
    const unsigned vdst  = sb + (vrow * 72 + vc8) * 2;

    float acc[2][4][4] = {};

    CP16(adst0, Pp + (size_t)arow * 1024 + ac8);
    CP16(adst1, Pp + (size_t)(arow + 64) * 1024 + ac8);
    CP16(vdst,  Vhp + vrow * 64 + vc8);
    CPCOMMIT();

    for (int kt = 0; kt < 32; ++kt) {
        const int cur = kt & 1;
        CPWAIT0();
        __syncthreads();
        if (kt < 31) {
            const unsigned nb = cur ^ 1;
            CP16(adst0 + nb * ABUF, Pp + (size_t)arow * 1024 + (kt + 1) * 32 + ac8);
            CP16(adst1 + nb * ABUF, Pp + (size_t)(arow + 64) * 1024 + (kt + 1) * 32 + ac8);
            CP16(vdst + nb * VBUF,  Vhp + (size_t)((kt + 1) * 32 + vrow) * 64 + vc8);
            CPCOMMIT();
        }
        #pragma unroll
        for (int kk = 0; kk < 32; kk += 16) {
            unsigned af[2][4], bvh[4][2];
            #pragma unroll
            for (int n2 = 0; n2 < 2; ++n2)
                LDSM_X4T(bvh[2*n2][0], bvh[2*n2][1], bvh[2*n2+1][0], bvh[2*n2+1][1],
                         baddr + cur * VBUF + kk * 144 + n2 * 32);
            #pragma unroll
            for (int mt = 0; mt < 2; ++mt)
                LDSM_X4(af[mt][0], af[mt][1], af[mt][2], af[mt][3],
                        aaddr + cur * ABUF + mt * 1280 + kk * 2);
            #pragma unroll
            for (int mt = 0; mt < 2; ++mt)
                #pragma unroll
                for (int nt = 0; nt < 4; ++nt)
                    MMA16(acc[mt][nt], af[mt], bvh[nt]);
        }
    }

    const int g = lane >> 2, th = lane & 3;
    #pragma unroll
    for (int mt = 0; mt < 2; ++mt) {
        const int m = it * 128 + wm + mt * 16 + g;
        #pragma unroll
        for (int nt = 0; nt < 4; ++nt) {
            const int c = wn + nt * 8 + 2 * th;
            const size_t base = ((size_t)b * 1024 + m) * 768 + h * 64 + c;
            *(__half2*)(g_Ch + base) =
                __floats2half2_rn(acc[mt][nt][0], acc[mt][nt][1]);
            *(__half2*)(g_Ch + base + 8 * 768) =
                __floats2half2_rn(acc[mt][nt][2], acc[mt][nt][3]);
        }
    }
}

// ---------------------------------------------------------------------------
// K5: out = Ctx(fp16) @ g_Woh + bo. Single A-pass, cp.async double-buffered.
// grid (6, 64)
// ---------------------------------------------------------------------------
__global__ __launch_bounds__(256, 2) void k_out(const float* __restrict__ bo,
                                                float* __restrict__ out) {
    __shared__ __align__(16) __half As[2][128 * 24];
    __shared__ __align__(16) __half Bs[2][16 * 136];
    const int tid = threadIdx.x, lane = tid & 31, w = tid >> 5;
    const int bx = blockIdx.x, by = blockIdx.y;
    const int wm = (w >> 2) * 64, wn = (w & 3) * 32;

    const int arow = tid >> 1, ac8 = (tid & 1) * 8;
    const int brow = tid >> 4, bc8 = (tid & 15) * 8;
    const __half* Chp = g_Ch + ((size_t)by * 128 + arow) * 768 + ac8;
    const __half* Bp  = g_Woh + (size_t)brow * 768 + bx * 128 + bc8;

    const int lr = lane & 7, hs = (lane >> 3) & 1, kc = lane >> 4;
    const unsigned sa = (unsigned)__cvta_generic_to_shared(&As[0][0]);
    const unsigned sb = (unsigned)__cvta_generic_to_shared(&Bs[0][0]);
    const unsigned aaddr = sa + ((wm + hs * 8 + lr) * 24 + kc * 8) * 2;
    const unsigned baddr = sb + ((hs * 8 + lr) * 136 + wn + kc * 8) * 2;
    const unsigned ABUF = 128 * 24 * 2, BBUF = 16 * 136 * 2;
    const unsigned adst = sa + (arow * 24 + ac8) * 2;
    const unsigned bdst = sb + (brow * 136 + bc8) * 2;

    float acc[4][4][4] = {};

    CP16(adst, Chp);
    CP16(bdst, Bp);
    CPCOMMIT();

    for (int kt = 0; kt < 48; ++kt) {
        const int cur = kt & 1;
        CPWAIT0();
        __syncthreads();
        if (kt < 47) {
            const unsigned nb = cur ^ 1;
            CP16(adst + nb * ABUF, Chp + (kt + 1) * 16);
            CP16(bdst + nb * BBUF, Bp + (size_t)(kt + 1) * 16 * 768);
            CPCOMMIT();
        }
        unsigned af[4][4], bh[4][2];
        #pragma unroll
        for (int n2 = 0; n2 < 2; ++n2)
            LDSM_X4T(bh[2*n2][0], bh[2*n2][1], bh[2*n2+1][0], bh[2*n2+1][1],
                     baddr + cur * BBUF + n2 * 32);
        #pragma unroll
        for (int mt = 0; mt < 4; ++mt)
            LDSM_X4(af[mt][0], af[mt][1], af[mt][2], af[mt][3],
                    aaddr + cur * ABUF + mt * 768);
        #pragma unroll
        for (int mt = 0; mt < 4; ++mt)
            #pragma unroll
            for (int nt = 0; nt < 4; ++nt)
                MMA16(acc[mt][nt], af[mt], bh[nt]);
    }

    const int g = lane >> 2, th = lane & 3;
    #pragma unroll
    for (int nt = 0; nt < 4; ++nt) {
        const int c = bx * 128 + wn + nt * 8 + 2 * th;
        const float b0v = bo[c], b1v = bo[c + 1];
        #pragma unroll
        for (int mt = 0; mt < 4; ++mt) {
            const int m = by * 128 + wm + mt * 16 + g;
            *(float2*)(out + (size_t)m * 768 + c) =
                make_float2(acc[mt][nt][0] + b0v, acc[mt][nt][1] + b1v);
            *(float2*)(out + (size_t)(m + 8) * 768 + c) =
                make_float2(acc[mt][nt][2] + b0v, acc[mt][nt][3] + b1v);
        }
    }
}

// ---------------------------------------------------------------------------
extern "C" void kernel_launch(void* const* d_in, const int* in_sizes, int n_in,
                              void* d_out, int out_size) {
    const float* x     = (const float*)d_in[0];
    const float* Wq    = (const float*)d_in[1];
    const float* Wkv   = (const float*)d_in[2];
    const float* mpre  = (const float*)d_in[3];
    const float* mpost = (const float*)d_in[4];
    const float* Wo    = (const float*)d_in[5];
    const float* bo    = (const float*)d_in[6];
    float* out = (float*)d_out;

    k_prep   <<<8448, 256>>>(x, Wq, Wkv, Wo);
    k_qkv    <<<dim3(18, 64),   256>>>();
    k_dots   <<<dim3(8, 8, 96), 256>>>();
    k_mixsoft<<<8192,           256>>>(mpre, mpost);
    k_av     <<<dim3(8, 96),    256>>>();
    k_out    <<<dim3(6, 64),    256>>>(bo, out);
}

// round 15
// speedup vs baseline: 1.4313x; 1.0542x over previous
#include <cuda_runtime.h>
#include <cuda_fp16.h>
#include <math.h>

#define Bb 8
#define Nn 1024
#define Hh 12

#define QKVSZ ((size_t)Bb*Hh*Nn*64)

// Scratch (static device globals)
__device__ __half g_xh[(size_t)8192*768], g_xl[(size_t)8192*768];
__device__ __half g_Wh[(size_t)768*2304];      // fp16 [Wq|Wkv], row-major [768][2304]
__device__ __half g_Woh[(size_t)768*768];      // fp16 Wo
__device__ __half g_Qh[QKVSZ], g_Ql[QKVSZ];
__device__ __half g_Kh[QKVSZ];
__device__ __half g_Vh[QKVSZ];
__device__ __half g_S[(size_t)Bb*Hh*Nn*Nn];    // fp16 raw logits
__device__ __half g_P[(size_t)Bb*Hh*Nn*Nn];    // fp16 post-mixed attn
__device__ __half g_Ch[(size_t)Bb*Nn*768];     // fp16 context (single plane)

// ---------------------------------------------------------------------------
__device__ __forceinline__ void split2(float a, float b, unsigned &h, unsigned &l) {
    __half ha = __float2half_rn(a), hb = __float2half_rn(b);
    __half2 H = __halves2half2(ha, hb);
    __half2 L = __halves2half2(__float2half_rn(a - __half2float(ha)),
                               __float2half_rn(b - __half2float(hb)));
    h = *(unsigned*)&H; l = *(unsigned*)&L;
}
__device__ __forceinline__ void split4(float4 v, uint2 &h, uint2 &l) {
    split2(v.x, v.y, h.x, l.x); split2(v.z, v.w, h.y, l.y);
}
__device__ __forceinline__ uint2 pack4h(float4 v) {
    __half2 a = __floats2half2_rn(v.x, v.y);
    __half2 b = __floats2half2_rn(v.z, v.w);
    uint2 r; r.x = *(unsigned*)&a; r.y = *(unsigned*)&b; return r;
}
__device__ __forceinline__ unsigned h2bits(__half2 v) { return *(unsigned*)&v; }
__device__ __forceinline__ void store_hl(__half* Gh, __half* Gl, size_t idx,
                                         float v0, float v1) {
    __half h0 = __float2half_rn(v0), h1 = __float2half_rn(v1);
    __half l0 = __float2half_rn(v0 - __half2float(h0));
    __half l1 = __float2half_rn(v1 - __half2float(h1));
    *(__half2*)(Gh + idx) = __halves2half2(h0, h1);
    *(__half2*)(Gl + idx) = __halves2half2(l0, l1);
}

#define LDSM_X4(r0, r1, r2, r3, a) \
  asm volatile("ldmatrix.sync.aligned.m8n8.x4.shared.b16 {%0,%1,%2,%3},[%4];" \
               : "=r"(r0), "=r"(r1), "=r"(r2), "=r"(r3) : "r"(a))
#define LDSM_X4T(r0, r1, r2, r3, a) \
  asm volatile("ldmatrix.sync.aligned.m8n8.x4.trans.shared.b16 {%0,%1,%2,%3},[%4];" \
               : "=r"(r0), "=r"(r1), "=r"(r2), "=r"(r3) : "r"(a))
#define MMA16(c, a, b) \
  asm volatile("mma.sync.aligned.m16n8k16.row.col.f32.f16.f16.f32 " \
               "{%0,%1,%2,%3},{%4,%5,%6,%7},{%8,%9},{%0,%1,%2,%3};" \
               : "+f"(c[0]), "+f"(c[1]), "+f"(c[2]), "+f"(c[3]) \
               : "r"(a[0]), "r"(a[1]), "r"(a[2]), "r"(a[3]), "r"(b[0]), "r"(b[1]))
#define CP16(dst, src) \
  asm volatile("cp.async.ca.shared.global [%0], [%1], 16;" :: "r"(dst), "l"(src))
#define CPCOMMIT() asm volatile("cp.async.commit_group;")
#define CPWAIT0()  asm volatile("cp.async.wait_group 0;" ::: "memory")

// ---------------------------------------------------------------------------
// K0: prep — split x into fp16 hi/lo, quantize W's to fp16 (once).
// ---------------------------------------------------------------------------
__global__ __launch_bounds__(256) void k_prep(const float* __restrict__ x,
                                              const float* __restrict__ Wq,
                                              const float* __restrict__ Wkv,
                                              const float* __restrict__ Wo) {
    const size_t id = (size_t)blockIdx.x * 256 + threadIdx.x;
    if (id < 1572864) {                       // x: 8192*768/4
        float4 v = ((const float4*)x)[id];
        uint2 h, l; split4(v, h, l);
        *(uint2*)(g_xh + 4 * id) = h;
        *(uint2*)(g_xl + 4 * id) = l;
    } else if (id < 1720320) {                // Wq
        const size_t f = id - 1572864;
        float4 v = ((const float4*)Wq)[f];
        const size_t e = 4 * f;
        const size_t k = e / 768, c = e % 768;
        *(uint2*)(g_Wh + k * 2304 + c) = pack4h(v);
    } else if (id < 2015232) {                // Wkv
        const size_t f = id - 1720320;
        float4 v = ((const float4*)Wkv)[f];
        const size_t e = 4 * f;
        const size_t k = e / 1536, c = e % 1536;
        *(uint2*)(g_Wh + k * 2304 + 768 + c) = pack4h(v);
    } else if (id < 2162688) {                // Wo
        const size_t f = id - 2015232;
        float4 v = ((const float4*)Wo)[f];
        *(uint2*)(g_Woh + 4 * f) = pack4h(v);
    }
}

// ---------------------------------------------------------------------------
// K1: QKV projection. xh/xl @ g_Wh -> Q(hi/lo, scaled 1/8), K, V fp16.
// K-chunk 32 (pitch-40 A), cp.async double-buffered. grid (18, 64).
// ---------------------------------------------------------------------------
__global__ __launch_bounds__(256, 2) void k_qkv() {
    __shared__ __align__(16) __half As[2][2 * 128 * 40];
    __shared__ __align__(16) __half Bs[2][32 * 136];
    const int tid = threadIdx.x, lane = tid & 31, w = tid >> 5;
    const int bx = blockIdx.x, by = blockIdx.y;
    const int nglob = bx * 128;
    const int m0 = by * 128;
    const int wm = (w >> 2) * 64, wn = (w & 3) * 32;

    const int lr = lane & 7, hs = (lane >> 3) & 1, kc = lane >> 4;
    const unsigned sa = (unsigned)__cvta_generic_to_shared(&As[0][0]);
    const unsigned sb = (unsigned)__cvta_generic_to_shared(&Bs[0][0]);
    const unsigned aaddr = sa + ((wm + hs * 8 + lr) * 40 + kc * 8) * 2;
    const unsigned baddr = sb + ((hs * 8 + lr) * 136 + wn + kc * 8) * 2;
    const unsigned ALOB = 128 * 40 * 2, ABUFB = 2 * 128 * 40 * 2, BBUFB = 32 * 136 * 2;
    const int arow = tid >> 2, ac8 = (tid & 3) * 8;   // + u*64 rows
    const int brow = tid >> 4, bc8 = (tid & 15) * 8;  // + u*16 rows

    float acc[4][4][4] = {};

    #pragma unroll
    for (int u = 0; u < 2; ++u) {
        const int r = u * 64 + arow;
        const unsigned d = sa + (r * 40 + ac8) * 2;
        CP16(d,        g_xh + ((size_t)(m0 + r)) * 768 + ac8);
        CP16(d + ALOB, g_xl + ((size_t)(m0 + r)) * 768 + ac8);
        const int rb = u * 16 + brow;
        CP16(sb + (rb * 136 + bc8) * 2, g_Wh + (size_t)rb * 2304 + nglob + bc8);
    }
    CPCOMMIT();

    for (int kt = 0; kt < 24; ++kt) {
        const int cur = kt & 1;
        CPWAIT0();
        __syncthreads();
        if (kt < 23) {
            const unsigned nb = cur ^ 1;
            #pragma unroll
            for (int u = 0; u < 2; ++u) {
                const int r = u * 64 + arow;
                const unsigned d = sa + nb * ABUFB + (r * 40 + ac8) * 2;
                CP16(d,        g_xh + ((size_t)(m0 + r)) * 768 + (kt + 1) * 32 + ac8);
                CP16(d + ALOB, g_xl + ((size_t)(m0 + r)) * 768 + (kt + 1) * 32 + ac8);
                const int rb = u * 16 + brow;
                CP16(sb + nb * BBUFB + (rb * 136 + bc8) * 2,
                     g_Wh + (size_t)((kt + 1) * 32 + rb) * 2304 + nglob + bc8);
            }
            CPCOMMIT();
        }
        #pragma unroll
        for (int kk = 0; kk < 32; kk += 16) {
            unsigned af[4][4], bh[4][2];
            #pragma unroll
            for (int n2 = 0; n2 < 2; ++n2)
                LDSM_X4T(bh[2*n2][0], bh[2*n2][1], bh[2*n2+1][0], bh[2*n2+1][1],
                         baddr + cur * BBUFB + kk * 272 + n2 * 32);
            #pragma unroll
            for (int mt = 0; mt < 4; ++mt)
                LDSM_X4(af[mt][0], af[mt][1], af[mt][2], af[mt][3],
                        aaddr + cur * ABUFB + mt * 1280 + kk * 2);
            #pragma unroll
            for (int mt = 0; mt < 4; ++mt)
                #pragma unroll
                for (int nt = 0; nt < 4; ++nt)
                    MMA16(acc[mt][nt], af[mt], bh[nt]);
            #pragma unroll
            for (int mt = 0; mt < 4; ++mt)
                LDSM_X4(af[mt][0], af[mt][1], af[mt][2], af[mt][3],
                        aaddr + cur * ABUFB + mt * 1280 + kk * 2 + ALOB);
            #pragma unroll
            for (int mt = 0; mt < 4; ++mt)
                #pragma unroll
                for (int nt = 0; nt < 4; ++nt)
                    MMA16(acc[mt][nt], af[mt], bh[nt]);
        }
    }

    const int g = lane >> 2, th = lane & 3;
    #pragma unroll
    for (int nt = 0; nt < 4; ++nt) {
        const int col = nglob + wn + nt * 8 + 2 * th;
        const int mat = col / 768;
        const int within = col - mat * 768;
        const int head = within >> 6, d = within & 63;
        #pragma unroll
        for (int mt = 0; mt < 4; ++mt) {
            const int mrow = m0 + wm + mt * 16 + g;
            const int b = mrow >> 10, nr = mrow & 1023;
            const size_t base = (((size_t)b * 12 + head) * 1024 + nr) * 64 + d;
            if (mat == 0) {
                store_hl(g_Qh, g_Ql, base,          acc[mt][nt][0] * 0.125f, acc[mt][nt][1] * 0.125f);
                store_hl(g_Qh, g_Ql, base + 8 * 64, acc[mt][nt][2] * 0.125f, acc[mt][nt][3] * 0.125f);
            } else {
                __half* G = (mat == 1) ? g_Kh : g_Vh;
                *(__half2*)(G + base)          = __floats2half2_rn(acc[mt][nt][0], acc[mt][nt][1]);
                *(__half2*)(G + base + 8 * 64) = __floats2half2_rn(acc[mt][nt][2], acc[mt][nt][3]);
            }
        }
    }
}

// ---------------------------------------------------------------------------
// K2: logits = (Q/8) @ K^T per (b,h). Single-stage cp.async. (round-14 proven)
// ---------------------------------------------------------------------------
__global__ __launch_bounds__(256, 2) void k_dots() {
    __shared__ __align__(16) __half Qs[2 * 128 * 72];
    __shared__ __align__(16) __half Ks[128 * 72];
    const int tid = threadIdx.x, lane = tid & 31, w = tid >> 5;
    const int jt = blockIdx.x, it = blockIdx.y, bh = blockIdx.z;
    const __half* Qhp = g_Qh + (size_t)bh * 65536 + (size_t)it * 128 * 64;
    const __half* Qlp = g_Ql + (size_t)bh * 65536 + (size_t)it * 128 * 64;
    const __half* Khp = g_Kh + (size_t)bh * 65536 + (size_t)jt * 128 * 64;
    __half* Sp = g_S + (size_t)bh * Nn * Nn;
    const int wm = (w >> 2) * 64, wn = (w & 3) * 32;

    const int lr = lane & 7, hs = (lane >> 3) & 1, kc = lane >> 4;
    const unsigned sq = (unsigned)__cvta_generic_to_shared(Qs);
    const unsigned sk = (unsigned)__cvta_generic_to_shared(Ks);
    const unsigned aaddr = sq + ((wm + hs * 8 + lr) * 72 + kc * 8) * 2;
    const unsigned kaddr = sk + ((wn + hs * 8 + lr) * 72 + kc * 8) * 2;
    const unsigned PLO = 128 * 72 * 2;

    #pragma unroll
    for (int j = 0; j < 4; ++j) {
        const int v = j * 256 + tid;
        const int row = v >> 3, c8 = (v & 7) * 8;
        const unsigned d = (row * 72 + c8) * 2;
        CP16(sq + d,       Qhp + row * 64 + c8);
        CP16(sq + d + PLO, Qlp + row * 64 + c8);
        CP16(sk + d,       Khp + row * 64 + c8);
    }
    CPCOMMIT();
    CPWAIT0();
    __syncthreads();

    float acc[4][4][4] = {};

    #pragma unroll
    for (int kk = 0; kk < 64; kk += 16) {
        unsigned bkh[4][2], af[4][4];
        #pragma unroll
        for (int n2 = 0; n2 < 2; ++n2)
            LDSM_X4(bkh[2*n2][0], bkh[2*n2+1][0], bkh[2*n2][1], bkh[2*n2+1][1],
                    kaddr + n2 * 2304 + kk * 2);
        #pragma unroll
        for (int mt = 0; mt < 4; ++mt)
            LDSM_X4(af[mt][0], af[mt][1], af[mt][2], af[mt][3],
                    aaddr + mt * 2304 + kk * 2);
        #pragma unroll
        for (int mt = 0; mt < 4; ++mt)
            #pragma unroll
            for (int nt = 0; nt < 4; ++nt)
                MMA16(acc[mt][nt], af[mt], bkh[nt]);
        #pragma unroll
        for (int mt = 0; mt < 4; ++mt)
            LDSM_X4(af[mt][0], af[mt][1], af[mt][2], af[mt][3],
                    aaddr + mt * 2304 + kk * 2 + PLO);
        #pragma unroll
        for (int mt = 0; mt < 4; ++mt)
            #pragma unroll
            for (int nt = 0; nt < 4; ++nt)
                MMA16(acc[mt][nt], af[mt], bkh[nt]);
    }

    const int g = lane >> 2, th = lane & 3;
    #pragma unroll
    for (int mt = 0; mt < 4; ++mt) {
        const int m = it * 128 + wm + mt * 16 + g;
        #pragma unroll
        for (int nt = 0; nt < 4; ++nt) {
            const int c = jt * 128 + wn + nt * 8 + 2 * th;
            *(__half2*)(Sp + (size_t)m * 1024 + c) =
                __floats2half2_rn(acc[mt][nt][0], acc[mt][nt][1]);
            *(__half2*)(Sp + (size_t)(m + 8) * 1024 + c) =
                __floats2half2_rn(acc[mt][nt][2], acc[mt][nt][3]);
        }
    }
}

// ---------------------------------------------------------------------------
// K3: talking-heads softmax on tensor cores. (round-14 proven)
// ---------------------------------------------------------------------------
__global__ __launch_bounds__(256, 2) void k_mixsoft(const float* __restrict__ mix_pre,
                                                    const float* __restrict__ mix_post) {
    __shared__ __align__(16) __half big[1024 * 18];
    __shared__ __align__(16) __half preS[16 * 24], postS[16 * 24];
    __shared__ float wred[8 * 16];
    __shared__ float gmax[16], ginv[16];
    const int t = threadIdx.x, lane = t & 31, w = t >> 5;
    const int b = blockIdx.x >> 10, i = blockIdx.x & 1023;
    const size_t rowbase = (size_t)b * 12 * 1048576 + (size_t)i * 1024;

    for (int v = t; v < 384; v += 256) {
        const int row = v / 24, col = v % 24;
        const bool ok = (row < 12) && (col < 12);
        preS[v]  = ok ? __float2half_rn(mix_pre[col * 12 + row])  : __float2half_rn(0.f);
        postS[v] = ok ? __float2half_rn(mix_post[col * 12 + row]) : __float2half_rn(0.f);
    }
    #pragma unroll
    for (int u = 0; u < 6; ++u) {
        const int v = u * 256 + t;
        const int h = v >> 7, j8 = (v & 127) * 8;
        *(uint4*)&big[h * 1032 + j8] =
            *(const uint4*)(g_S + rowbase + (size_t)h * 1048576 + j8);
    }
    #pragma unroll
    for (int u = 0; u < 3; ++u) {
        const int v = u * 256 + t;
        if (v < 516) *(uint4*)&big[12384 + v * 8] = make_uint4(0, 0, 0, 0);
    }
    __syncthreads();

    const int lr = lane & 7, hb = (lane >> 3) & 1, kc = lane >> 4;
    const int th = lane & 3, g8 = lane >> 2;
    unsigned preB[4], postB[4];
    LDSM_X4(preB[0], preB[1], preB[2], preB[3],
            (unsigned)__cvta_generic_to_shared(preS) + ((hb * 8 + lr) * 24 + kc * 8) * 2);
    LDSM_X4(postB[0], postB[1], postB[2], postB[3],
            (unsigned)__cvta_generic_to_shared(postS) + ((hb * 8 + lr) * 24 + kc * 8) * 2);

    const unsigned sbig = (unsigned)__cvta_generic_to_shared(big);
    const int hrow = ((lane >> 4) << 3) | (lane & 7);
    const int joff = ((lane >> 3) & 1) * 8;
    const int jbase = w * 128;

    float acc[8][2][4];
    #pragma unroll
    for (int mt = 0; mt < 8; ++mt) {
        unsigned a[4];
        LDSM_X4T(a[0], a[1], a[2], a[3],
                 sbig + (hrow * 1032 + jbase + mt * 16 + joff) * 2);
        #pragma unroll
        for (int nt = 0; nt < 2; ++nt) {
            acc[mt][nt][0] = acc[mt][nt][1] = acc[mt][nt][2] = acc[mt][nt][3] = 0.f;
            unsigned bf[2] = {preB[nt], preB[nt + 2]};
            MMA16(acc[mt][nt], a, bf);
        }
    }

    float lm[4] = {-1e30f, -1e30f, -1e30f, -1e30f};
    #pragma unroll
    for (int mt = 0; mt < 8; ++mt)
        #pragma unroll
        for (int nt = 0; nt < 2; ++nt) {
            lm[nt * 2 + 0] = fmaxf(lm[nt * 2 + 0], fmaxf(acc[mt][nt][0], acc[mt][nt][2]));
            lm[nt * 2 + 1] = fmaxf(lm[nt * 2 + 1], fmaxf(acc[mt][nt][1], acc[mt][nt][3]));
        }
    #pragma unroll
    for (int o = 4; o < 32; o <<= 1)
        #pragma unroll
        for (int c = 0; c < 4; ++c)
            lm[c] = fmaxf(lm[c], __shfl_xor_sync(0xffffffffu, lm[c], o));
    if (lane < 4) {
        wred[w * 16 + 2 * th]         = lm[0];
        wred[w * 16 + 2 * th + 1]     = lm[1];
        wred[w * 16 + 8 + 2 * th]     = lm[2];
        wred[w * 16 + 8 + 2 * th + 1] = lm[3];
    }
    __syncthreads();
    if (t < 16) {
        float m = wred[t];
        #pragma unroll
        for (int ww = 1; ww < 8; ++ww) m = fmaxf(m, wred[ww * 16 + t]);
        gmax[t] = m;
    }
    __syncthreads();

    const float gm0 = gmax[2 * th], gm1 = gmax[2 * th + 1];
    const float gm2 = gmax[8 + 2 * th], gm3 = gmax[9 + 2 * th];
    float ls[4] = {0.f, 0.f, 0.f, 0.f};
    #pragma unroll
    for (int mt = 0; mt < 8; ++mt) {
        acc[mt][0][0] = __expf(acc[mt][0][0] - gm0);
        acc[mt][0][1] = __expf(acc[mt][0][1] - gm1);
        acc[mt][0][2] = __expf(acc[mt][0][2] - gm0);
        acc[mt][0][3] = __expf(acc[mt][0][3] - gm1);
        acc[mt][1][0] = __expf(acc[mt][1][0] - gm2);
        acc[mt][1][1] = __expf(acc[mt][1][1] - gm3);
        acc[mt][1][2] = __expf(acc[mt][1][2] - gm2);
        acc[mt][1][3] = __expf(acc[mt][1][3] - gm3);
        ls[0] += acc[mt][0][0] + acc[mt][0][2];
        ls[1] += acc[mt][0][1] + acc[mt][0][3];
        ls[2] += acc[mt][1][0] + acc[mt][1][2];
        ls[3] += acc[mt][1][1] + acc[mt][1][3];
    }
    #pragma unroll
    for (int o = 4; o < 32; o <<= 1)
        #pragma unroll
        for (int c = 0; c < 4; ++c)
            ls[c] += __shfl_xor_sync(0xffffffffu, ls[c], o);
    if (lane < 4) {
        wred[w * 16 + 2 * th]         = ls[0];
        wred[w * 16 + 2 * th + 1]     = ls[1];
        wred[w * 16 + 8 + 2 * th]     = ls[2];
        wred[w * 16 + 8 + 2 * th + 1] = ls[3];
    }
    __syncthreads();
    if (t < 16) {
        float s = 0.f;
        #pragma unroll
        for (int ww = 0; ww < 8; ++ww) s += wred[ww * 16 + t];
        ginv[t] = 1.0f / s;
    }
    __syncthreads();
    const float gi0 = ginv[2 * th], gi1 = ginv[2 * th + 1];
    const float gi2 = ginv[8 + 2 * th], gi3 = ginv[9 + 2 * th];

    #pragma unroll
    for (int mt = 0; mt < 8; ++mt) {
        unsigned aP[4];
        aP[0] = h2bits(__floats2half2_rn(acc[mt][0][0] * gi0, acc[mt][0][1] * gi1));
        aP[1] = h2bits(__floats2half2_rn(acc[mt][0][2] * gi0, acc[mt][0][3] * gi1));
        aP[2] = h2bits(__floats2half2_rn(acc[mt][1][0] * gi2, acc[mt][1][1] * gi3));
        aP[3] = h2bits(__floats2half2_rn(acc[mt][1][2] * gi2, acc[mt][1][3] * gi3));
        float o0[4] = {0.f, 0.f, 0.f, 0.f}, o1[4] = {0.f, 0.f, 0.f, 0.f};
        unsigned bf0[2] = {postB[0], postB[2]};
        unsigned bf1[2] = {postB[1], postB[3]};
        MMA16(o0, aP, bf0);
        MMA16(o1, aP, bf1);
        const int r = jbase + mt * 16 + g8;
        *(__half2*)&big[r * 18 + 2 * th]           = __floats2half2_rn(o0[0], o0[1]);
        *(__half2*)&big[(r + 8) * 18 + 2 * th]     = __floats2half2_rn(o0[2], o0[3]);
        *(__half2*)&big[r * 18 + 8 + 2 * th]       = __floats2half2_rn(o1[0], o1[1]);
        *(__half2*)&big[(r + 8) * 18 + 8 + 2 * th] = __floats2half2_rn(o1[2], o1[3]);
    }
    __syncthreads();

    #pragma unroll
    for (int h = 0; h < 12; ++h) {
        __half* dst = g_P + rowbase + (size_t)h * 1048576;
        #pragma unroll
        for (int rep = 0; rep < 2; ++rep) {
            const int p = rep * 256 + t;
            const __half lo = big[(2 * p) * 18 + h];
            const __half hi = big[(2 * p + 1) * 18 + h];
            *(__half2*)(dst + 2 * p) = __halves2half2(lo, hi);
        }
    }
}

// ---------------------------------------------------------------------------
// K4: O = attn(fp16) @ Vh(fp16) per (b,h) -> g_Ch. M-tile 64 (MT=1), K-chunk 32,
// cp.async double-buffered. grid (16 it, 96 bh).
// ---------------------------------------------------------------------------
__global__ __launch_bounds__(256) void k_av() {
    __shared__ __align__(16) __half As[2][64 * 40];
    __shared__ __align__(16) __half Vs[2][32 * 72];
    const int tid = threadIdx.x, lane = tid & 31, w = tid >> 5;
    const int it = blockIdx.x, bh = blockIdx.y;
    const int b = bh / 12, h = bh % 12;
    const __half* Pp  = g_P  + (size_t)bh * 1048576 + (size_t)it * 65536;
    const __half* Vhp = g_Vh + (size_t)bh * 65536;
    const int wm = (w >> 1) * 16, wn = (w & 1) * 32;

    const int arow = tid >> 2, ac8 = (tid & 3) * 8;   // 64 rows x 4 groups
    const int vrow = tid >> 3, vc8 = (tid & 7) * 8;   // 32 rows x 8 groups

    const int lr = lane & 7, hs = (lane >> 3) & 1, kc = lane >> 4;
    const unsigned sa = (unsigned)__cvta_generic_to_shared(&As[0][0]);
    const unsigned sb = (unsigned)__cvta_generic_to_shared(&Vs[0][0]);
    const unsigned aaddr = sa + ((wm + hs * 8 + lr) * 40 + kc * 8) * 2;
    const unsigned baddr = sb + ((hs * 8 + lr) * 72 + wn + kc * 8) * 2;
    const unsigned ABUFB = 64 * 40 * 2;
    const unsigned VBUFB = 32 * 72 * 2;
    const unsigned adst = sa + (arow * 40 + ac8) * 2;
    const unsigned vdst = sb + (vrow * 72 + vc8) * 2;

    float acc[4][4] = {};

    CP16(adst, Pp + (size_t)arow * 1024 + ac8);
    CP16(vdst, Vhp + vrow * 64 + vc8);
    CPCOMMIT();

    for (int kt = 0; kt < 32; ++kt) {
        const int cur = kt & 1;
        CPWAIT0();
        __syncthreads();
        if (kt < 31) {
            const unsigned nb = cur ^ 1;
            CP16(adst + nb * ABUFB, Pp + (size_t)arow * 1024 + (kt + 1) * 32 + ac8);
            CP16(vdst + nb * VBUFB, Vhp + (size_t)((kt + 1) * 32 + vrow) * 64 + vc8);
            CPCOMMIT();
        }
        #pragma unroll
        for (int kk = 0; kk < 32; kk += 16) {
            unsigned af[4], bvh[4][2];
            #pragma unroll
            for (int n2 = 0; n2 < 2; ++n2)
                LDSM_X4T(bvh[2*n2][0], bvh[2*n2][1], bvh[2*n2+1][0], bvh[2*n2+1][1],
                         baddr + cur * VBUFB + kk * 144 + n2 * 32);
            LDSM_X4(af[0], af[1], af[2], af[3],
                    aaddr + cur * ABUFB + kk * 2);
            #pragma unroll
            for (int nt = 0; nt < 4; ++nt)
                MMA16(acc[nt], af, bvh[nt]);
        }
    }

    const int g = lane >> 2, th = lane & 3;
    const int m = it * 64 + wm + g;
    #pragma unroll
    for (int nt = 0; nt < 4; ++nt) {
        const int c = wn + nt * 8 + 2 * th;
        const size_t base = ((size_t)b * 1024 + m) * 768 + h * 64 + c;
        *(__half2*)(g_Ch + base)           = __floats2half2_rn(acc[nt][0], acc[nt][1]);
        *(__half2*)(g_Ch + base + 8 * 768) = __floats2half2_rn(acc[nt][2], acc[nt][3]);
    }
}

// ---------------------------------------------------------------------------
// K5: out = Ctx(fp16) @ g_Woh + bo. N-tile 64, K-chunk 32, double-buffered.
// grid (12, 64). Warps 4m x 2n (MT=2, NT=4).
// ---------------------------------------------------------------------------
__global__ __launch_bounds__(256) void k_out(const float* __restrict__ bo,
                                             float* __restrict__ out) {
    __shared__ __align__(16) __half As[2][128 * 40];
    __shared__ __align__(16) __half Bs[2][32 * 72];
    const int tid = threadIdx.x, lane = tid & 31, w = tid >> 5;
    const int bx = blockIdx.x, by = blockIdx.y;
    const int wm = (w >> 1) * 32, wn = (w & 1) * 32;

    const int arow = tid >> 1, ac8 = (tid & 1) * 8;   // 128 rows x 2 groups (16 halves) -> 2 CP16 via u
    const int brow = tid >> 3, bc8 = (tid & 7) * 8;   // 32 rows x 8 groups
    const __half* Chp = g_Ch + ((size_t)by * 128) * 768;
    const __half* Bp  = g_Woh + bx * 64;

    const int lr = lane & 7, hs = (lane >> 3) & 1, kc = lane >> 4;
    const unsigned sa = (unsigned)__cvta_generic_to_shared(&As[0][0]);
    const unsigned sb = (unsigned)__cvta_generic_to_shared(&Bs[0][0]);
    const unsigned aaddr = sa + ((wm + hs * 8 + lr) * 40 + kc * 8) * 2;
    const unsigned baddr = sb + ((hs * 8 + lr) * 72 + wn + kc * 8) * 2;
    const unsigned ABUFB = 128 * 40 * 2, BBUFB = 32 * 72 * 2;

    float acc[2][4][4] = {};

    #pragma unroll
    for (int u = 0; u < 2; ++u) {
        const unsigned d = sa + (arow * 40 + u * 16 + ac8) * 2;
        CP16(d, Chp + (size_t)arow * 768 + u * 16 + ac8);
    }
    CP16(sb + (brow * 72 + bc8) * 2, Bp + (size_t)brow * 768 + bc8);
    CPCOMMIT();

    for (int kt = 0; kt < 24; ++kt) {
        const int cur = kt & 1;
        CPWAIT0();
        __syncthreads();
        if (kt < 23) {
            const unsigned nb = cur ^ 1;
            #pragma unroll
            for (int u = 0; u < 2; ++u) {
                const unsigned d = sa + nb * ABUFB + (arow * 40 + u * 16 + ac8) * 2;
                CP16(d, Chp + (size_t)arow * 768 + (kt + 1) * 32 + u * 16 + ac8);
            }
            CP16(sb + nb * BBUFB + (brow * 72 + bc8) * 2,
                 Bp + (size_t)((kt + 1) * 32 + brow) * 768 + bc8);
            CPCOMMIT();
        }
        #pragma unroll
        for (int kk = 0; kk < 32; kk += 16) {
            unsigned af[2][4], bh[4][2];
            #pragma unroll
            for (int n2 = 0; n2 < 2; ++n2)
                LDSM_X4T(bh[2*n2][0], bh[2*n2][1], bh[2*n2+1][0], bh[2*n2+1][1],
                         baddr + cur * BBUFB + kk * 144 + n2 * 32);
            #pragma unroll
            for (int mt = 0; mt < 2; ++mt)
                LDSM_X4(af[mt][0], af[mt][1], af[mt][2], af[mt][3],
                        aaddr + cur * ABUFB + mt * 1280 + kk * 2);
            #pragma unroll
            for (int mt = 0; mt < 2; ++mt)
                #pragma unroll
                for (int nt = 0; nt < 4; ++nt)
                    MMA16(acc[mt][nt], af[mt], bh[nt]);
        }
    }

    const int g = lane >> 2, th = lane & 3;
    #pragma unroll
    for (int nt = 0; nt < 4; ++nt) {
        const int c = bx * 64 + wn + nt * 8 + 2 * th;
        const float b0v = bo[c], b1v = bo[c + 1];
        #pragma unroll
        for (int mt = 0; mt < 2; ++mt) {
            const int m = by * 128 + wm + mt * 16 + g;
            *(float2*)(out + (size_t)m * 768 + c) =
                make_float2(acc[mt][nt][0] + b0v, acc[mt][nt][1] + b1v);
            *(float2*)(out + (size_t)(m + 8) * 768 + c) =
                make_float2(acc[mt][nt][2] + b0v, acc[mt][nt][3] + b1v);
        }
    }
}

// ---------------------------------------------------------------------------
extern "C" void kernel_launch(void* const* d_in, const int* in_sizes, int n_in,
                              void* d_out, int out_size) {
    const float* x     = (const float*)d_in[0];
    const float* Wq    = (const float*)d_in[1];
    const float* Wkv   = (const float*)d_in[2];
    const float* mpre  = (const float*)d_in[3];
    const float* mpost = (const float*)d_in[4];
    const float* Wo    = (const float*)d_in[5];
    const float* bo    = (const float*)d_in[6];
    float* out = (float*)d_out;

    k_prep   <<<8448, 256>>>(x, Wq, Wkv, Wo);
    k_qkv    <<<dim3(18, 64),   256>>>();
    k_dots   <<<dim3(8, 8, 96), 256>>>();
    k_mixsoft<<<8192,           256>>>(mpre, mpost);
    k_av     <<<dim3(16, 96),   256>>>();
    k_out    <<<dim3(12, 64),   256>>>(bo, out);
}

// round 16
// speedup vs baseline: 1.4694x; 1.0266x over previous
#include <cuda_runtime.h>
#include <cuda_fp16.h>
#include <math.h>

#define Bb 8
#define Nn 1024
#define Hh 12

#define QKVSZ ((size_t)Bb*Hh*Nn*64)

// Scratch (static device globals)
__device__ __half g_xh[(size_t)8192*768], g_xl[(size_t)8192*768];
__device__ __half g_Wh[(size_t)768*2304];      // fp16 [Wq|Wkv], row-major [768][2304]
__device__ __half g_Woh[(size_t)768*768];      // fp16 Wo
__device__ __half g_Qh[QKVSZ], g_Ql[QKVSZ];
__device__ __half g_Kh[QKVSZ];
__device__ __half g_Vh[QKVSZ];
__device__ __half g_S[(size_t)Bb*Hh*Nn*Nn];    // fp16 raw logits
__device__ __half g_P[(size_t)Bb*Hh*Nn*Nn];    // fp16 post-mixed attn
__device__ __half g_Ch[(size_t)Bb*Nn*768];     // fp16 context (single plane)

// ---------------------------------------------------------------------------
__device__ __forceinline__ void split2(float a, float b, unsigned &h, unsigned &l) {
    __half ha = __float2half_rn(a), hb = __float2half_rn(b);
    __half2 H = __halves2half2(ha, hb);
    __half2 L = __halves2half2(__float2half_rn(a - __half2float(ha)),
                               __float2half_rn(b - __half2float(hb)));
    h = *(unsigned*)&H; l = *(unsigned*)&L;
}
__device__ __forceinline__ void split4(float4 v, uint2 &h, uint2 &l) {
    split2(v.x, v.y, h.x, l.x); split2(v.z, v.w, h.y, l.y);
}
__device__ __forceinline__ uint2 pack4h(float4 v) {
    __half2 a = __floats2half2_rn(v.x, v.y);
    __half2 b = __floats2half2_rn(v.z, v.w);
    uint2 r; r.x = *(unsigned*)&a; r.y = *(unsigned*)&b; return r;
}
__device__ __forceinline__ unsigned h2bits(__half2 v) { return *(unsigned*)&v; }
__device__ __forceinline__ void store_hl(__half* Gh, __half* Gl, size_t idx,
                                         float v0, float v1) {
    __half h0 = __float2half_rn(v0), h1 = __float2half_rn(v1);
    __half l0 = __float2half_rn(v0 - __half2float(h0));
    __half l1 = __float2half_rn(v1 - __half2float(h1));
    *(__half2*)(Gh + idx) = __halves2half2(h0, h1);
    *(__half2*)(Gl + idx) = __halves2half2(l0, l1);
}

#define LDSM_X4(r0, r1, r2, r3, a) \
  asm volatile("ldmatrix.sync.aligned.m8n8.x4.shared.b16 {%0,%1,%2,%3},[%4];" \
               : "=r"(r0), "=r"(r1), "=r"(r2), "=r"(r3) : "r"(a))
#define LDSM_X4T(r0, r1, r2, r3, a) \
  asm volatile("ldmatrix.sync.aligned.m8n8.x4.trans.shared.b16 {%0,%1,%2,%3},[%4];" \
               : "=r"(r0), "=r"(r1), "=r"(r2), "=r"(r3) : "r"(a))
#define MMA16(c, a, b) \
  asm volatile("mma.sync.aligned.m16n8k16.row.col.f32.f16.f16.f32 " \
               "{%0,%1,%2,%3},{%4,%5,%6,%7},{%8,%9},{%0,%1,%2,%3};" \
               : "+f"(c[0]), "+f"(c[1]), "+f"(c[2]), "+f"(c[3]) \
               : "r"(a[0]), "r"(a[1]), "r"(a[2]), "r"(a[3]), "r"(b[0]), "r"(b[1]))
#define CP16(dst, src) \
  asm volatile("cp.async.ca.shared.global [%0], [%1], 16;" :: "r"(dst), "l"(src))
#define CPCOMMIT() asm volatile("cp.async.commit_group;")
#define CPWAIT0()  asm volatile("cp.async.wait_group 0;" ::: "memory")

// ---------------------------------------------------------------------------
// K0: prep — split x into fp16 hi/lo, quantize W's to fp16 (once).
// ---------------------------------------------------------------------------
__global__ __launch_bounds__(256) void k_prep(const float* __restrict__ x,
                                              const float* __restrict__ Wq,
                                              const float* __restrict__ Wkv,
                                              const float* __restrict__ Wo) {
    const size_t id = (size_t)blockIdx.x * 256 + threadIdx.x;
    if (id < 1572864) {                       // x: 8192*768/4
        float4 v = ((const float4*)x)[id];
        uint2 h, l; split4(v, h, l);
        *(uint2*)(g_xh + 4 * id) = h;
        *(uint2*)(g_xl + 4 * id) = l;
    } else if (id < 1720320) {                // Wq
        const size_t f = id - 1572864;
        float4 v = ((const float4*)Wq)[f];
        const size_t e = 4 * f;
        const size_t k = e / 768, c = e % 768;
        *(uint2*)(g_Wh + k * 2304 + c) = pack4h(v);
    } else if (id < 2015232) {                // Wkv
        const size_t f = id - 1720320;
        float4 v = ((const float4*)Wkv)[f];
        const size_t e = 4 * f;
        const size_t k = e / 1536, c = e % 1536;
        *(uint2*)(g_Wh + k * 2304 + 768 + c) = pack4h(v);
    } else if (id < 2162688) {                // Wo
        const size_t f = id - 2015232;
        float4 v = ((const float4*)Wo)[f];
        *(uint2*)(g_Woh + 4 * f) = pack4h(v);
    }
}

// ---------------------------------------------------------------------------
// K1: QKV projection. xh/xl @ g_Wh -> Q(hi/lo, scaled 1/8), K, V fp16.
// K-chunk 32 (pitch-40 A), cp.async double-buffered. grid (18, 64).
// ---------------------------------------------------------------------------
__global__ __launch_bounds__(256, 2) void k_qkv() {
    __shared__ __align__(16) __half As[2][2 * 128 * 40];
    __shared__ __align__(16) __half Bs[2][32 * 136];
    const int tid = threadIdx.x, lane = tid & 31, w = tid >> 5;
    const int bx = blockIdx.x, by = blockIdx.y;
    const int nglob = bx * 128;
    const int m0 = by * 128;
    const int wm = (w >> 2) * 64, wn = (w & 3) * 32;

    const int lr = lane & 7, hs = (lane >> 3) & 1, kc = lane >> 4;
    const unsigned sa = (unsigned)__cvta_generic_to_shared(&As[0][0]);
    const unsigned sb = (unsigned)__cvta_generic_to_shared(&Bs[0][0]);
    const unsigned aaddr = sa + ((wm + hs * 8 + lr) * 40 + kc * 8) * 2;
    const unsigned baddr = sb + ((hs * 8 + lr) * 136 + wn + kc * 8) * 2;
    const unsigned ALOB = 128 * 40 * 2, ABUFB = 2 * 128 * 40 * 2, BBUFB = 32 * 136 * 2;
    const int arow = tid >> 2, ac8 = (tid & 3) * 8;   // + u*64 rows
    const int brow = tid >> 4, bc8 = (tid & 15) * 8;  // + u*16 rows

    float acc[4][4][4] = {};

    #pragma unroll
    for (int u = 0; u < 2; ++u) {
        const int r = u * 64 + arow;
        const unsigned d = sa + (r * 40 + ac8) * 2;
        CP16(d,        g_xh + ((size_t)(m0 + r)) * 768 + ac8);
        CP16(d + ALOB, g_xl + ((size_t)(m0 + r)) * 768 + ac8);
        const int rb = u * 16 + brow;
        CP16(sb + (rb * 136 + bc8) * 2, g_Wh + (size_t)rb * 2304 + nglob + bc8);
    }
    CPCOMMIT();

    for (int kt = 0; kt < 24; ++kt) {
        const int cur = kt & 1;
        CPWAIT0();
        __syncthreads();
        if (kt < 23) {
            const unsigned nb = cur ^ 1;
            #pragma unroll
            for (int u = 0; u < 2; ++u) {
                const int r = u * 64 + arow;
                const unsigned d = sa + nb * ABUFB + (r * 40 + ac8) * 2;
                CP16(d,        g_xh + ((size_t)(m0 + r)) * 768 + (kt + 1) * 32 + ac8);
                CP16(d + ALOB, g_xl + ((size_t)(m0 + r)) * 768 + (kt + 1) * 32 + ac8);
                const int rb = u * 16 + brow;
                CP16(sb + nb * BBUFB + (rb * 136 + bc8) * 2,
                     g_Wh + (size_t)((kt + 1) * 32 + rb) * 2304 + nglob + bc8);
            }
            CPCOMMIT();
        }
        #pragma unroll
        for (int kk = 0; kk < 32; kk += 16) {
            unsigned af[4][4], bh[4][2];
            #pragma unroll
            for (int n2 = 0; n2 < 2; ++n2)
                LDSM_X4T(bh[2*n2][0], bh[2*n2][1], bh[2*n2+1][0], bh[2*n2+1][1],
                         baddr + cur * BBUFB + kk * 272 + n2 * 32);
            #pragma unroll
            for (int mt = 0; mt < 4; ++mt)
                LDSM_X4(af[mt][0], af[mt][1], af[mt][2], af[mt][3],
                        aaddr + cur * ABUFB + mt * 1280 + kk * 2);
            #pragma unroll
            for (int mt = 0; mt < 4; ++mt)
                #pragma unroll
                for (int nt = 0; nt < 4; ++nt)
                    MMA16(acc[mt][nt], af[mt], bh[nt]);
            #pragma unroll
            for (int mt = 0; mt < 4; ++mt)
                LDSM_X4(af[mt][0], af[mt][1], af[mt][2], af[mt][3],
                        aaddr + cur * ABUFB + mt * 1280 + kk * 2 + ALOB);
            #pragma unroll
            for (int mt = 0; mt < 4; ++mt)
                #pragma unroll
                for (int nt = 0; nt < 4; ++nt)
                    MMA16(acc[mt][nt], af[mt], bh[nt]);
        }
    }

    const int g = lane >> 2, th = lane & 3;
    #pragma unroll
    for (int nt = 0; nt < 4; ++nt) {
        const int col = nglob + wn + nt * 8 + 2 * th;
        const int mat = col / 768;
        const int within = col - mat * 768;
        const int head = within >> 6, d = within & 63;
        #pragma unroll
        for (int mt = 0; mt < 4; ++mt) {
            const int mrow = m0 + wm + mt * 16 + g;
            const int b = mrow >> 10, nr = mrow & 1023;
            const size_t base = (((size_t)b * 12 + head) * 1024 + nr) * 64 + d;
            if (mat == 0) {
                store_hl(g_Qh, g_Ql, base,          acc[mt][nt][0] * 0.125f, acc[mt][nt][1] * 0.125f);
                store_hl(g_Qh, g_Ql, base + 8 * 64, acc[mt][nt][2] * 0.125f, acc[mt][nt][3] * 0.125f);
            } else {
                __half* G = (mat == 1) ? g_Kh : g_Vh;
                *(__half2*)(G + base)          = __floats2half2_rn(acc[mt][nt][0], acc[mt][nt][1]);
                *(__half2*)(G + base + 8 * 64) = __floats2half2_rn(acc[mt][nt][2], acc[mt][nt][3]);
            }
        }
    }
}

// ---------------------------------------------------------------------------
// K2: logits = (Q/8) @ K^T per (b,h). Single-stage cp.async. (round-15 proven)
// ---------------------------------------------------------------------------
__global__ __launch_bounds__(256, 2) void k_dots() {
    __shared__ __align__(16) __half Qs[2 * 128 * 72];
    __shared__ __align__(16) __half Ks[128 * 72];
    const int tid = threadIdx.x, lane = tid & 31, w = tid >> 5;
    const int jt = blockIdx.x, it = blockIdx.y, bh = blockIdx.z;
    const __half* Qhp = g_Qh + (size_t)bh * 65536 + (size_t)it * 128 * 64;
    const __half* Qlp = g_Ql + (size_t)bh * 65536 + (size_t)it * 128 * 64;
    const __half* Khp = g_Kh + (size_t)bh * 65536 + (size_t)jt * 128 * 64;
    __half* Sp = g_S + (size_t)bh * Nn * Nn;
    const int wm = (w >> 2) * 64, wn = (w & 3) * 32;

    const int lr = lane & 7, hs = (lane >> 3) & 1, kc = lane >> 4;
    const unsigned sq = (unsigned)__cvta_generic_to_shared(Qs);
    const unsigned sk = (unsigned)__cvta_generic_to_shared(Ks);
    const unsigned aaddr = sq + ((wm + hs * 8 + lr) * 72 + kc * 8) * 2;
    const unsigned kaddr = sk + ((wn + hs * 8 + lr) * 72 + kc * 8) * 2;
    const unsigned PLO = 128 * 72 * 2;

    #pragma unroll
    for (int j = 0; j < 4; ++j) {
        const int v = j * 256 + tid;
        const int row = v >> 3, c8 = (v & 7) * 8;
        const unsigned d = (row * 72 + c8) * 2;
        CP16(sq + d,       Qhp + row * 64 + c8);
        CP16(sq + d + PLO, Qlp + row * 64 + c8);
        CP16(sk + d,       Khp + row * 64 + c8);
    }
    CPCOMMIT();
    CPWAIT0();
    __syncthreads();

    float acc[4][4][4] = {};

    #pragma unroll
    for (int kk = 0; kk < 64; kk += 16) {
        unsigned bkh[4][2], af[4][4];
        #pragma unroll
        for (int n2 = 0; n2 < 2; ++n2)
            LDSM_X4(bkh[2*n2][0], bkh[2*n2+1][0], bkh[2*n2][1], bkh[2*n2+1][1],
                    kaddr + n2 * 2304 + kk * 2);
        #pragma unroll
        for (int mt = 0; mt < 4; ++mt)
            LDSM_X4(af[mt][0], af[mt][1], af[mt][2], af[mt][3],
                    aaddr + mt * 2304 + kk * 2);
        #pragma unroll
        for (int mt = 0; mt < 4; ++mt)
            #pragma unroll
            for (int nt = 0; nt < 4; ++nt)
                MMA16(acc[mt][nt], af[mt], bkh[nt]);
        #pragma unroll
        for (int mt = 0; mt < 4; ++mt)
            LDSM_X4(af[mt][0], af[mt][1], af[mt][2], af[mt][3],
                    aaddr + mt * 2304 + kk * 2 + PLO);
        #pragma unroll
        for (int mt = 0; mt < 4; ++mt)
            #pragma unroll
            for (int nt = 0; nt < 4; ++nt)
                MMA16(acc[mt][nt], af[mt], bkh[nt]);
    }

    const int g = lane >> 2, th = lane & 3;
    #pragma unroll
    for (int mt = 0; mt < 4; ++mt) {
        const int m = it * 128 + wm + mt * 16 + g;
        #pragma unroll
        for (int nt = 0; nt < 4; ++nt) {
            const int c = jt * 128 + wn + nt * 8 + 2 * th;
            *(__half2*)(Sp + (size_t)m * 1024 + c) =
                __floats2half2_rn(acc[mt][nt][0], acc[mt][nt][1]);
            *(__half2*)(Sp + (size_t)(m + 8) * 1024 + c) =
                __floats2half2_rn(acc[mt][nt][2], acc[mt][nt][3]);
        }
    }
}

// ---------------------------------------------------------------------------
// K3: talking-heads softmax on tensor cores. min-3-CTAs register cap
// (107 regs limited occupancy to 2 CTAs/SM; spills are cold acc tail).
// ---------------------------------------------------------------------------
__global__ __launch_bounds__(256, 3) void k_mixsoft(const float* __restrict__ mix_pre,
                                                    const float* __restrict__ mix_post) {
    __shared__ __align__(16) __half big[1024 * 18];
    __shared__ __align__(16) __half preS[16 * 24], postS[16 * 24];
    __shared__ float wred[8 * 16];
    __shared__ float gmax[16], ginv[16];
    const int t = threadIdx.x, lane = t & 31, w = t >> 5;
    const int b = blockIdx.x >> 10, i = blockIdx.x & 1023;
    const size_t rowbase = (size_t)b * 12 * 1048576 + (size_t)i * 1024;

    for (int v = t; v < 384; v += 256) {
        const int row = v / 24, col = v % 24;
        const bool ok = (row < 12) && (col < 12);
        preS[v]  = ok ? __float2half_rn(mix_pre[col * 12 + row])  : __float2half_rn(0.f);
        postS[v] = ok ? __float2half_rn(mix_post[col * 12 + row]) : __float2half_rn(0.f);
    }
    #pragma unroll
    for (int u = 0; u < 6; ++u) {
        const int v = u * 256 + t;
        const int h = v >> 7, j8 = (v & 127) * 8;
        *(uint4*)&big[h * 1032 + j8] =
            *(const uint4*)(g_S + rowbase + (size_t)h * 1048576 + j8);
    }
    #pragma unroll
    for (int u = 0; u < 3; ++u) {
        const int v = u * 256 + t;
        if (v < 516) *(uint4*)&big[12384 + v * 8] = make_uint4(0, 0, 0, 0);
    }
    __syncthreads();

    const int lr = lane & 7, hb = (lane >> 3) & 1, kc = lane >> 4;
    const int th = lane & 3, g8 = lane >> 2;
    unsigned preB[4], postB[4];
    LDSM_X4(preB[0], preB[1], preB[2], preB[3],
            (unsigned)__cvta_generic_to_shared(preS) + ((hb * 8 + lr) * 24 + kc * 8) * 2);
    LDSM_X4(postB[0], postB[1], postB[2], postB[3],
            (unsigned)__cvta_generic_to_shared(postS) + ((hb * 8 + lr) * 24 + kc * 8) * 2);

    const unsigned sbig = (unsigned)__cvta_generic_to_shared(big);
    const int hrow = ((lane >> 4) << 3) | (lane & 7);
    const int joff = ((lane >> 3) & 1) * 8;
    const int jbase = w * 128;

    float acc[8][2][4];
    #pragma unroll
    for (int mt = 0; mt < 8; ++mt) {
        unsigned a[4];
        LDSM_X4T(a[0], a[1], a[2], a[3],
                 sbig + (hrow * 1032 + jbase + mt * 16 + joff) * 2);
        #pragma unroll
        for (int nt = 0; nt < 2; ++nt) {
            acc[mt][nt][0] = acc[mt][nt][1] = acc[mt][nt][2] = acc[mt][nt][3] = 0.f;
            unsigned bf[2] = {preB[nt], preB[nt + 2]};
            MMA16(acc[mt][nt], a, bf);
        }
    }

    float lm[4] = {-1e30f, -1e30f, -1e30f, -1e30f};
    #pragma unroll
    for (int mt = 0; mt < 8; ++mt)
        #pragma unroll
        for (int nt = 0; nt < 2; ++nt) {
            lm[nt * 2 + 0] = fmaxf(lm[nt * 2 + 0], fmaxf(acc[mt][nt][0], acc[mt][nt][2]));
            lm[nt * 2 + 1] = fmaxf(lm[nt * 2 + 1], fmaxf(acc[mt][nt][1], acc[mt][nt][3]));
        }
    #pragma unroll
    for (int o = 4; o < 32; o <<= 1)
        #pragma unroll
        for (int c = 0; c < 4; ++c)
            lm[c] = fmaxf(lm[c], __shfl_xor_sync(0xffffffffu, lm[c], o));
    if (lane < 4) {
        wred[w * 16 + 2 * th]         = lm[0];
        wred[w * 16 + 2 * th + 1]     = lm[1];
        wred[w * 16 + 8 + 2 * th]     = lm[2];
        wred[w * 16 + 8 + 2 * th + 1] = lm[3];
    }
    __syncthreads();
    if (t < 16) {
        float m = wred[t];
        #pragma unroll
        for (int ww = 1; ww < 8; ++ww) m = fmaxf(m, wred[ww * 16 + t]);
        gmax[t] = m;
    }
    __syncthreads();

    const float gm0 = gmax[2 * th], gm1 = gmax[2 * th + 1];
    const float gm2 = gmax[8 + 2 * th], gm3 = gmax[9 + 2 * th];
    float ls[4] = {0.f, 0.f, 0.f, 0.f};
    #pragma unroll
    for (int mt = 0; mt < 8; ++mt) {
        acc[mt][0][0] = __expf(acc[mt][0][0] - gm0);
        acc[mt][0][1] = __expf(acc[mt][0][1] - gm1);
        acc[mt][0][2] = __expf(acc[mt][0][2] - gm0);
        acc[mt][0][3] = __expf(acc[mt][0][3] - gm1);
        acc[mt][1][0] = __expf(acc[mt][1][0] - gm2);
        acc[mt][1][1] = __expf(acc[mt][1][1] - gm3);
        acc[mt][1][2] = __expf(acc[mt][1][2] - gm2);
        acc[mt][1][3] = __expf(acc[mt][1][3] - gm3);
        ls[0] += acc[mt][0][0] + acc[mt][0][2];
        ls[1] += acc[mt][0][1] + acc[mt][0][3];
        ls[2] += acc[mt][1][0] + acc[mt][1][2];
        ls[3] += acc[mt][1][1] + acc[mt][1][3];
    }
    #pragma unroll
    for (int o = 4; o < 32; o <<= 1)
        #pragma unroll
        for (int c = 0; c < 4; ++c)
            ls[c] += __shfl_xor_sync(0xffffffffu, ls[c], o);
    if (lane < 4) {
        wred[w * 16 + 2 * th]         = ls[0];
        wred[w * 16 + 2 * th + 1]     = ls[1];
        wred[w * 16 + 8 + 2 * th]     = ls[2];
        wred[w * 16 + 8 + 2 * th + 1] = ls[3];
    }
    __syncthreads();
    if (t < 16) {
        float s = 0.f;
        #pragma unroll
        for (int ww = 0; ww < 8; ++ww) s += wred[ww * 16 + t];
        ginv[t] = 1.0f / s;
    }
    __syncthreads();
    const float gi0 = ginv[2 * th], gi1 = ginv[2 * th + 1];
    const float gi2 = ginv[8 + 2 * th], gi3 = ginv[9 + 2 * th];

    #pragma unroll
    for (int mt = 0; mt < 8; ++mt) {
        unsigned aP[4];
        aP[0] = h2bits(__floats2half2_rn(acc[mt][0][0] * gi0, acc[mt][0][1] * gi1));
        aP[1] = h2bits(__floats2half2_rn(acc[mt][0][2] * gi0, acc[mt][0][3] * gi1));
        aP[2] = h2bits(__floats2half2_rn(acc[mt][1][0] * gi2, acc[mt][1][1] * gi3));
        aP[3] = h2bits(__floats2half2_rn(acc[mt][1][2] * gi2, acc[mt][1][3] * gi3));
        float o0[4] = {0.f, 0.f, 0.f, 0.f}, o1[4] = {0.f, 0.f, 0.f, 0.f};
        unsigned bf0[2] = {postB[0], postB[2]};
        unsigned bf1[2] = {postB[1], postB[3]};
        MMA16(o0, aP, bf0);
        MMA16(o1, aP, bf1);
        const int r = jbase + mt * 16 + g8;
        *(__half2*)&big[r * 18 + 2 * th]           = __floats2half2_rn(o0[0], o0[1]);
        *(__half2*)&big[(r + 8) * 18 + 2 * th]     = __floats2half2_rn(o0[2], o0[3]);
        *(__half2*)&big[r * 18 + 8 + 2 * th]       = __floats2half2_rn(o1[0], o1[1]);
        *(__half2*)&big[(r + 8) * 18 + 8 + 2 * th] = __floats2half2_rn(o1[2], o1[3]);
    }
    __syncthreads();

    #pragma unroll
    for (int h = 0; h < 12; ++h) {
        __half* dst = g_P + rowbase + (size_t)h * 1048576;
        #pragma unroll
        for (int rep = 0; rep < 2; ++rep) {
            const int p = rep * 256 + t;
            const __half lo = big[(2 * p) * 18 + h];
            const __half hi = big[(2 * p + 1) * 18 + h];
            *(__half2*)(dst + 2 * p) = __halves2half2(lo, hi);
        }
    }
}

// ---------------------------------------------------------------------------
// K4: O = attn(fp16) @ Vh(fp16) per (b,h) -> g_Ch. M-tile 64 (MT=1), K-chunk 32,
// cp.async double-buffered. grid (16 it, 96 bh). (round-15 proven)
// ---------------------------------------------------------------------------
__global__ __launch_bounds__(256) void k_av() {
    __shared__ __align__(16) __half As[2][64 * 40];
    __shared__ __align__(16) __half Vs[2][32 * 72];
    const int tid = threadIdx.x, lane = tid & 31, w = tid >> 5;
    const int it = blockIdx.x, bh = blockIdx.y;
    const int b = bh / 12, h = bh % 12;
    const __half* Pp  = g_P  + (size_t)bh * 1048576 + (size_t)it * 65536;
    const __half* Vhp = g_Vh + (size_t)bh * 65536;
    const int wm = (w >> 1) * 16, wn = (w & 1) * 32;

    const int arow = tid >> 2, ac8 = (tid & 3) * 8;
    const int vrow = tid >> 3, vc8 = (tid & 7) * 8;

    const int lr = lane & 7, hs = (lane >> 3) & 1, kc = lane >> 4;
    const unsigned sa = (unsigned)__cvta_generic_to_shared(&As[0][0]);
    const unsigned sb = (unsigned)__cvta_generic_to_shared(&Vs[0][0]);
    const unsigned aaddr = sa + ((wm + hs * 8 + lr) * 40 + kc * 8) * 2;
    const unsigned baddr = sb + ((hs * 8 + lr) * 72 + wn + kc * 8) * 2;
    const unsigned ABUFB = 64 * 40 * 2;
    const unsigned VBUFB = 32 * 72 * 2;
    const unsigned adst = sa + (arow * 40 + ac8) * 2;
    const unsigned vdst = sb + (vrow * 72 + vc8) * 2;

    float acc[4][4] = {};

    CP16(adst, Pp + (size_t)arow * 1024 + ac8);
    CP16(vdst, Vhp + vrow * 64 + vc8);
    CPCOMMIT();

    for (int kt = 0; kt < 32; ++kt) {
        const int cur = kt & 1;
        CPWAIT0();
        __syncthreads();
        if (kt < 31) {
            const unsigned nb = cur ^ 1;
            CP16(adst + nb * ABUFB, Pp + (size_t)arow * 1024 + (kt + 1) * 32 + ac8);
            CP16(vdst + nb * VBUFB, Vhp + (size_t)((kt + 1) * 32 + vrow) * 64 + vc8);
            CPCOMMIT();
        }
        #pragma unroll
        for (int kk = 0; kk < 32; kk += 16) {
            unsigned af[4], bvh[4][2];
            #pragma unroll
            for (int n2 = 0; n2 < 2; ++n2)
                LDSM_X4T(bvh[2*n2][0], bvh[2*n2][1], bvh[2*n2+1][0], bvh[2*n2+1][1],
                         baddr + cur * VBUFB + kk * 144 + n2 * 32);
            LDSM_X4(af[0], af[1], af[2], af[3],
                    aaddr + cur * ABUFB + kk * 2);
            #pragma unroll
            for (int nt = 0; nt < 4; ++nt)
                MMA16(acc[nt], af, bvh[nt]);
        }
    }

    const int g = lane >> 2, th = lane & 3;
    const int m = it * 64 + wm + g;
    #pragma unroll
    for (int nt = 0; nt < 4; ++nt) {
        const int c = wn + nt * 8 + 2 * th;
        const size_t base = ((size_t)b * 1024 + m) * 768 + h * 64 + c;
        *(__half2*)(g_Ch + base)           = __floats2half2_rn(acc[nt][0], acc[nt][1]);
        *(__half2*)(g_Ch + base + 8 * 768) = __floats2half2_rn(acc[nt][2], acc[nt][3]);
    }
}

// ---------------------------------------------------------------------------
// K5: out = Ctx(fp16) @ g_Woh + bo. N-tile 64, K-chunk 32, double-buffered.
// grid (12, 64). Warps 4m x 2n (MT=2, NT=4). (round-15 proven)
// ---------------------------------------------------------------------------
__global__ __launch_bounds__(256) void k_out(const float* __restrict__ bo,
                                             float* __restrict__ out) {
    __shared__ __align__(16) __half As[2][128 * 40];
    __shared__ __align__(16) __half Bs[2][32 * 72];
    const int tid = threadIdx.x, lane = tid & 31, w = tid >> 5;
    const int bx = blockIdx.x, by = blockIdx.y;
    const int wm = (w >> 1) * 32, wn = (w & 1) * 32;

    const int arow = tid >> 1, ac8 = (tid & 1) * 8;
    const int brow = tid >> 3, bc8 = (tid & 7) * 8;
    const __half* Chp = g_Ch + ((size_t)by * 128) * 768;
    const __half* Bp  = g_Woh + bx * 64;

    const int lr = lane & 7, hs = (lane >> 3) & 1, kc = lane >> 4;
    const unsigned sa = (unsigned)__cvta_generic_to_shared(&As[0][0]);
    const unsigned sb = (unsigned)__cvta_generic_to_shared(&Bs[0][0]);
    const unsigned aaddr = sa + ((wm + hs * 8 + lr) * 40 + kc * 8) * 2;
    const unsigned baddr = sb + ((hs * 8 + lr) * 72 + wn + kc * 8) * 2;
    const unsigned ABUFB = 128 * 40 * 2, BBUFB = 32 * 72 * 2;

    float acc[2][4][4] = {};

    #pragma unroll
    for (int u = 0; u < 2; ++u) {
        const unsigned d = sa + (arow * 40 + u * 16 + ac8) * 2;
        CP16(d, Chp + (size_t)arow * 768 + u * 16 + ac8);
    }
    CP16(sb + (brow * 72 + bc8) * 2, Bp + (size_t)brow * 768 + bc8);
    CPCOMMIT();

    for (int kt = 0; kt < 24; ++kt) {
        const int cur = kt & 1;
        CPWAIT0();
        __syncthreads();
        if (kt < 23) {
            const unsigned nb = cur ^ 1;
            #pragma unroll
            for (int u = 0; u < 2; ++u) {
                const unsigned d = sa + nb * ABUFB + (arow * 40 + u * 16 + ac8) * 2;
                CP16(d, Chp + (size_t)arow * 768 + (kt + 1) * 32 + u * 16 + ac8);
            }
            CP16(sb + nb * BBUFB + (brow * 72 + bc8) * 2,
                 Bp + (size_t)((kt + 1) * 32 + brow) * 768 + bc8);
            CPCOMMIT();
        }
        #pragma unroll
        for (int kk = 0; kk < 32; kk += 16) {
            unsigned af[2][4], bh[4][2];
            #pragma unroll
            for (int n2 = 0; n2 < 2; ++n2)
                LDSM_X4T(bh[2*n2][0], bh[2*n2][1], bh[2*n2+1][0], bh[2*n2+1][1],
                         baddr + cur * BBUFB + kk * 144 + n2 * 32);
            #pragma unroll
            for (int mt = 0; mt < 2; ++mt)
                LDSM_X4(af[mt][0], af[mt][1], af[mt][2], af[mt][3],
                        aaddr + cur * ABUFB + mt * 1280 + kk * 2);
            #pragma unroll
            for (int mt = 0; mt < 2; ++mt)
                #pragma unroll
                for (int nt = 0; nt < 4; ++nt)
                    MMA16(acc[mt][nt], af[mt], bh[nt]);
        }
    }

    const int g = lane >> 2, th = lane & 3;
    #pragma unroll
    for (int nt = 0; nt < 4; ++nt) {
        const int c = bx * 64 + wn + nt * 8 + 2 * th;
        const float b0v = bo[c], b1v = bo[c + 1];
        #pragma unroll
        for (int mt = 0; mt < 2; ++mt) {
            const int m = by * 128 + wm + mt * 16 + g;
            *(float2*)(out + (size_t)m * 768 + c) =
                make_float2(acc[mt][nt][0] + b0v, acc[mt][nt][1] + b1v);
            *(float2*)(out + (size_t)(m + 8) * 768 + c) =
                make_float2(acc[mt][nt][2] + b0v, acc[mt][nt][3] + b1v);
        }
    }
}

// ---------------------------------------------------------------------------
extern "C" void kernel_launch(void* const* d_in, const int* in_sizes, int n_in,
                              void* d_out, int out_size) {
    const float* x     = (const float*)d_in[0];
    const float* Wq    = (const float*)d_in[1];
    const float* Wkv   = (const float*)d_in[2];
    const float* mpre  = (const float*)d_in[3];
    const float* mpost = (const float*)d_in[4];
    const float* Wo    = (const float*)d_in[5];
    const float* bo    = (const float*)d_in[6];
    float* out = (float*)d_out;

    k_prep   <<<8448, 256>>>(x, Wq, Wkv, Wo);
    k_qkv    <<<dim3(18, 64),   256>>>();
    k_dots   <<<dim3(8, 8, 96), 256>>>();
    k_mixsoft<<<8192,           256>>>(mpre, mpost);
    k_av     <<<dim3(16, 96),   256>>>();
    k_out    <<<dim3(12, 64),   256>>>(bo, out);
}